// round 5
// baseline (speedup 1.0000x reference)
#include <cuda_runtime.h>
#include <cuda_bf16.h>
#include <cstdint>
#include <math.h>

#define NN     16384
#define EE     524288
#define F_IN   128
#define H1     256
#define H2     256
#define D1     64

// ---------------- scratch (device globals; no allocations) ----------------
__device__ float g_Z[NN * F_IN];     // aggregated features (layer-1 pre-GEMM)
__device__ float g_Xs[NN * H1];      // layer-2 gemm output, dinv-scaled
__device__ float g_h1[NN * H1];
__device__ float g_dinv[NN];
__device__ int   g_deg[NN];
__device__ int   g_rowptr[NN + 1];
__device__ int   g_cursor[NN];
__device__ int   g_col[EE];
__device__ float g_fc1wT[H2 * D1];
__device__ float g_assign[NN * 2];
__device__ float g_gf[2 * H2];
__device__ float g_newadj[4];

// ---------------- init ----------------
__global__ void k_init() {
    int i = blockIdx.x * blockDim.x + threadIdx.x;
    if (i < NN) { g_deg[i] = 1; g_cursor[i] = 0; }
    if (i < 2 * H2) g_gf[i] = 0.0f;
    if (i < 4) g_newadj[i] = 0.0f;
}

__global__ void k_deg(const int* __restrict__ dst) {
    int e = blockIdx.x * blockDim.x + threadIdx.x;
    if (e < EE) atomicAdd(&g_deg[dst[e]], 1);
}

// ---------------- fused scan + dinv: 1 block, 1024 threads ----------------
__global__ __launch_bounds__(1024) void k_scan() {
    int t = threadIdx.x;
    int base = t * 16;
    int local[16];
    int s = 0;
    #pragma unroll
    for (int j = 0; j < 16; j++) {
        int dg = g_deg[base + j];
        g_dinv[base + j] = rsqrtf((float)dg);
        local[j] = s;
        s += dg - 1;
    }
    int lane = t & 31, wid = t >> 5;
    int v = s;
    #pragma unroll
    for (int d = 1; d < 32; d <<= 1) {
        int u = __shfl_up_sync(0xffffffffu, v, d);
        if (lane >= d) v += u;
    }
    __shared__ int wsum[32];
    if (lane == 31) wsum[wid] = v;
    __syncthreads();
    if (wid == 0) {
        int w = wsum[lane];
        #pragma unroll
        for (int d = 1; d < 32; d <<= 1) {
            int u = __shfl_up_sync(0xffffffffu, w, d);
            if (lane >= d) w += u;
        }
        wsum[lane] = w;
    }
    __syncthreads();
    int off = (v - s) + (wid ? wsum[wid - 1] : 0);
    #pragma unroll
    for (int j = 0; j < 16; j++) g_rowptr[base + j] = off + local[j];
    if (t == 1023) g_rowptr[NN] = off + s;
}

__global__ void k_scatter(const int* __restrict__ src, const int* __restrict__ dst) {
    int e = blockIdx.x * blockDim.x + threadIdx.x;
    if (e < EE) {
        int d = dst[e];
        int p = atomicAdd(&g_cursor[d], 1);
        g_col[g_rowptr[d] + p] = src[e];
    }
}

__global__ void k_transpose(const float* __restrict__ w) {
    int i = blockIdx.x * blockDim.x + threadIdx.x;
    if (i < D1 * H2) {
        int o = i >> 8, k = i & 255;
        g_fc1wT[k * D1 + o] = w[i];
    }
}

// ---------------- layer-1 aggregation (128-wide), dinv fused, unroll-4 ----------------
// Z[d] = dinv[d] * ( dinv[d]*X[d] + sum_s dinv[s]*X[s] )
__global__ __launch_bounds__(256) void k_agg1(const float* __restrict__ X) {
    int gi = threadIdx.x >> 5;
    int lane = threadIdx.x & 31;
    int d = blockIdx.x * 8 + gi;
    const float4* X4 = (const float4*)X;
    float scd = g_dinv[d];
    float4 acc = X4[(size_t)d * 32 + lane];
    acc.x *= scd; acc.y *= scd; acc.z *= scd; acc.w *= scd;
    int j = g_rowptr[d], s1 = g_rowptr[d + 1];
    for (; j + 4 <= s1; j += 4) {
        int i0 = g_col[j], i1 = g_col[j + 1], i2 = g_col[j + 2], i3 = g_col[j + 3];
        float w0 = g_dinv[i0], w1 = g_dinv[i1], w2 = g_dinv[i2], w3 = g_dinv[i3];
        float4 v0 = X4[(size_t)i0 * 32 + lane];
        float4 v1 = X4[(size_t)i1 * 32 + lane];
        float4 v2 = X4[(size_t)i2 * 32 + lane];
        float4 v3 = X4[(size_t)i3 * 32 + lane];
        acc.x += w0 * v0.x + w1 * v1.x + w2 * v2.x + w3 * v3.x;
        acc.y += w0 * v0.y + w1 * v1.y + w2 * v2.y + w3 * v3.y;
        acc.z += w0 * v0.z + w1 * v1.z + w2 * v2.z + w3 * v3.z;
        acc.w += w0 * v0.w + w1 * v1.w + w2 * v2.w + w3 * v3.w;
    }
    for (; j < s1; j++) {
        int s = g_col[j];
        float w = g_dinv[s];
        float4 v = X4[(size_t)s * 32 + lane];
        acc.x += w * v.x; acc.y += w * v.y; acc.z += w * v.z; acc.w += w * v.w;
    }
    acc.x *= scd; acc.y *= scd; acc.z *= scd; acc.w *= scd;
    ((float4*)g_Z)[(size_t)d * 32 + lane] = acc;
}

// ---------------- tf32 tensor-core GEMM ----------------
__device__ __forceinline__ unsigned int f2tf32(float x) {
    unsigned int r;
    asm("cvt.rna.tf32.f32 %0, %1;" : "=r"(r) : "f"(x));
    return r;
}
__device__ __forceinline__ void mma_tf32(float* d, const unsigned int* a, const unsigned int* b) {
    asm volatile(
        "mma.sync.aligned.m16n8k8.row.col.f32.tf32.tf32.f32 "
        "{%0,%1,%2,%3},{%4,%5,%6,%7},{%8,%9},{%0,%1,%2,%3};\n"
        : "+f"(d[0]), "+f"(d[1]), "+f"(d[2]), "+f"(d[3])
        : "r"(a[0]), "r"(a[1]), "r"(a[2]), "r"(a[3]), "r"(b[0]), "r"(b[1]));
}

#define GBK 32
__global__ __launch_bounds__(256) void k_gemm_tc(const float* __restrict__ A,
                                                 const float* __restrict__ B,
                                                 float* __restrict__ C,
                                                 const float* __restrict__ bias,
                                                 int K, int mode) {
    __shared__ unsigned int As[GBK][136];
    __shared__ unsigned int Bs[GBK][136];
    int t = threadIdx.x;
    int row0 = blockIdx.y * 128, col0 = blockIdx.x * 128;
    int wid = t >> 5, lane = t & 31;
    int wr = wid >> 2, wc = wid & 3;
    int g = lane >> 2, tig = lane & 3;
    float acc[4][4][4] = {};

    for (int k0 = 0; k0 < K; k0 += GBK) {
        #pragma unroll
        for (int j = 0; j < 4; j++) {
            int i = t + 256 * j;
            int r = i >> 3, kq = (i & 7) * 4;
            float4 v = *(const float4*)&A[(size_t)(row0 + r) * K + k0 + kq];
            As[kq + 0][r] = f2tf32(v.x); As[kq + 1][r] = f2tf32(v.y);
            As[kq + 2][r] = f2tf32(v.z); As[kq + 3][r] = f2tf32(v.w);
        }
        #pragma unroll
        for (int j = 0; j < 4; j++) {
            int i = t + 256 * j;
            int kr = i >> 5, nq = (i & 31) * 4;
            float4 v = *(const float4*)&B[(size_t)(k0 + kr) * 256 + col0 + nq];
            Bs[kr][nq + 0] = f2tf32(v.x); Bs[kr][nq + 1] = f2tf32(v.y);
            Bs[kr][nq + 2] = f2tf32(v.z); Bs[kr][nq + 3] = f2tf32(v.w);
        }
        __syncthreads();

        #pragma unroll
        for (int kk = 0; kk < GBK; kk += 8) {
            unsigned int af[4][4], bf[4][2];
            #pragma unroll
            for (int mi = 0; mi < 4; mi++) {
                int r = wr * 64 + mi * 16 + g;
                af[mi][0] = As[kk + tig][r];
                af[mi][1] = As[kk + tig][r + 8];
                af[mi][2] = As[kk + tig + 4][r];
                af[mi][3] = As[kk + tig + 4][r + 8];
            }
            #pragma unroll
            for (int ni = 0; ni < 4; ni++) {
                int c = wc * 32 + ni * 8 + g;
                bf[ni][0] = Bs[kk + tig][c];
                bf[ni][1] = Bs[kk + tig + 4][c];
            }
            #pragma unroll
            for (int mi = 0; mi < 4; mi++)
                #pragma unroll
                for (int ni = 0; ni < 4; ni++)
                    mma_tf32(acc[mi][ni], af[mi], bf[ni]);
        }
        __syncthreads();
    }

    #pragma unroll
    for (int mi = 0; mi < 4; mi++) {
        #pragma unroll
        for (int half = 0; half < 2; half++) {
            int r = row0 + wr * 64 + mi * 16 + g + half * 8;
            float sc = (mode == 1) ? g_dinv[r] : 1.0f;
            #pragma unroll
            for (int ni = 0; ni < 4; ni++) {
                int c = col0 + wc * 32 + ni * 8 + tig * 2;
                float v0 = acc[mi][ni][half * 2 + 0];
                float v1 = acc[mi][ni][half * 2 + 1];
                if (mode == 0) {
                    v0 = fmaxf(v0 + bias[c], 0.0f);
                    v1 = fmaxf(v1 + bias[c + 1], 0.0f);
                } else {
                    v0 *= sc; v1 *= sc;
                }
                *(float2*)&C[(size_t)r * 256 + c] = make_float2(v0, v1);
            }
        }
    }
}

// ---------------- fused layer-2 aggregation + MLP + softmax + pooled partials ----------------
// Per block: 64 nodes. For each chunk of 4 nodes: aggregate h2 row into smem
// (never touching gmem h2), then fc1/tanh/fc2/softmax/assign, accumulate gf.
__global__ __launch_bounds__(256) void k_aggfc(const float* __restrict__ b2,
                                               const float* __restrict__ fc1b,
                                               const float* __restrict__ fc2w,
                                               const float* __restrict__ fc2b) {
    __shared__ float h2s[4][260];
    __shared__ float a1s[4][64];
    __shared__ float ps[4][2];
    __shared__ float gfl[2][256];
    int t = threadIdx.x;
    gfl[0][t] = 0.0f; gfl[1][t] = 0.0f;
    int n0 = blockIdx.x * 64;
    int gi = t >> 6, lane = t & 63;
    const float4* Xs4 = (const float4*)g_Xs;
    float4 bv = ((const float4*)b2)[lane];

    for (int q = 0; q < 64; q += 4) {
        // --- aggregate node d = n0+q+gi, 64 threads x float4 ---
        int d = n0 + q + gi;
        float4 acc = Xs4[(size_t)d * 64 + lane];
        int j = g_rowptr[d], s1 = g_rowptr[d + 1];
        for (; j + 4 <= s1; j += 4) {
            int i0 = g_col[j], i1 = g_col[j + 1], i2 = g_col[j + 2], i3 = g_col[j + 3];
            float4 v0 = Xs4[(size_t)i0 * 64 + lane];
            float4 v1 = Xs4[(size_t)i1 * 64 + lane];
            float4 v2 = Xs4[(size_t)i2 * 64 + lane];
            float4 v3 = Xs4[(size_t)i3 * 64 + lane];
            acc.x += v0.x + v1.x + v2.x + v3.x;
            acc.y += v0.y + v1.y + v2.y + v3.y;
            acc.z += v0.z + v1.z + v2.z + v3.z;
            acc.w += v0.w + v1.w + v2.w + v3.w;
        }
        for (; j < s1; j++) {
            int s = g_col[j];
            float4 v = Xs4[(size_t)s * 64 + lane];
            acc.x += v.x; acc.y += v.y; acc.z += v.z; acc.w += v.w;
        }
        float sc = g_dinv[d];
        float4 o;
        o.x = acc.x * sc + bv.x; o.y = acc.y * sc + bv.y;
        o.z = acc.z * sc + bv.z; o.w = acc.w * sc + bv.w;
        h2s[gi][lane * 4 + 0] = o.x; h2s[gi][lane * 4 + 1] = o.y;
        h2s[gi][lane * 4 + 2] = o.z; h2s[gi][lane * 4 + 3] = o.w;
        __syncthreads();

        // --- fc1: 64 outputs per node; thread t -> node (t>>6), out (t&63) ---
        int nq = gi, oo = lane;
        float dot = fc1b[oo];
        #pragma unroll 8
        for (int k = 0; k < 256; k++)
            dot += g_fc1wT[k * 64 + oo] * h2s[nq][k];
        a1s[nq][oo] = tanhf(dot);
        __syncthreads();

        if (t < 8) {
            int n = t >> 1, c = t & 1;
            float l = fc2b[c];
            #pragma unroll
            for (int k = 0; k < 64; k++) l += fc2w[c * 64 + k] * a1s[n][k];
            ps[n][c] = l;
        }
        __syncthreads();
        if (t < 4) {
            float l0 = ps[t][0], l1 = ps[t][1];
            float m = fmaxf(l0, l1);
            float e0 = expf(l0 - m), e1 = expf(l1 - m);
            float inv = 1.0f / (e0 + e1);
            float p0 = e0 * inv, p1 = e1 * inv;
            ps[t][0] = p0; ps[t][1] = p1;
            g_assign[2 * (n0 + q + t)] = p0;
            g_assign[2 * (n0 + q + t) + 1] = p1;
        }
        __syncthreads();
        #pragma unroll
        for (int n = 0; n < 4; n++) {
            float p0 = ps[n][0], p1 = ps[n][1];
            float hv = h2s[n][t];
            gfl[0][t] += p0 * hv;
            gfl[1][t] += p1 * hv;
        }
        __syncthreads();
    }
    atomicAdd(&g_gf[t], gfl[0][t]);
    atomicAdd(&g_gf[256 + t], gfl[1][t]);
}

// ---------------- new_adj ----------------
__global__ void k_newadj(const int* __restrict__ src, const int* __restrict__ dst) {
    float a0 = 0, a1 = 0, a2 = 0, a3 = 0;
    const float2* as2 = (const float2*)g_assign;
    for (int e = blockIdx.x * blockDim.x + threadIdx.x; e < EE; e += gridDim.x * blockDim.x) {
        int s = src[e], d = dst[e];
        float2 sv = as2[s];
        float2 dv = as2[d];
        a0 += sv.x * dv.x; a1 += sv.x * dv.y; a2 += sv.y * dv.x; a3 += sv.y * dv.y;
    }
    #pragma unroll
    for (int w = 16; w; w >>= 1) {
        a0 += __shfl_down_sync(0xffffffff, a0, w);
        a1 += __shfl_down_sync(0xffffffff, a1, w);
        a2 += __shfl_down_sync(0xffffffff, a2, w);
        a3 += __shfl_down_sync(0xffffffff, a3, w);
    }
    __shared__ float sa[8][4];
    int lane = threadIdx.x & 31, wid = threadIdx.x >> 5;
    if (lane == 0) { sa[wid][0] = a0; sa[wid][1] = a1; sa[wid][2] = a2; sa[wid][3] = a3; }
    __syncthreads();
    if (threadIdx.x < 4) {
        float sum = 0;
        #pragma unroll
        for (int w = 0; w < 8; w++) sum += sa[w][threadIdx.x];
        atomicAdd(&g_newadj[threadIdx.x], sum);
    }
}

// ---------------- finalize ----------------
__global__ void k_final(float* __restrict__ out) {
    int t = threadIdx.x;
    float g0 = g_gf[t], g1 = g_gf[256 + t];
    out[t]       = 0.5f * (g0 + g1);
    out[256 + t] = fminf(fmaxf(g0, -100.0f), 100.0f);
    out[512 + t] = fminf(fmaxf(g1, -100.0f), 100.0f);
    if (t == 0) {
        float a00 = g_newadj[0], a01 = g_newadj[1], a10 = g_newadj[2], a11 = g_newadj[3];
        float den0 = fmaxf(fabsf(a00) + fabsf(a01), 1e-12f);
        float den1 = fmaxf(fabsf(a10) + fabsf(a11), 1e-12f);
        float nd0 = a00 / den0, nd1 = a11 / den1;
        out[768] = 0.5f * ((nd0 - 1.0f) * (nd0 - 1.0f) + (nd1 - 1.0f) * (nd1 - 1.0f));
    }
}

extern "C" void kernel_launch(void* const* d_in, const int* in_sizes, int n_in,
                              void* d_out, int out_size) {
    const float* features = (const float*)d_in[0];
    const int*   edges    = (const int*)d_in[1];
    const float* W1    = (const float*)d_in[2];
    const float* b1    = (const float*)d_in[3];
    const float* W2    = (const float*)d_in[4];
    const float* b2    = (const float*)d_in[5];
    const float* fc1w  = (const float*)d_in[6];
    const float* fc1b  = (const float*)d_in[7];
    const float* fc2w  = (const float*)d_in[8];
    const float* fc2b  = (const float*)d_in[9];
    float* out = (float*)d_out;
    const int* src = edges;
    const int* dst = edges + EE;

    float *pXs, *ph1, *pZ;
    cudaGetSymbolAddress((void**)&pXs, g_Xs);
    cudaGetSymbolAddress((void**)&ph1, g_h1);
    cudaGetSymbolAddress((void**)&pZ,  g_Z);

    k_init<<<NN / 256, 256>>>();
    k_deg<<<EE / 256, 256>>>(dst);
    k_scan<<<1, 1024>>>();
    k_scatter<<<EE / 256, 256>>>(src, dst);
    k_transpose<<<(D1 * H2) / 256, 256>>>(fc1w);

    // layer 1: aggregate raw features (dinv fused), then tensor-core transform
    k_agg1<<<NN / 8, 256>>>(features);
    dim3 gg(2, NN / 128);
    k_gemm_tc<<<gg, 256>>>(pZ, W1, ph1, b1, F_IN, 0);     // h1 = relu(Z@W1+b1)

    // layer 2: transform, then fused aggregate+MLP+softmax+pool
    k_gemm_tc<<<gg, 256>>>(ph1, W2, pXs, (const float*)0, H1, 1);  // Xs = dinv*(h1@W2)
    k_aggfc<<<NN / 64, 256>>>(b2, fc1b, fc2w, fc2b);

    k_newadj<<<256, 256>>>(src, dst);
    k_final<<<1, 256>>>(out);
}

// round 6
// speedup vs baseline: 1.2221x; 1.2221x over previous
#include <cuda_runtime.h>
#include <cuda_bf16.h>
#include <cstdint>
#include <math.h>

#define NN     16384
#define EE     524288
#define F_IN   128
#define H1     256
#define H2     256
#define D1     64

// ---------------- scratch (device globals; no allocations) ----------------
__device__ float g_Z[NN * F_IN];     // aggregated features (layer-1 pre-GEMM)
__device__ float g_Xs[NN * H1];      // layer-2 gemm output, dinv-scaled
__device__ float g_h1[NN * H1];
__device__ float g_h2[NN * H2];
__device__ float g_dinv[NN];
__device__ int   g_deg[NN];
__device__ int   g_rowptr[NN + 1];
__device__ int   g_cursor[NN];
__device__ int   g_col[EE];
__device__ float g_fc1wT[H2 * D1];
__device__ float g_assign[NN * 2];
__device__ float g_gf[2 * H2];
__device__ float g_newadj[4];

// ---------------- init ----------------
__global__ void k_init() {
    int i = blockIdx.x * blockDim.x + threadIdx.x;
    if (i < NN) { g_deg[i] = 1; g_cursor[i] = 0; }
    if (i < 2 * H2) g_gf[i] = 0.0f;
    if (i < 4) g_newadj[i] = 0.0f;
}

__global__ void k_deg(const int* __restrict__ dst) {
    int e = blockIdx.x * blockDim.x + threadIdx.x;
    if (e < EE) atomicAdd(&g_deg[dst[e]], 1);
}

// ---------------- fused scan + dinv: 1 block, 1024 threads ----------------
__global__ __launch_bounds__(1024) void k_scan() {
    int t = threadIdx.x;
    int base = t * 16;
    int local[16];
    int s = 0;
    #pragma unroll
    for (int j = 0; j < 16; j++) {
        int dg = g_deg[base + j];
        g_dinv[base + j] = rsqrtf((float)dg);
        local[j] = s;
        s += dg - 1;
    }
    int lane = t & 31, wid = t >> 5;
    int v = s;
    #pragma unroll
    for (int d = 1; d < 32; d <<= 1) {
        int u = __shfl_up_sync(0xffffffffu, v, d);
        if (lane >= d) v += u;
    }
    __shared__ int wsum[32];
    if (lane == 31) wsum[wid] = v;
    __syncthreads();
    if (wid == 0) {
        int w = wsum[lane];
        #pragma unroll
        for (int d = 1; d < 32; d <<= 1) {
            int u = __shfl_up_sync(0xffffffffu, w, d);
            if (lane >= d) w += u;
        }
        wsum[lane] = w;
    }
    __syncthreads();
    int off = (v - s) + (wid ? wsum[wid - 1] : 0);
    #pragma unroll
    for (int j = 0; j < 16; j++) g_rowptr[base + j] = off + local[j];
    if (t == 1023) g_rowptr[NN] = off + s;
}

__global__ void k_scatter(const int* __restrict__ src, const int* __restrict__ dst) {
    int e = blockIdx.x * blockDim.x + threadIdx.x;
    if (e < EE) {
        int d = dst[e];
        int p = atomicAdd(&g_cursor[d], 1);
        g_col[g_rowptr[d] + p] = src[e];
    }
}

__global__ void k_transpose(const float* __restrict__ w) {
    int i = blockIdx.x * blockDim.x + threadIdx.x;
    if (i < D1 * H2) {
        int o = i >> 8, k = i & 255;
        g_fc1wT[k * D1 + o] = w[i];
    }
}

// ---------------- layer-1 aggregation (128-wide), dinv fused, unroll-4 ----------------
// Z[d] = dinv[d] * ( dinv[d]*X[d] + sum_s dinv[s]*X[s] )
__global__ __launch_bounds__(256) void k_agg1(const float* __restrict__ X) {
    int gi = threadIdx.x >> 5;
    int lane = threadIdx.x & 31;
    int d = blockIdx.x * 8 + gi;
    const float4* X4 = (const float4*)X;
    float scd = g_dinv[d];
    float4 acc = X4[(size_t)d * 32 + lane];
    acc.x *= scd; acc.y *= scd; acc.z *= scd; acc.w *= scd;
    int j = g_rowptr[d], s1 = g_rowptr[d + 1];
    for (; j + 4 <= s1; j += 4) {
        int i0 = g_col[j], i1 = g_col[j + 1], i2 = g_col[j + 2], i3 = g_col[j + 3];
        float w0 = g_dinv[i0], w1 = g_dinv[i1], w2 = g_dinv[i2], w3 = g_dinv[i3];
        float4 v0 = X4[(size_t)i0 * 32 + lane];
        float4 v1 = X4[(size_t)i1 * 32 + lane];
        float4 v2 = X4[(size_t)i2 * 32 + lane];
        float4 v3 = X4[(size_t)i3 * 32 + lane];
        acc.x += w0 * v0.x + w1 * v1.x + w2 * v2.x + w3 * v3.x;
        acc.y += w0 * v0.y + w1 * v1.y + w2 * v2.y + w3 * v3.y;
        acc.z += w0 * v0.z + w1 * v1.z + w2 * v2.z + w3 * v3.z;
        acc.w += w0 * v0.w + w1 * v1.w + w2 * v2.w + w3 * v3.w;
    }
    for (; j < s1; j++) {
        int s = g_col[j];
        float w = g_dinv[s];
        float4 v = X4[(size_t)s * 32 + lane];
        acc.x += w * v.x; acc.y += w * v.y; acc.z += w * v.z; acc.w += w * v.w;
    }
    acc.x *= scd; acc.y *= scd; acc.z *= scd; acc.w *= scd;
    ((float4*)g_Z)[(size_t)d * 32 + lane] = acc;
}

// ---------------- tf32 tensor-core GEMM, register double-buffered ----------------
__device__ __forceinline__ unsigned int f2tf32(float x) {
    unsigned int r;
    asm("cvt.rna.tf32.f32 %0, %1;" : "=r"(r) : "f"(x));
    return r;
}
__device__ __forceinline__ void mma_tf32(float* d, const unsigned int* a, const unsigned int* b) {
    asm volatile(
        "mma.sync.aligned.m16n8k8.row.col.f32.tf32.tf32.f32 "
        "{%0,%1,%2,%3},{%4,%5,%6,%7},{%8,%9},{%0,%1,%2,%3};\n"
        : "+f"(d[0]), "+f"(d[1]), "+f"(d[2]), "+f"(d[3])
        : "r"(a[0]), "r"(a[1]), "r"(a[2]), "r"(a[3]), "r"(b[0]), "r"(b[1]));
}

#define GBK 32
__global__ __launch_bounds__(256) void k_gemm_tc(const float* __restrict__ A,
                                                 const float* __restrict__ B,
                                                 float* __restrict__ C,
                                                 const float* __restrict__ bias,
                                                 int K, int mode) {
    __shared__ unsigned int As[GBK][136];
    __shared__ unsigned int Bs[GBK][136];
    int t = threadIdx.x;
    int row0 = blockIdx.y * 128, col0 = blockIdx.x * 128;
    int wid = t >> 5, lane = t & 31;
    int wr = wid >> 2, wc = wid & 3;
    int g = lane >> 2, tig = lane & 3;
    float acc[4][4][4] = {};

    // per-thread load coordinates
    int arr = t >> 3, akq = (t & 7) * 4;        // A: row (0..31 base, 4 j-strides of 32), k quad
    int bkr = t >> 5, bnq = (t & 31) * 4;       // B: k row (0..7 base), col quad

    float4 ra[4], rb[4];
    #pragma unroll
    for (int j = 0; j < 4; j++)
        ra[j] = *(const float4*)&A[(size_t)(row0 + arr + j * 32) * K + akq];
    #pragma unroll
    for (int j = 0; j < 4; j++)
        rb[j] = *(const float4*)&B[(size_t)(bkr + j * 8) * 256 + col0 + bnq];

    for (int k0 = 0; k0 < K; k0 += GBK) {
        // store current regs -> smem (tf32 convert)
        #pragma unroll
        for (int j = 0; j < 4; j++) {
            int r = arr + j * 32;
            As[akq + 0][r] = f2tf32(ra[j].x); As[akq + 1][r] = f2tf32(ra[j].y);
            As[akq + 2][r] = f2tf32(ra[j].z); As[akq + 3][r] = f2tf32(ra[j].w);
        }
        #pragma unroll
        for (int j = 0; j < 4; j++) {
            int kr = bkr + j * 8;
            Bs[kr][bnq + 0] = f2tf32(rb[j].x); Bs[kr][bnq + 1] = f2tf32(rb[j].y);
            Bs[kr][bnq + 2] = f2tf32(rb[j].z); Bs[kr][bnq + 3] = f2tf32(rb[j].w);
        }
        __syncthreads();

        // prefetch next tile while computing
        bool more = (k0 + GBK) < K;
        if (more) {
            #pragma unroll
            for (int j = 0; j < 4; j++)
                ra[j] = *(const float4*)&A[(size_t)(row0 + arr + j * 32) * K + k0 + GBK + akq];
            #pragma unroll
            for (int j = 0; j < 4; j++)
                rb[j] = *(const float4*)&B[(size_t)(k0 + GBK + bkr + j * 8) * 256 + col0 + bnq];
        }

        #pragma unroll
        for (int kk = 0; kk < GBK; kk += 8) {
            unsigned int af[4][4], bf[4][2];
            #pragma unroll
            for (int mi = 0; mi < 4; mi++) {
                int r = wr * 64 + mi * 16 + g;
                af[mi][0] = As[kk + tig][r];
                af[mi][1] = As[kk + tig][r + 8];
                af[mi][2] = As[kk + tig + 4][r];
                af[mi][3] = As[kk + tig + 4][r + 8];
            }
            #pragma unroll
            for (int ni = 0; ni < 4; ni++) {
                int c = wc * 32 + ni * 8 + g;
                bf[ni][0] = Bs[kk + tig][c];
                bf[ni][1] = Bs[kk + tig + 4][c];
            }
            #pragma unroll
            for (int mi = 0; mi < 4; mi++)
                #pragma unroll
                for (int ni = 0; ni < 4; ni++)
                    mma_tf32(acc[mi][ni], af[mi], bf[ni]);
        }
        __syncthreads();
    }

    #pragma unroll
    for (int mi = 0; mi < 4; mi++) {
        #pragma unroll
        for (int half = 0; half < 2; half++) {
            int r = row0 + wr * 64 + mi * 16 + g + half * 8;
            float sc = (mode == 1) ? g_dinv[r] : 1.0f;
            #pragma unroll
            for (int ni = 0; ni < 4; ni++) {
                int c = col0 + wc * 32 + ni * 8 + tig * 2;
                float v0 = acc[mi][ni][half * 2 + 0];
                float v1 = acc[mi][ni][half * 2 + 1];
                if (mode == 0) {
                    v0 = fmaxf(v0 + bias[c], 0.0f);
                    v1 = fmaxf(v1 + bias[c + 1], 0.0f);
                } else {
                    v0 *= sc; v1 *= sc;
                }
                *(float2*)&C[(size_t)r * 256 + c] = make_float2(v0, v1);
            }
        }
    }
}

// ---------------- layer-2 aggregation (256-wide), unroll-4 ----------------
__global__ __launch_bounds__(256) void k_agg(float* __restrict__ out,
                                             const float* __restrict__ bias) {
    int gi = threadIdx.x >> 6;
    int lane = threadIdx.x & 63;
    int d = blockIdx.x * 4 + gi;
    const float4* Xs = (const float4*)g_Xs;
    float4 acc = Xs[(size_t)d * 64 + lane];
    int j = g_rowptr[d], s1 = g_rowptr[d + 1];
    for (; j + 4 <= s1; j += 4) {
        int i0 = g_col[j], i1 = g_col[j + 1], i2 = g_col[j + 2], i3 = g_col[j + 3];
        float4 v0 = Xs[(size_t)i0 * 64 + lane];
        float4 v1 = Xs[(size_t)i1 * 64 + lane];
        float4 v2 = Xs[(size_t)i2 * 64 + lane];
        float4 v3 = Xs[(size_t)i3 * 64 + lane];
        acc.x += v0.x + v1.x + v2.x + v3.x;
        acc.y += v0.y + v1.y + v2.y + v3.y;
        acc.z += v0.z + v1.z + v2.z + v3.z;
        acc.w += v0.w + v1.w + v2.w + v3.w;
    }
    for (; j < s1; j++) {
        int s = g_col[j];
        float4 v = Xs[(size_t)s * 64 + lane];
        acc.x += v.x; acc.y += v.y; acc.z += v.z; acc.w += v.w;
    }
    float sc = g_dinv[d];
    float4 bv = ((const float4*)bias)[lane];
    float4 o;
    o.x = acc.x * sc + bv.x; o.y = acc.y * sc + bv.y;
    o.z = acc.z * sc + bv.z; o.w = acc.w * sc + bv.w;
    ((float4*)out)[(size_t)d * 64 + lane] = o;
}

// ---------------- per-node MLP ----------------
#define FC_NODES 64
__global__ void k_fc(const float* __restrict__ h2,
                     const float* __restrict__ fc1b,
                     const float* __restrict__ fc2w, const float* __restrict__ fc2b) {
    __shared__ float h2s[4][256];
    __shared__ float a1s[4][64];
    __shared__ float ps[4][2];
    __shared__ float gfl[2][256];
    int t = threadIdx.x;
    gfl[0][t] = 0.0f; gfl[1][t] = 0.0f;
    int n0 = blockIdx.x * FC_NODES;
    int nq = t >> 6, o = t & 63;
    for (int q = 0; q < FC_NODES; q += 4) {
        for (int i = t; i < 1024; i += 256)
            h2s[i >> 8][i & 255] = h2[(size_t)(n0 + q + (i >> 8)) * 256 + (i & 255)];
        __syncthreads();
        float dot = fc1b[o];
        #pragma unroll 8
        for (int k = 0; k < 256; k++)
            dot += g_fc1wT[k * 64 + o] * h2s[nq][k];
        a1s[nq][o] = tanhf(dot);
        __syncthreads();
        if (t < 8) {
            int n = t >> 1, c = t & 1;
            float l = fc2b[c];
            #pragma unroll
            for (int k = 0; k < 64; k++) l += fc2w[c * 64 + k] * a1s[n][k];
            ps[n][c] = l;
        }
        __syncthreads();
        if (t < 4) {
            float l0 = ps[t][0], l1 = ps[t][1];
            float m = fmaxf(l0, l1);
            float e0 = expf(l0 - m), e1 = expf(l1 - m);
            float inv = 1.0f / (e0 + e1);
            float p0 = e0 * inv, p1 = e1 * inv;
            ps[t][0] = p0; ps[t][1] = p1;
            g_assign[2 * (n0 + q + t)] = p0;
            g_assign[2 * (n0 + q + t) + 1] = p1;
        }
        __syncthreads();
        #pragma unroll
        for (int n = 0; n < 4; n++) {
            float p0 = ps[n][0], p1 = ps[n][1];
            float hv = h2s[n][t];
            gfl[0][t] += p0 * hv;
            gfl[1][t] += p1 * hv;
        }
        __syncthreads();
    }
    atomicAdd(&g_gf[t], gfl[0][t]);
    atomicAdd(&g_gf[256 + t], gfl[1][t]);
}

// ---------------- new_adj ----------------
__global__ void k_newadj(const int* __restrict__ src, const int* __restrict__ dst) {
    float a0 = 0, a1 = 0, a2 = 0, a3 = 0;
    const float2* as2 = (const float2*)g_assign;
    for (int e = blockIdx.x * blockDim.x + threadIdx.x; e < EE; e += gridDim.x * blockDim.x) {
        int s = src[e], d = dst[e];
        float2 sv = as2[s];
        float2 dv = as2[d];
        a0 += sv.x * dv.x; a1 += sv.x * dv.y; a2 += sv.y * dv.x; a3 += sv.y * dv.y;
    }
    #pragma unroll
    for (int w = 16; w; w >>= 1) {
        a0 += __shfl_down_sync(0xffffffff, a0, w);
        a1 += __shfl_down_sync(0xffffffff, a1, w);
        a2 += __shfl_down_sync(0xffffffff, a2, w);
        a3 += __shfl_down_sync(0xffffffff, a3, w);
    }
    __shared__ float sa[8][4];
    int lane = threadIdx.x & 31, wid = threadIdx.x >> 5;
    if (lane == 0) { sa[wid][0] = a0; sa[wid][1] = a1; sa[wid][2] = a2; sa[wid][3] = a3; }
    __syncthreads();
    if (threadIdx.x < 4) {
        float sum = 0;
        #pragma unroll
        for (int w = 0; w < 8; w++) sum += sa[w][threadIdx.x];
        atomicAdd(&g_newadj[threadIdx.x], sum);
    }
}

// ---------------- finalize ----------------
__global__ void k_final(float* __restrict__ out) {
    int t = threadIdx.x;
    float g0 = g_gf[t], g1 = g_gf[256 + t];
    out[t]       = 0.5f * (g0 + g1);
    out[256 + t] = fminf(fmaxf(g0, -100.0f), 100.0f);
    out[512 + t] = fminf(fmaxf(g1, -100.0f), 100.0f);
    if (t == 0) {
        float a00 = g_newadj[0], a01 = g_newadj[1], a10 = g_newadj[2], a11 = g_newadj[3];
        float den0 = fmaxf(fabsf(a00) + fabsf(a01), 1e-12f);
        float den1 = fmaxf(fabsf(a10) + fabsf(a11), 1e-12f);
        float nd0 = a00 / den0, nd1 = a11 / den1;
        out[768] = 0.5f * ((nd0 - 1.0f) * (nd0 - 1.0f) + (nd1 - 1.0f) * (nd1 - 1.0f));
    }
}

extern "C" void kernel_launch(void* const* d_in, const int* in_sizes, int n_in,
                              void* d_out, int out_size) {
    const float* features = (const float*)d_in[0];
    const int*   edges    = (const int*)d_in[1];
    const float* W1    = (const float*)d_in[2];
    const float* b1    = (const float*)d_in[3];
    const float* W2    = (const float*)d_in[4];
    const float* b2    = (const float*)d_in[5];
    const float* fc1w  = (const float*)d_in[6];
    const float* fc1b  = (const float*)d_in[7];
    const float* fc2w  = (const float*)d_in[8];
    const float* fc2b  = (const float*)d_in[9];
    float* out = (float*)d_out;
    const int* src = edges;
    const int* dst = edges + EE;

    float *pXs, *ph1, *ph2, *pZ;
    cudaGetSymbolAddress((void**)&pXs, g_Xs);
    cudaGetSymbolAddress((void**)&ph1, g_h1);
    cudaGetSymbolAddress((void**)&ph2, g_h2);
    cudaGetSymbolAddress((void**)&pZ,  g_Z);

    k_init<<<NN / 256, 256>>>();
    k_deg<<<EE / 256, 256>>>(dst);
    k_scan<<<1, 1024>>>();
    k_scatter<<<EE / 256, 256>>>(src, dst);
    k_transpose<<<(D1 * H2) / 256, 256>>>(fc1w);

    // layer 1: aggregate raw features (dinv fused), then tensor-core transform
    k_agg1<<<NN / 8, 256>>>(features);
    dim3 gg(2, NN / 128);
    k_gemm_tc<<<gg, 256>>>(pZ, W1, ph1, b1, F_IN, 0);     // h1 = relu(Z@W1+b1)

    // layer 2: transform, then aggregate, then MLP
    k_gemm_tc<<<gg, 256>>>(ph1, W2, pXs, (const float*)0, H1, 1);  // Xs = dinv*(h1@W2)
    k_agg<<<NN / 4, 256>>>(ph2, b2);
    k_fc<<<NN / FC_NODES, 256>>>(ph2, fc1b, fc2w, fc2b);

    k_newadj<<<256, 256>>>(src, dst);
    k_final<<<1, 256>>>(out);
}

// round 7
// speedup vs baseline: 1.2721x; 1.0409x over previous
#include <cuda_runtime.h>
#include <cuda_bf16.h>
#include <cstdint>
#include <math.h>

#define NN     16384
#define EE     524288
#define F_IN   128
#define H1     256
#define H2     256
#define D1     64

// ---------------- scratch (device globals; no allocations) ----------------
__device__ float g_Z[NN * F_IN];          // aggregated features (layer-1 pre-GEMM)
__device__ __nv_bfloat16 g_Xb[NN * H1];   // layer-2 gemm output, dinv-scaled, bf16
__device__ float g_h1[NN * H1];
__device__ float g_h2[NN * H2];
__device__ float g_dinv[NN];
__device__ int   g_deg[NN];
__device__ int   g_rowptr[NN + 1];
__device__ int   g_cursor[NN];
__device__ int   g_col[EE];
__device__ float g_fc1wT[H2 * D1];
__device__ float g_assign[NN * 2];
__device__ float g_gf[2 * H2];
__device__ float g_newadj[4];

// ---------------- init ----------------
__global__ void k_init() {
    int i = blockIdx.x * blockDim.x + threadIdx.x;
    if (i < NN) { g_deg[i] = 1; g_cursor[i] = 0; }
    if (i < 2 * H2) g_gf[i] = 0.0f;
    if (i < 4) g_newadj[i] = 0.0f;
}

__global__ void k_deg(const int* __restrict__ dst) {
    int e = blockIdx.x * blockDim.x + threadIdx.x;
    if (e < EE) atomicAdd(&g_deg[dst[e]], 1);
}

// ---------------- fused scan + dinv: 1 block, 1024 threads ----------------
__global__ __launch_bounds__(1024) void k_scan() {
    int t = threadIdx.x;
    int base = t * 16;
    int local[16];
    int s = 0;
    #pragma unroll
    for (int j = 0; j < 16; j++) {
        int dg = g_deg[base + j];
        g_dinv[base + j] = rsqrtf((float)dg);
        local[j] = s;
        s += dg - 1;
    }
    int lane = t & 31, wid = t >> 5;
    int v = s;
    #pragma unroll
    for (int d = 1; d < 32; d <<= 1) {
        int u = __shfl_up_sync(0xffffffffu, v, d);
        if (lane >= d) v += u;
    }
    __shared__ int wsum[32];
    if (lane == 31) wsum[wid] = v;
    __syncthreads();
    if (wid == 0) {
        int w = wsum[lane];
        #pragma unroll
        for (int d = 1; d < 32; d <<= 1) {
            int u = __shfl_up_sync(0xffffffffu, w, d);
            if (lane >= d) w += u;
        }
        wsum[lane] = w;
    }
    __syncthreads();
    int off = (v - s) + (wid ? wsum[wid - 1] : 0);
    #pragma unroll
    for (int j = 0; j < 16; j++) g_rowptr[base + j] = off + local[j];
    if (t == 1023) g_rowptr[NN] = off + s;
}

__global__ void k_scatter(const int* __restrict__ src, const int* __restrict__ dst) {
    int e = blockIdx.x * blockDim.x + threadIdx.x;
    if (e < EE) {
        int d = dst[e];
        int p = atomicAdd(&g_cursor[d], 1);
        g_col[g_rowptr[d] + p] = src[e];
    }
}

__global__ void k_transpose(const float* __restrict__ w) {
    int i = blockIdx.x * blockDim.x + threadIdx.x;
    if (i < D1 * H2) {
        int o = i >> 8, k = i & 255;
        g_fc1wT[k * D1 + o] = w[i];
    }
}

// ---------------- layer-1 aggregation (128-wide), dinv fused, unroll-4 ----------------
__global__ __launch_bounds__(256) void k_agg1(const float* __restrict__ X) {
    int gi = threadIdx.x >> 5;
    int lane = threadIdx.x & 31;
    int d = blockIdx.x * 8 + gi;
    const float4* X4 = (const float4*)X;
    float scd = g_dinv[d];
    float4 acc = X4[(size_t)d * 32 + lane];
    acc.x *= scd; acc.y *= scd; acc.z *= scd; acc.w *= scd;
    int j = g_rowptr[d], s1 = g_rowptr[d + 1];
    for (; j + 4 <= s1; j += 4) {
        int i0 = g_col[j], i1 = g_col[j + 1], i2 = g_col[j + 2], i3 = g_col[j + 3];
        float w0 = g_dinv[i0], w1 = g_dinv[i1], w2 = g_dinv[i2], w3 = g_dinv[i3];
        float4 v0 = X4[(size_t)i0 * 32 + lane];
        float4 v1 = X4[(size_t)i1 * 32 + lane];
        float4 v2 = X4[(size_t)i2 * 32 + lane];
        float4 v3 = X4[(size_t)i3 * 32 + lane];
        acc.x += w0 * v0.x + w1 * v1.x + w2 * v2.x + w3 * v3.x;
        acc.y += w0 * v0.y + w1 * v1.y + w2 * v2.y + w3 * v3.y;
        acc.z += w0 * v0.z + w1 * v1.z + w2 * v2.z + w3 * v3.z;
        acc.w += w0 * v0.w + w1 * v1.w + w2 * v2.w + w3 * v3.w;
    }
    for (; j < s1; j++) {
        int s = g_col[j];
        float w = g_dinv[s];
        float4 v = X4[(size_t)s * 32 + lane];
        acc.x += w * v.x; acc.y += w * v.y; acc.z += w * v.z; acc.w += w * v.w;
    }
    acc.x *= scd; acc.y *= scd; acc.z *= scd; acc.w *= scd;
    ((float4*)g_Z)[(size_t)d * 32 + lane] = acc;
}

// ---------------- tf32 tensor-core GEMM, register double-buffered ----------------
// mode 0: C (float*) = relu(AB + bias)   mode 1: Cb (bf16*) = dinv[row] * AB
__device__ __forceinline__ unsigned int f2tf32(float x) {
    unsigned int r;
    asm("cvt.rna.tf32.f32 %0, %1;" : "=r"(r) : "f"(x));
    return r;
}
__device__ __forceinline__ void mma_tf32(float* d, const unsigned int* a, const unsigned int* b) {
    asm volatile(
        "mma.sync.aligned.m16n8k8.row.col.f32.tf32.tf32.f32 "
        "{%0,%1,%2,%3},{%4,%5,%6,%7},{%8,%9},{%0,%1,%2,%3};\n"
        : "+f"(d[0]), "+f"(d[1]), "+f"(d[2]), "+f"(d[3])
        : "r"(a[0]), "r"(a[1]), "r"(a[2]), "r"(a[3]), "r"(b[0]), "r"(b[1]));
}

#define GBK 32
__global__ __launch_bounds__(256) void k_gemm_tc(const float* __restrict__ A,
                                                 const float* __restrict__ B,
                                                 float* __restrict__ C,
                                                 __nv_bfloat16* __restrict__ Cb,
                                                 const float* __restrict__ bias,
                                                 int K, int mode) {
    __shared__ unsigned int As[GBK][136];
    __shared__ unsigned int Bs[GBK][136];
    int t = threadIdx.x;
    int row0 = blockIdx.y * 128, col0 = blockIdx.x * 128;
    int wid = t >> 5, lane = t & 31;
    int wr = wid >> 2, wc = wid & 3;
    int g = lane >> 2, tig = lane & 3;
    float acc[4][4][4] = {};

    int arr = t >> 3, akq = (t & 7) * 4;
    int bkr = t >> 5, bnq = (t & 31) * 4;

    float4 ra[4], rb[4];
    #pragma unroll
    for (int j = 0; j < 4; j++)
        ra[j] = *(const float4*)&A[(size_t)(row0 + arr + j * 32) * K + akq];
    #pragma unroll
    for (int j = 0; j < 4; j++)
        rb[j] = *(const float4*)&B[(size_t)(bkr + j * 8) * 256 + col0 + bnq];

    for (int k0 = 0; k0 < K; k0 += GBK) {
        #pragma unroll
        for (int j = 0; j < 4; j++) {
            int r = arr + j * 32;
            As[akq + 0][r] = f2tf32(ra[j].x); As[akq + 1][r] = f2tf32(ra[j].y);
            As[akq + 2][r] = f2tf32(ra[j].z); As[akq + 3][r] = f2tf32(ra[j].w);
        }
        #pragma unroll
        for (int j = 0; j < 4; j++) {
            int kr = bkr + j * 8;
            Bs[kr][bnq + 0] = f2tf32(rb[j].x); Bs[kr][bnq + 1] = f2tf32(rb[j].y);
            Bs[kr][bnq + 2] = f2tf32(rb[j].z); Bs[kr][bnq + 3] = f2tf32(rb[j].w);
        }
        __syncthreads();

        bool more = (k0 + GBK) < K;
        if (more) {
            #pragma unroll
            for (int j = 0; j < 4; j++)
                ra[j] = *(const float4*)&A[(size_t)(row0 + arr + j * 32) * K + k0 + GBK + akq];
            #pragma unroll
            for (int j = 0; j < 4; j++)
                rb[j] = *(const float4*)&B[(size_t)(k0 + GBK + bkr + j * 8) * 256 + col0 + bnq];
        }

        #pragma unroll
        for (int kk = 0; kk < GBK; kk += 8) {
            unsigned int af[4][4], bf[4][2];
            #pragma unroll
            for (int mi = 0; mi < 4; mi++) {
                int r = wr * 64 + mi * 16 + g;
                af[mi][0] = As[kk + tig][r];
                af[mi][1] = As[kk + tig][r + 8];
                af[mi][2] = As[kk + tig + 4][r];
                af[mi][3] = As[kk + tig + 4][r + 8];
            }
            #pragma unroll
            for (int ni = 0; ni < 4; ni++) {
                int c = wc * 32 + ni * 8 + g;
                bf[ni][0] = Bs[kk + tig][c];
                bf[ni][1] = Bs[kk + tig + 4][c];
            }
            #pragma unroll
            for (int mi = 0; mi < 4; mi++)
                #pragma unroll
                for (int ni = 0; ni < 4; ni++)
                    mma_tf32(acc[mi][ni], af[mi], bf[ni]);
        }
        __syncthreads();
    }

    #pragma unroll
    for (int mi = 0; mi < 4; mi++) {
        #pragma unroll
        for (int half = 0; half < 2; half++) {
            int r = row0 + wr * 64 + mi * 16 + g + half * 8;
            float sc = (mode == 1) ? g_dinv[r] : 1.0f;
            #pragma unroll
            for (int ni = 0; ni < 4; ni++) {
                int c = col0 + wc * 32 + ni * 8 + tig * 2;
                float v0 = acc[mi][ni][half * 2 + 0];
                float v1 = acc[mi][ni][half * 2 + 1];
                if (mode == 0) {
                    v0 = fmaxf(v0 + bias[c], 0.0f);
                    v1 = fmaxf(v1 + bias[c + 1], 0.0f);
                    *(float2*)&C[(size_t)r * 256 + c] = make_float2(v0, v1);
                } else {
                    __nv_bfloat162 bv = __floats2bfloat162_rn(v0 * sc, v1 * sc);
                    *(__nv_bfloat162*)&Cb[(size_t)r * 256 + c] = bv;
                }
            }
        }
    }
}

// ---------------- layer-2 aggregation (256-wide, bf16 input), unroll-4 ----------------
__global__ __launch_bounds__(256) void k_agg(float* __restrict__ out,
                                             const float* __restrict__ bias) {
    int gi = threadIdx.x >> 6;
    int lane = threadIdx.x & 63;   // 4 features per lane
    int d = blockIdx.x * 4 + gi;
    const uint2* Xb = (const uint2*)g_Xb;   // uint2 = 4 bf16

    uint2 u = Xb[(size_t)d * 64 + lane];
    float2 l0 = __bfloat1622float2(*(__nv_bfloat162*)&u.x);
    float2 h0 = __bfloat1622float2(*(__nv_bfloat162*)&u.y);
    float4 acc = make_float4(l0.x, l0.y, h0.x, h0.y);

    int j = g_rowptr[d], s1 = g_rowptr[d + 1];
    for (; j + 4 <= s1; j += 4) {
        int i0 = g_col[j], i1 = g_col[j + 1], i2 = g_col[j + 2], i3 = g_col[j + 3];
        uint2 u0 = Xb[(size_t)i0 * 64 + lane];
        uint2 u1 = Xb[(size_t)i1 * 64 + lane];
        uint2 u2 = Xb[(size_t)i2 * 64 + lane];
        uint2 u3 = Xb[(size_t)i3 * 64 + lane];
        float2 a0 = __bfloat1622float2(*(__nv_bfloat162*)&u0.x);
        float2 b0 = __bfloat1622float2(*(__nv_bfloat162*)&u0.y);
        float2 a1 = __bfloat1622float2(*(__nv_bfloat162*)&u1.x);
        float2 b1 = __bfloat1622float2(*(__nv_bfloat162*)&u1.y);
        float2 a2 = __bfloat1622float2(*(__nv_bfloat162*)&u2.x);
        float2 b2v = __bfloat1622float2(*(__nv_bfloat162*)&u2.y);
        float2 a3 = __bfloat1622float2(*(__nv_bfloat162*)&u3.x);
        float2 b3 = __bfloat1622float2(*(__nv_bfloat162*)&u3.y);
        acc.x += a0.x + a1.x + a2.x + a3.x;
        acc.y += a0.y + a1.y + a2.y + a3.y;
        acc.z += b0.x + b1.x + b2v.x + b3.x;
        acc.w += b0.y + b1.y + b2v.y + b3.y;
    }
    for (; j < s1; j++) {
        int s = g_col[j];
        uint2 us = Xb[(size_t)s * 64 + lane];
        float2 a = __bfloat1622float2(*(__nv_bfloat162*)&us.x);
        float2 b = __bfloat1622float2(*(__nv_bfloat162*)&us.y);
        acc.x += a.x; acc.y += a.y; acc.z += b.x; acc.w += b.y;
    }
    float sc = g_dinv[d];
    float4 bv = ((const float4*)bias)[lane];
    float4 o;
    o.x = acc.x * sc + bv.x; o.y = acc.y * sc + bv.y;
    o.z = acc.z * sc + bv.z; o.w = acc.w * sc + bv.w;
    ((float4*)out)[(size_t)d * 64 + lane] = o;
}

// ---------------- per-node MLP ----------------
#define FC_NODES 64
__global__ void k_fc(const float* __restrict__ h2,
                     const float* __restrict__ fc1b,
                     const float* __restrict__ fc2w, const float* __restrict__ fc2b) {
    __shared__ float h2s[4][256];
    __shared__ float a1s[4][64];
    __shared__ float ps[4][2];
    __shared__ float gfl[2][256];
    int t = threadIdx.x;
    gfl[0][t] = 0.0f; gfl[1][t] = 0.0f;
    int n0 = blockIdx.x * FC_NODES;
    int nq = t >> 6, o = t & 63;
    for (int q = 0; q < FC_NODES; q += 4) {
        for (int i = t; i < 1024; i += 256)
            h2s[i >> 8][i & 255] = h2[(size_t)(n0 + q + (i >> 8)) * 256 + (i & 255)];
        __syncthreads();
        float dot = fc1b[o];
        #pragma unroll 8
        for (int k = 0; k < 256; k++)
            dot += g_fc1wT[k * 64 + o] * h2s[nq][k];
        a1s[nq][o] = tanhf(dot);
        __syncthreads();
        if (t < 8) {
            int n = t >> 1, c = t & 1;
            float l = fc2b[c];
            #pragma unroll
            for (int k = 0; k < 64; k++) l += fc2w[c * 64 + k] * a1s[n][k];
            ps[n][c] = l;
        }
        __syncthreads();
        if (t < 4) {
            float l0 = ps[t][0], l1 = ps[t][1];
            float m = fmaxf(l0, l1);
            float e0 = expf(l0 - m), e1 = expf(l1 - m);
            float inv = 1.0f / (e0 + e1);
            float p0 = e0 * inv, p1 = e1 * inv;
            ps[t][0] = p0; ps[t][1] = p1;
            g_assign[2 * (n0 + q + t)] = p0;
            g_assign[2 * (n0 + q + t) + 1] = p1;
        }
        __syncthreads();
        #pragma unroll
        for (int n = 0; n < 4; n++) {
            float p0 = ps[n][0], p1 = ps[n][1];
            float hv = h2s[n][t];
            gfl[0][t] += p0 * hv;
            gfl[1][t] += p1 * hv;
        }
        __syncthreads();
    }
    atomicAdd(&g_gf[t], gfl[0][t]);
    atomicAdd(&g_gf[256 + t], gfl[1][t]);
}

// ---------------- new_adj ----------------
__global__ void k_newadj(const int* __restrict__ src, const int* __restrict__ dst) {
    float a0 = 0, a1 = 0, a2 = 0, a3 = 0;
    const float2* as2 = (const float2*)g_assign;
    for (int e = blockIdx.x * blockDim.x + threadIdx.x; e < EE; e += gridDim.x * blockDim.x) {
        int s = src[e], d = dst[e];
        float2 sv = as2[s];
        float2 dv = as2[d];
        a0 += sv.x * dv.x; a1 += sv.x * dv.y; a2 += sv.y * dv.x; a3 += sv.y * dv.y;
    }
    #pragma unroll
    for (int w = 16; w; w >>= 1) {
        a0 += __shfl_down_sync(0xffffffff, a0, w);
        a1 += __shfl_down_sync(0xffffffff, a1, w);
        a2 += __shfl_down_sync(0xffffffff, a2, w);
        a3 += __shfl_down_sync(0xffffffff, a3, w);
    }
    __shared__ float sa[8][4];
    int lane = threadIdx.x & 31, wid = threadIdx.x >> 5;
    if (lane == 0) { sa[wid][0] = a0; sa[wid][1] = a1; sa[wid][2] = a2; sa[wid][3] = a3; }
    __syncthreads();
    if (threadIdx.x < 4) {
        float sum = 0;
        #pragma unroll
        for (int w = 0; w < 8; w++) sum += sa[w][threadIdx.x];
        atomicAdd(&g_newadj[threadIdx.x], sum);
    }
}

// ---------------- finalize ----------------
__global__ void k_final(float* __restrict__ out) {
    int t = threadIdx.x;
    float g0 = g_gf[t], g1 = g_gf[256 + t];
    out[t]       = 0.5f * (g0 + g1);
    out[256 + t] = fminf(fmaxf(g0, -100.0f), 100.0f);
    out[512 + t] = fminf(fmaxf(g1, -100.0f), 100.0f);
    if (t == 0) {
        float a00 = g_newadj[0], a01 = g_newadj[1], a10 = g_newadj[2], a11 = g_newadj[3];
        float den0 = fmaxf(fabsf(a00) + fabsf(a01), 1e-12f);
        float den1 = fmaxf(fabsf(a10) + fabsf(a11), 1e-12f);
        float nd0 = a00 / den0, nd1 = a11 / den1;
        out[768] = 0.5f * ((nd0 - 1.0f) * (nd0 - 1.0f) + (nd1 - 1.0f) * (nd1 - 1.0f));
    }
}

extern "C" void kernel_launch(void* const* d_in, const int* in_sizes, int n_in,
                              void* d_out, int out_size) {
    const float* features = (const float*)d_in[0];
    const int*   edges    = (const int*)d_in[1];
    const float* W1    = (const float*)d_in[2];
    const float* b1    = (const float*)d_in[3];
    const float* W2    = (const float*)d_in[4];
    const float* b2    = (const float*)d_in[5];
    const float* fc1w  = (const float*)d_in[6];
    const float* fc1b  = (const float*)d_in[7];
    const float* fc2w  = (const float*)d_in[8];
    const float* fc2b  = (const float*)d_in[9];
    float* out = (float*)d_out;
    const int* src = edges;
    const int* dst = edges + EE;

    float *ph1, *ph2, *pZ;
    __nv_bfloat16* pXb;
    cudaGetSymbolAddress((void**)&pXb, g_Xb);
    cudaGetSymbolAddress((void**)&ph1, g_h1);
    cudaGetSymbolAddress((void**)&ph2, g_h2);
    cudaGetSymbolAddress((void**)&pZ,  g_Z);

    k_init<<<NN / 256, 256>>>();
    k_deg<<<EE / 256, 256>>>(dst);
    k_scan<<<1, 1024>>>();
    k_scatter<<<EE / 256, 256>>>(src, dst);
    k_transpose<<<(D1 * H2) / 256, 256>>>(fc1w);

    // layer 1: aggregate raw features (dinv fused), then tensor-core transform
    k_agg1<<<NN / 8, 256>>>(features);
    dim3 gg(2, NN / 128);
    k_gemm_tc<<<gg, 256>>>(pZ, W1, ph1, (__nv_bfloat16*)0, b1, F_IN, 0);

    // layer 2: transform (bf16 out), aggregate, MLP
    k_gemm_tc<<<gg, 256>>>(ph1, W2, (float*)0, pXb, (const float*)0, H1, 1);
    k_agg<<<NN / 4, 256>>>(ph2, b2);
    k_fc<<<NN / FC_NODES, 256>>>(ph2, fc1b, fc2w, fc2b);

    k_newadj<<<256, 256>>>(src, dst);
    k_final<<<1, 256>>>(out);
}

// round 8
// speedup vs baseline: 1.9677x; 1.5468x over previous
#include <cuda_runtime.h>
#include <cuda_bf16.h>
#include <cstdint>
#include <math.h>

#define NN     16384
#define EE     524288
#define F_IN   128
#define H1     256
#define H2     256
#define D1     64

// ---------------- scratch (device globals; no allocations) ----------------
__device__ __nv_bfloat16 g_Yb[NN * F_IN]; // dinv[r]*features, bf16
__device__ float g_Z[NN * F_IN];          // aggregated features (layer-1 pre-GEMM)
__device__ __nv_bfloat16 g_Xb[NN * H1];   // layer-2 gemm output, dinv-scaled, bf16
__device__ float g_h1[NN * H1];
__device__ float g_h2[NN * H2];
__device__ float g_a1[NN * D1];           // tanh(fc1) output
__device__ float g_dinv[NN];
__device__ int   g_deg[NN];
__device__ int   g_rowptr[NN + 1];
__device__ int   g_cursor[NN];
__device__ int   g_col[EE];
__device__ float g_fc1wT[H2 * D1];
__device__ float g_assign[NN * 2];
__device__ float g_gf[2 * H2];
__device__ float g_newadj[4];

// ---------------- init ----------------
__global__ void k_init() {
    int i = blockIdx.x * blockDim.x + threadIdx.x;
    if (i < NN) { g_deg[i] = 1; g_cursor[i] = 0; }
    if (i < 2 * H2) g_gf[i] = 0.0f;
    if (i < 4) g_newadj[i] = 0.0f;
}

__global__ void k_deg(const int* __restrict__ dst) {
    int e = blockIdx.x * blockDim.x + threadIdx.x;
    if (e < EE) atomicAdd(&g_deg[dst[e]], 1);
}

// ---------------- fused scan + dinv: 1 block, 1024 threads ----------------
__global__ __launch_bounds__(1024) void k_scan() {
    int t = threadIdx.x;
    int base = t * 16;
    int local[16];
    int s = 0;
    #pragma unroll
    for (int j = 0; j < 16; j++) {
        int dg = g_deg[base + j];
        g_dinv[base + j] = rsqrtf((float)dg);
        local[j] = s;
        s += dg - 1;
    }
    int lane = t & 31, wid = t >> 5;
    int v = s;
    #pragma unroll
    for (int d = 1; d < 32; d <<= 1) {
        int u = __shfl_up_sync(0xffffffffu, v, d);
        if (lane >= d) v += u;
    }
    __shared__ int wsum[32];
    if (lane == 31) wsum[wid] = v;
    __syncthreads();
    if (wid == 0) {
        int w = wsum[lane];
        #pragma unroll
        for (int d = 1; d < 32; d <<= 1) {
            int u = __shfl_up_sync(0xffffffffu, w, d);
            if (lane >= d) w += u;
        }
        wsum[lane] = w;
    }
    __syncthreads();
    int off = (v - s) + (wid ? wsum[wid - 1] : 0);
    #pragma unroll
    for (int j = 0; j < 16; j++) g_rowptr[base + j] = off + local[j];
    if (t == 1023) g_rowptr[NN] = off + s;
}

__global__ void k_scatter(const int* __restrict__ src, const int* __restrict__ dst) {
    int e = blockIdx.x * blockDim.x + threadIdx.x;
    if (e < EE) {
        int d = dst[e];
        int p = atomicAdd(&g_cursor[d], 1);
        g_col[g_rowptr[d] + p] = src[e];
    }
}

__global__ void k_transpose(const float* __restrict__ w) {
    int i = blockIdx.x * blockDim.x + threadIdx.x;
    if (i < D1 * H2) {
        int o = i >> 8, k = i & 255;
        g_fc1wT[k * D1 + o] = w[i];
    }
}

// ---------------- Yb = bf16(dinv[r]*X) ----------------
__global__ void k_pre(const float* __restrict__ X) {
    int i = blockIdx.x * blockDim.x + threadIdx.x;   // float4 index
    int node = i >> 5;
    float sc = g_dinv[node];
    float4 v = ((const float4*)X)[i];
    __nv_bfloat162 lo = __floats2bfloat162_rn(v.x * sc, v.y * sc);
    __nv_bfloat162 hi = __floats2bfloat162_rn(v.z * sc, v.w * sc);
    uint2 u;
    u.x = *(unsigned int*)&lo; u.y = *(unsigned int*)&hi;
    ((uint2*)g_Yb)[i] = u;
}

// ---------------- layer-1 aggregation (128-wide, bf16 input), unroll-4 ----------------
// Z[d] = dinv[d] * (Yb[d] + sum Yb[s])
__global__ __launch_bounds__(256) void k_agg1() {
    int gi = threadIdx.x >> 5;
    int lane = threadIdx.x & 31;
    int d = blockIdx.x * 8 + gi;
    const uint2* Y = (const uint2*)g_Yb;   // 32 uint2 (4 bf16) per node

    uint2 u = Y[(size_t)d * 32 + lane];
    float2 l0 = __bfloat1622float2(*(__nv_bfloat162*)&u.x);
    float2 h0 = __bfloat1622float2(*(__nv_bfloat162*)&u.y);
    float4 acc = make_float4(l0.x, l0.y, h0.x, h0.y);

    int j = g_rowptr[d], s1 = g_rowptr[d + 1];
    for (; j + 4 <= s1; j += 4) {
        int i0 = g_col[j], i1 = g_col[j + 1], i2 = g_col[j + 2], i3 = g_col[j + 3];
        uint2 u0 = Y[(size_t)i0 * 32 + lane];
        uint2 u1 = Y[(size_t)i1 * 32 + lane];
        uint2 u2 = Y[(size_t)i2 * 32 + lane];
        uint2 u3 = Y[(size_t)i3 * 32 + lane];
        float2 a0 = __bfloat1622float2(*(__nv_bfloat162*)&u0.x);
        float2 b0 = __bfloat1622float2(*(__nv_bfloat162*)&u0.y);
        float2 a1 = __bfloat1622float2(*(__nv_bfloat162*)&u1.x);
        float2 b1 = __bfloat1622float2(*(__nv_bfloat162*)&u1.y);
        float2 a2 = __bfloat1622float2(*(__nv_bfloat162*)&u2.x);
        float2 b2 = __bfloat1622float2(*(__nv_bfloat162*)&u2.y);
        float2 a3 = __bfloat1622float2(*(__nv_bfloat162*)&u3.x);
        float2 b3 = __bfloat1622float2(*(__nv_bfloat162*)&u3.y);
        acc.x += a0.x + a1.x + a2.x + a3.x;
        acc.y += a0.y + a1.y + a2.y + a3.y;
        acc.z += b0.x + b1.x + b2.x + b3.x;
        acc.w += b0.y + b1.y + b2.y + b3.y;
    }
    for (; j < s1; j++) {
        int s = g_col[j];
        uint2 us = Y[(size_t)s * 32 + lane];
        float2 a = __bfloat1622float2(*(__nv_bfloat162*)&us.x);
        float2 b = __bfloat1622float2(*(__nv_bfloat162*)&us.y);
        acc.x += a.x; acc.y += a.y; acc.z += b.x; acc.w += b.y;
    }
    float scd = g_dinv[d];
    acc.x *= scd; acc.y *= scd; acc.z *= scd; acc.w *= scd;
    ((float4*)g_Z)[(size_t)d * 32 + lane] = acc;
}

// ---------------- tf32 helpers ----------------
__device__ __forceinline__ unsigned int f2tf32(float x) {
    unsigned int r;
    asm("cvt.rna.tf32.f32 %0, %1;" : "=r"(r) : "f"(x));
    return r;
}
__device__ __forceinline__ void mma_tf32(float* d, const unsigned int* a, const unsigned int* b) {
    asm volatile(
        "mma.sync.aligned.m16n8k8.row.col.f32.tf32.tf32.f32 "
        "{%0,%1,%2,%3},{%4,%5,%6,%7},{%8,%9},{%0,%1,%2,%3};\n"
        : "+f"(d[0]), "+f"(d[1]), "+f"(d[2]), "+f"(d[3])
        : "r"(a[0]), "r"(a[1]), "r"(a[2]), "r"(a[3]), "r"(b[0]), "r"(b[1]));
}

// ---------------- main tf32 GEMM (N=256), register double-buffered ----------------
// mode 0: C (float*) = relu(AB + bias)   mode 1: Cb (bf16*) = dinv[row] * AB
#define GBK 32
__global__ __launch_bounds__(256) void k_gemm_tc(const float* __restrict__ A,
                                                 const float* __restrict__ B,
                                                 float* __restrict__ C,
                                                 __nv_bfloat16* __restrict__ Cb,
                                                 const float* __restrict__ bias,
                                                 int K, int mode) {
    __shared__ unsigned int As[GBK][136];
    __shared__ unsigned int Bs[GBK][136];
    int t = threadIdx.x;
    int row0 = blockIdx.y * 128, col0 = blockIdx.x * 128;
    int wid = t >> 5, lane = t & 31;
    int wr = wid >> 2, wc = wid & 3;
    int g = lane >> 2, tig = lane & 3;
    float acc[4][4][4] = {};

    int arr = t >> 3, akq = (t & 7) * 4;
    int bkr = t >> 5, bnq = (t & 31) * 4;

    float4 ra[4], rb[4];
    #pragma unroll
    for (int j = 0; j < 4; j++)
        ra[j] = *(const float4*)&A[(size_t)(row0 + arr + j * 32) * K + akq];
    #pragma unroll
    for (int j = 0; j < 4; j++)
        rb[j] = *(const float4*)&B[(size_t)(bkr + j * 8) * 256 + col0 + bnq];

    for (int k0 = 0; k0 < K; k0 += GBK) {
        #pragma unroll
        for (int j = 0; j < 4; j++) {
            int r = arr + j * 32;
            As[akq + 0][r] = f2tf32(ra[j].x); As[akq + 1][r] = f2tf32(ra[j].y);
            As[akq + 2][r] = f2tf32(ra[j].z); As[akq + 3][r] = f2tf32(ra[j].w);
        }
        #pragma unroll
        for (int j = 0; j < 4; j++) {
            int kr = bkr + j * 8;
            Bs[kr][bnq + 0] = f2tf32(rb[j].x); Bs[kr][bnq + 1] = f2tf32(rb[j].y);
            Bs[kr][bnq + 2] = f2tf32(rb[j].z); Bs[kr][bnq + 3] = f2tf32(rb[j].w);
        }
        __syncthreads();

        bool more = (k0 + GBK) < K;
        if (more) {
            #pragma unroll
            for (int j = 0; j < 4; j++)
                ra[j] = *(const float4*)&A[(size_t)(row0 + arr + j * 32) * K + k0 + GBK + akq];
            #pragma unroll
            for (int j = 0; j < 4; j++)
                rb[j] = *(const float4*)&B[(size_t)(k0 + GBK + bkr + j * 8) * 256 + col0 + bnq];
        }

        #pragma unroll
        for (int kk = 0; kk < GBK; kk += 8) {
            unsigned int af[4][4], bf[4][2];
            #pragma unroll
            for (int mi = 0; mi < 4; mi++) {
                int r = wr * 64 + mi * 16 + g;
                af[mi][0] = As[kk + tig][r];
                af[mi][1] = As[kk + tig][r + 8];
                af[mi][2] = As[kk + tig + 4][r];
                af[mi][3] = As[kk + tig + 4][r + 8];
            }
            #pragma unroll
            for (int ni = 0; ni < 4; ni++) {
                int c = wc * 32 + ni * 8 + g;
                bf[ni][0] = Bs[kk + tig][c];
                bf[ni][1] = Bs[kk + tig + 4][c];
            }
            #pragma unroll
            for (int mi = 0; mi < 4; mi++)
                #pragma unroll
                for (int ni = 0; ni < 4; ni++)
                    mma_tf32(acc[mi][ni], af[mi], bf[ni]);
        }
        __syncthreads();
    }

    #pragma unroll
    for (int mi = 0; mi < 4; mi++) {
        #pragma unroll
        for (int half = 0; half < 2; half++) {
            int r = row0 + wr * 64 + mi * 16 + g + half * 8;
            float sc = (mode == 1) ? g_dinv[r] : 1.0f;
            #pragma unroll
            for (int ni = 0; ni < 4; ni++) {
                int c = col0 + wc * 32 + ni * 8 + tig * 2;
                float v0 = acc[mi][ni][half * 2 + 0];
                float v1 = acc[mi][ni][half * 2 + 1];
                if (mode == 0) {
                    v0 = fmaxf(v0 + bias[c], 0.0f);
                    v1 = fmaxf(v1 + bias[c + 1], 0.0f);
                    *(float2*)&C[(size_t)r * 256 + c] = make_float2(v0, v1);
                } else {
                    __nv_bfloat162 bv = __floats2bfloat162_rn(v0 * sc, v1 * sc);
                    *(__nv_bfloat162*)&Cb[(size_t)r * 256 + c] = bv;
                }
            }
        }
    }
}

// ---------------- layer-2 aggregation (256-wide, bf16 input), unroll-4 ----------------
__global__ __launch_bounds__(256) void k_agg(float* __restrict__ out,
                                             const float* __restrict__ bias) {
    int gi = threadIdx.x >> 6;
    int lane = threadIdx.x & 63;
    int d = blockIdx.x * 4 + gi;
    const uint2* Xb = (const uint2*)g_Xb;

    uint2 u = Xb[(size_t)d * 64 + lane];
    float2 l0 = __bfloat1622float2(*(__nv_bfloat162*)&u.x);
    float2 h0 = __bfloat1622float2(*(__nv_bfloat162*)&u.y);
    float4 acc = make_float4(l0.x, l0.y, h0.x, h0.y);

    int j = g_rowptr[d], s1 = g_rowptr[d + 1];
    for (; j + 4 <= s1; j += 4) {
        int i0 = g_col[j], i1 = g_col[j + 1], i2 = g_col[j + 2], i3 = g_col[j + 3];
        uint2 u0 = Xb[(size_t)i0 * 64 + lane];
        uint2 u1 = Xb[(size_t)i1 * 64 + lane];
        uint2 u2 = Xb[(size_t)i2 * 64 + lane];
        uint2 u3 = Xb[(size_t)i3 * 64 + lane];
        float2 a0 = __bfloat1622float2(*(__nv_bfloat162*)&u0.x);
        float2 b0 = __bfloat1622float2(*(__nv_bfloat162*)&u0.y);
        float2 a1 = __bfloat1622float2(*(__nv_bfloat162*)&u1.x);
        float2 b1 = __bfloat1622float2(*(__nv_bfloat162*)&u1.y);
        float2 a2 = __bfloat1622float2(*(__nv_bfloat162*)&u2.x);
        float2 b2 = __bfloat1622float2(*(__nv_bfloat162*)&u2.y);
        float2 a3 = __bfloat1622float2(*(__nv_bfloat162*)&u3.x);
        float2 b3 = __bfloat1622float2(*(__nv_bfloat162*)&u3.y);
        acc.x += a0.x + a1.x + a2.x + a3.x;
        acc.y += a0.y + a1.y + a2.y + a3.y;
        acc.z += b0.x + b1.x + b2.x + b3.x;
        acc.w += b0.y + b1.y + b2.y + b3.y;
    }
    for (; j < s1; j++) {
        int s = g_col[j];
        uint2 us = Xb[(size_t)s * 64 + lane];
        float2 a = __bfloat1622float2(*(__nv_bfloat162*)&us.x);
        float2 b = __bfloat1622float2(*(__nv_bfloat162*)&us.y);
        acc.x += a.x; acc.y += a.y; acc.z += b.x; acc.w += b.y;
    }
    float sc = g_dinv[d];
    float4 bv = ((const float4*)bias)[lane];
    float4 o;
    o.x = acc.x * sc + bv.x; o.y = acc.y * sc + bv.y;
    o.z = acc.z * sc + bv.z; o.w = acc.w * sc + bv.w;
    ((float4*)out)[(size_t)d * 64 + lane] = o;
}

// ---------------- fc1 via tf32 MMA: a1 = tanh(h2 @ fc1wT + fc1b) ----------------
// M=16384, N=64, K=256. Tile 128x64, 8 warps (4 row-groups x 2 col-groups).
__global__ __launch_bounds__(256) void k_fc1_tc(const float* __restrict__ A,
                                                const float* __restrict__ fc1b) {
    __shared__ unsigned int As[GBK][136];
    __shared__ unsigned int Bs[GBK][72];
    int t = threadIdx.x;
    int row0 = blockIdx.x * 128;
    int wid = t >> 5, lane = t & 31;
    int wr = wid >> 1, wc = wid & 1;     // rows wr*32, cols wc*32
    int g = lane >> 2, tig = lane & 3;
    float acc[2][4][4] = {};

    int arr = t >> 3, akq = (t & 7) * 4;     // A: 32 rows x 8 quads
    int bkr = t >> 3, bcq = (t & 7) * 8;     // B: 32 k-rows x 8 col-octs

    float4 ra[4];
    float4 rb0, rb1;
    #pragma unroll
    for (int j = 0; j < 4; j++)
        ra[j] = *(const float4*)&A[(size_t)(row0 + arr + j * 32) * 256 + akq];
    rb0 = *(const float4*)&g_fc1wT[(size_t)bkr * 64 + bcq];
    rb1 = *(const float4*)&g_fc1wT[(size_t)bkr * 64 + bcq + 4];

    for (int k0 = 0; k0 < 256; k0 += GBK) {
        #pragma unroll
        for (int j = 0; j < 4; j++) {
            int r = arr + j * 32;
            As[akq + 0][r] = f2tf32(ra[j].x); As[akq + 1][r] = f2tf32(ra[j].y);
            As[akq + 2][r] = f2tf32(ra[j].z); As[akq + 3][r] = f2tf32(ra[j].w);
        }
        Bs[bkr][bcq + 0] = f2tf32(rb0.x); Bs[bkr][bcq + 1] = f2tf32(rb0.y);
        Bs[bkr][bcq + 2] = f2tf32(rb0.z); Bs[bkr][bcq + 3] = f2tf32(rb0.w);
        Bs[bkr][bcq + 4] = f2tf32(rb1.x); Bs[bkr][bcq + 5] = f2tf32(rb1.y);
        Bs[bkr][bcq + 6] = f2tf32(rb1.z); Bs[bkr][bcq + 7] = f2tf32(rb1.w);
        __syncthreads();

        bool more = (k0 + GBK) < 256;
        if (more) {
            #pragma unroll
            for (int j = 0; j < 4; j++)
                ra[j] = *(const float4*)&A[(size_t)(row0 + arr + j * 32) * 256 + k0 + GBK + akq];
            rb0 = *(const float4*)&g_fc1wT[(size_t)(k0 + GBK + bkr) * 64 + bcq];
            rb1 = *(const float4*)&g_fc1wT[(size_t)(k0 + GBK + bkr) * 64 + bcq + 4];
        }

        #pragma unroll
        for (int kk = 0; kk < GBK; kk += 8) {
            unsigned int af[2][4], bf[4][2];
            #pragma unroll
            for (int mi = 0; mi < 2; mi++) {
                int r = wr * 32 + mi * 16 + g;
                af[mi][0] = As[kk + tig][r];
                af[mi][1] = As[kk + tig][r + 8];
                af[mi][2] = As[kk + tig + 4][r];
                af[mi][3] = As[kk + tig + 4][r + 8];
            }
            #pragma unroll
            for (int ni = 0; ni < 4; ni++) {
                int c = wc * 32 + ni * 8 + g;
                bf[ni][0] = Bs[kk + tig][c];
                bf[ni][1] = Bs[kk + tig + 4][c];
            }
            #pragma unroll
            for (int mi = 0; mi < 2; mi++)
                #pragma unroll
                for (int ni = 0; ni < 4; ni++)
                    mma_tf32(acc[mi][ni], af[mi], bf[ni]);
        }
        __syncthreads();
    }

    #pragma unroll
    for (int mi = 0; mi < 2; mi++) {
        #pragma unroll
        for (int half = 0; half < 2; half++) {
            int r = row0 + wr * 32 + mi * 16 + g + half * 8;
            #pragma unroll
            for (int ni = 0; ni < 4; ni++) {
                int c = wc * 32 + ni * 8 + tig * 2;
                float v0 = tanhf(acc[mi][ni][half * 2 + 0] + fc1b[c]);
                float v1 = tanhf(acc[mi][ni][half * 2 + 1] + fc1b[c + 1]);
                *(float2*)&g_a1[(size_t)r * 64 + c] = make_float2(v0, v1);
            }
        }
    }
}

// ---------------- fc2 + softmax + assign + gf partials ----------------
__global__ __launch_bounds__(256) void k_fc2(const float* __restrict__ h2,
                                             const float* __restrict__ fc2w,
                                             const float* __restrict__ fc2b) {
    __shared__ float a1s[64][65];
    __shared__ float ps[64][2];
    __shared__ float w2s[128];
    __shared__ float gfl[2][256];
    int t = threadIdx.x;
    int n0 = blockIdx.x * 64;
    gfl[0][t] = 0.0f; gfl[1][t] = 0.0f;
    if (t < 128) w2s[t] = fc2w[t];

    // load a1 rows for 64 nodes
    for (int i = t; i < 64 * 64; i += 256)
        a1s[i >> 6][i & 63] = g_a1[(size_t)n0 * 64 + i];
    __syncthreads();

    // logits: 128 threads, node t>>1, class t&1
    if (t < 128) {
        int n = t >> 1, c = t & 1;
        float l = fc2b[c];
        #pragma unroll
        for (int k = 0; k < 64; k++) l += w2s[c * 64 + k] * a1s[n][k];
        ps[n][c] = l;
    }
    __syncthreads();
    if (t < 64) {
        float l0 = ps[t][0], l1 = ps[t][1];
        float m = fmaxf(l0, l1);
        float e0 = expf(l0 - m), e1 = expf(l1 - m);
        float inv = 1.0f / (e0 + e1);
        float p0 = e0 * inv, p1 = e1 * inv;
        ps[t][0] = p0; ps[t][1] = p1;
        g_assign[2 * (n0 + t)] = p0;
        g_assign[2 * (n0 + t) + 1] = p1;
    }
    __syncthreads();

    // gf partials: thread t covers feature t across all 64 nodes, 4 at a time
    for (int q = 0; q < 64; q += 4) {
        float h0 = h2[(size_t)(n0 + q + 0) * 256 + t];
        float h1v = h2[(size_t)(n0 + q + 1) * 256 + t];
        float h2v = h2[(size_t)(n0 + q + 2) * 256 + t];
        float h3 = h2[(size_t)(n0 + q + 3) * 256 + t];
        gfl[0][t] += ps[q][0] * h0 + ps[q + 1][0] * h1v + ps[q + 2][0] * h2v + ps[q + 3][0] * h3;
        gfl[1][t] += ps[q][1] * h0 + ps[q + 1][1] * h1v + ps[q + 2][1] * h2v + ps[q + 3][1] * h3;
    }
    atomicAdd(&g_gf[t], gfl[0][t]);
    atomicAdd(&g_gf[256 + t], gfl[1][t]);
}

// ---------------- new_adj ----------------
__global__ void k_newadj(const int* __restrict__ src, const int* __restrict__ dst) {
    float a0 = 0, a1 = 0, a2 = 0, a3 = 0;
    const float2* as2 = (const float2*)g_assign;
    for (int e = blockIdx.x * blockDim.x + threadIdx.x; e < EE; e += gridDim.x * blockDim.x) {
        int s = src[e], d = dst[e];
        float2 sv = as2[s];
        float2 dv = as2[d];
        a0 += sv.x * dv.x; a1 += sv.x * dv.y; a2 += sv.y * dv.x; a3 += sv.y * dv.y;
    }
    #pragma unroll
    for (int w = 16; w; w >>= 1) {
        a0 += __shfl_down_sync(0xffffffff, a0, w);
        a1 += __shfl_down_sync(0xffffffff, a1, w);
        a2 += __shfl_down_sync(0xffffffff, a2, w);
        a3 += __shfl_down_sync(0xffffffff, a3, w);
    }
    __shared__ float sa[8][4];
    int lane = threadIdx.x & 31, wid = threadIdx.x >> 5;
    if (lane == 0) { sa[wid][0] = a0; sa[wid][1] = a1; sa[wid][2] = a2; sa[wid][3] = a3; }
    __syncthreads();
    if (threadIdx.x < 4) {
        float sum = 0;
        #pragma unroll
        for (int w = 0; w < 8; w++) sum += sa[w][threadIdx.x];
        atomicAdd(&g_newadj[threadIdx.x], sum);
    }
}

// ---------------- finalize ----------------
__global__ void k_final(float* __restrict__ out) {
    int t = threadIdx.x;
    float g0 = g_gf[t], g1 = g_gf[256 + t];
    out[t]       = 0.5f * (g0 + g1);
    out[256 + t] = fminf(fmaxf(g0, -100.0f), 100.0f);
    out[512 + t] = fminf(fmaxf(g1, -100.0f), 100.0f);
    if (t == 0) {
        float a00 = g_newadj[0], a01 = g_newadj[1], a10 = g_newadj[2], a11 = g_newadj[3];
        float den0 = fmaxf(fabsf(a00) + fabsf(a01), 1e-12f);
        float den1 = fmaxf(fabsf(a10) + fabsf(a11), 1e-12f);
        float nd0 = a00 / den0, nd1 = a11 / den1;
        out[768] = 0.5f * ((nd0 - 1.0f) * (nd0 - 1.0f) + (nd1 - 1.0f) * (nd1 - 1.0f));
    }
}

extern "C" void kernel_launch(void* const* d_in, const int* in_sizes, int n_in,
                              void* d_out, int out_size) {
    const float* features = (const float*)d_in[0];
    const int*   edges    = (const int*)d_in[1];
    const float* W1    = (const float*)d_in[2];
    const float* b1    = (const float*)d_in[3];
    const float* W2    = (const float*)d_in[4];
    const float* b2    = (const float*)d_in[5];
    const float* fc1w  = (const float*)d_in[6];
    const float* fc1b  = (const float*)d_in[7];
    const float* fc2w  = (const float*)d_in[8];
    const float* fc2b  = (const float*)d_in[9];
    float* out = (float*)d_out;
    const int* src = edges;
    const int* dst = edges + EE;

    float *ph1, *ph2, *pZ;
    __nv_bfloat16* pXb;
    cudaGetSymbolAddress((void**)&pXb, g_Xb);
    cudaGetSymbolAddress((void**)&ph1, g_h1);
    cudaGetSymbolAddress((void**)&ph2, g_h2);
    cudaGetSymbolAddress((void**)&pZ,  g_Z);

    k_init<<<NN / 256, 256>>>();
    k_deg<<<EE / 256, 256>>>(dst);
    k_scan<<<1, 1024>>>();
    k_scatter<<<EE / 256, 256>>>(src, dst);
    k_transpose<<<(D1 * H2) / 256, 256>>>(fc1w);

    // layer 1: bf16-prescale, aggregate, tensor-core transform
    k_pre<<<(NN * F_IN / 4) / 256, 256>>>(features);
    k_agg1<<<NN / 8, 256>>>();
    dim3 gg(2, NN / 128);
    k_gemm_tc<<<gg, 256>>>(pZ, W1, ph1, (__nv_bfloat16*)0, b1, F_IN, 0);

    // layer 2: transform (bf16 out), aggregate
    k_gemm_tc<<<gg, 256>>>(ph1, W2, (float*)0, pXb, (const float*)0, H1, 1);
    k_agg<<<NN / 4, 256>>>(ph2, b2);

    // MLP head: tensor-core fc1, then fc2/softmax/pool
    k_fc1_tc<<<NN / 128, 256>>>(ph2, fc1b);
    k_fc2<<<NN / 64, 256>>>(ph2, fc2w, fc2b);

    k_newadj<<<256, 256>>>(src, dst);
    k_final<<<1, 256>>>(out);
}

// round 9
// speedup vs baseline: 2.0525x; 1.0431x over previous
#include <cuda_runtime.h>
#include <cuda_bf16.h>
#include <cstdint>
#include <math.h>

#define NN     16384
#define EE     524288
#define F_IN   128
#define H1     256
#define H2     256
#define D1     64

// ---------------- scratch (device globals; no allocations) ----------------
__device__ __nv_bfloat16 g_Yb[NN * F_IN]; // dinv[r]*features, bf16
__device__ float g_Z[NN * F_IN];          // aggregated features (layer-1 pre-GEMM)
__device__ __nv_bfloat16 g_Xb[NN * H1];   // layer-2 gemm output, dinv-scaled, bf16
__device__ float g_h1[NN * H1];
__device__ float g_h2[NN * H2];
__device__ float g_a1[NN * D1];           // tanh(fc1) output
__device__ float g_dinv[NN];
__device__ int   g_deg[NN];
__device__ int   g_rowptr[NN + 1];
__device__ int   g_slot[EE];
__device__ int   g_col[EE];
__device__ float g_fc1wT[H2 * D1];
__device__ float g_assign[NN * 2];
__device__ float g_gf[2 * H2];
__device__ float g_newadj[4];

// ---------------- init + fc1 weight transpose ----------------
__global__ void k_init(const float* __restrict__ w) {
    int i = blockIdx.x * blockDim.x + threadIdx.x;
    if (i < NN) g_deg[i] = 1;
    if (i < 2 * H2) g_gf[i] = 0.0f;
    if (i < 4) g_newadj[i] = 0.0f;
    if (i < D1 * H2) {          // transpose fc1_w [64,256] -> [256,64]
        int o = i >> 8, k = i & 255;
        g_fc1wT[k * D1 + o] = w[i];
    }
}

// ---------------- in-degree histogram; atomicAdd return = slot ----------------
__global__ void k_deg(const int* __restrict__ dst) {
    int e = blockIdx.x * blockDim.x + threadIdx.x;
    if (e < EE) g_slot[e] = atomicAdd(&g_deg[dst[e]], 1);   // >= 1 (deg starts at 1)
}

// ---------------- fused scan + dinv: 1 block, 1024 threads ----------------
__global__ __launch_bounds__(1024) void k_scan() {
    int t = threadIdx.x;
    int base = t * 16;
    int local[16];
    int s = 0;
    #pragma unroll
    for (int j = 0; j < 16; j++) {
        int dg = g_deg[base + j];
        g_dinv[base + j] = rsqrtf((float)dg);
        local[j] = s;
        s += dg - 1;
    }
    int lane = t & 31, wid = t >> 5;
    int v = s;
    #pragma unroll
    for (int d = 1; d < 32; d <<= 1) {
        int u = __shfl_up_sync(0xffffffffu, v, d);
        if (lane >= d) v += u;
    }
    __shared__ int wsum[32];
    if (lane == 31) wsum[wid] = v;
    __syncthreads();
    if (wid == 0) {
        int w = wsum[lane];
        #pragma unroll
        for (int d = 1; d < 32; d <<= 1) {
            int u = __shfl_up_sync(0xffffffffu, w, d);
            if (lane >= d) w += u;
        }
        wsum[lane] = w;
    }
    __syncthreads();
    int off = (v - s) + (wid ? wsum[wid - 1] : 0);
    #pragma unroll
    for (int j = 0; j < 16; j++) g_rowptr[base + j] = off + local[j];
    if (t == 1023) g_rowptr[NN] = off + s;
}

// ---------------- atomic-free scatter + bf16 feature prescale (fused) ----------------
// 2048 blocks x 256 threads. Each thread: 1 edge scatter + 1 float4 convert.
__global__ void k_scatter_pre(const int* __restrict__ src, const int* __restrict__ dst,
                              const float* __restrict__ X) {
    int i = blockIdx.x * blockDim.x + threadIdx.x;
    // edge scatter (no atomics: slot precomputed by k_deg)
    {
        int d = dst[i];
        g_col[g_rowptr[d] + g_slot[i] - 1] = src[i];
    }
    // feature prescale: NN*F_IN/4 = 524288 float4 == EE threads
    {
        int node = i >> 5;
        float sc = g_dinv[node];
        float4 v = ((const float4*)X)[i];
        __nv_bfloat162 lo = __floats2bfloat162_rn(v.x * sc, v.y * sc);
        __nv_bfloat162 hi = __floats2bfloat162_rn(v.z * sc, v.w * sc);
        uint2 u;
        u.x = *(unsigned int*)&lo; u.y = *(unsigned int*)&hi;
        ((uint2*)g_Yb)[i] = u;
    }
}

// ---------------- layer-1 aggregation (128-wide, bf16 input), unroll-4 ----------------
__global__ __launch_bounds__(256) void k_agg1() {
    int gi = threadIdx.x >> 5;
    int lane = threadIdx.x & 31;
    int d = blockIdx.x * 8 + gi;
    const uint2* Y = (const uint2*)g_Yb;

    uint2 u = Y[(size_t)d * 32 + lane];
    float2 l0 = __bfloat1622float2(*(__nv_bfloat162*)&u.x);
    float2 h0 = __bfloat1622float2(*(__nv_bfloat162*)&u.y);
    float4 acc = make_float4(l0.x, l0.y, h0.x, h0.y);

    int j = g_rowptr[d], s1 = g_rowptr[d + 1];
    for (; j + 4 <= s1; j += 4) {
        int i0 = g_col[j], i1 = g_col[j + 1], i2 = g_col[j + 2], i3 = g_col[j + 3];
        uint2 u0 = Y[(size_t)i0 * 32 + lane];
        uint2 u1 = Y[(size_t)i1 * 32 + lane];
        uint2 u2 = Y[(size_t)i2 * 32 + lane];
        uint2 u3 = Y[(size_t)i3 * 32 + lane];
        float2 a0 = __bfloat1622float2(*(__nv_bfloat162*)&u0.x);
        float2 b0 = __bfloat1622float2(*(__nv_bfloat162*)&u0.y);
        float2 a1 = __bfloat1622float2(*(__nv_bfloat162*)&u1.x);
        float2 b1 = __bfloat1622float2(*(__nv_bfloat162*)&u1.y);
        float2 a2 = __bfloat1622float2(*(__nv_bfloat162*)&u2.x);
        float2 b2 = __bfloat1622float2(*(__nv_bfloat162*)&u2.y);
        float2 a3 = __bfloat1622float2(*(__nv_bfloat162*)&u3.x);
        float2 b3 = __bfloat1622float2(*(__nv_bfloat162*)&u3.y);
        acc.x += a0.x + a1.x + a2.x + a3.x;
        acc.y += a0.y + a1.y + a2.y + a3.y;
        acc.z += b0.x + b1.x + b2.x + b3.x;
        acc.w += b0.y + b1.y + b2.y + b3.y;
    }
    for (; j < s1; j++) {
        int s = g_col[j];
        uint2 us = Y[(size_t)s * 32 + lane];
        float2 a = __bfloat1622float2(*(__nv_bfloat162*)&us.x);
        float2 b = __bfloat1622float2(*(__nv_bfloat162*)&us.y);
        acc.x += a.x; acc.y += a.y; acc.z += b.x; acc.w += b.y;
    }
    float scd = g_dinv[d];
    acc.x *= scd; acc.y *= scd; acc.z *= scd; acc.w *= scd;
    ((float4*)g_Z)[(size_t)d * 32 + lane] = acc;
}

// ---------------- tf32 helpers ----------------
__device__ __forceinline__ unsigned int f2tf32(float x) {
    unsigned int r;
    asm("cvt.rna.tf32.f32 %0, %1;" : "=r"(r) : "f"(x));
    return r;
}
__device__ __forceinline__ void mma_tf32(float* d, const unsigned int* a, const unsigned int* b) {
    asm volatile(
        "mma.sync.aligned.m16n8k8.row.col.f32.tf32.tf32.f32 "
        "{%0,%1,%2,%3},{%4,%5,%6,%7},{%8,%9},{%0,%1,%2,%3};\n"
        : "+f"(d[0]), "+f"(d[1]), "+f"(d[2]), "+f"(d[3])
        : "r"(a[0]), "r"(a[1]), "r"(a[2]), "r"(a[3]), "r"(b[0]), "r"(b[1]));
}

// ---------------- main tf32 GEMM (N=256), register double-buffered ----------------
#define GBK 32
__global__ __launch_bounds__(256) void k_gemm_tc(const float* __restrict__ A,
                                                 const float* __restrict__ B,
                                                 float* __restrict__ C,
                                                 __nv_bfloat16* __restrict__ Cb,
                                                 const float* __restrict__ bias,
                                                 int K, int mode) {
    __shared__ unsigned int As[GBK][136];
    __shared__ unsigned int Bs[GBK][136];
    int t = threadIdx.x;
    int row0 = blockIdx.y * 128, col0 = blockIdx.x * 128;
    int wid = t >> 5, lane = t & 31;
    int wr = wid >> 2, wc = wid & 3;
    int g = lane >> 2, tig = lane & 3;
    float acc[4][4][4] = {};

    int arr = t >> 3, akq = (t & 7) * 4;
    int bkr = t >> 5, bnq = (t & 31) * 4;

    float4 ra[4], rb[4];
    #pragma unroll
    for (int j = 0; j < 4; j++)
        ra[j] = *(const float4*)&A[(size_t)(row0 + arr + j * 32) * K + akq];
    #pragma unroll
    for (int j = 0; j < 4; j++)
        rb[j] = *(const float4*)&B[(size_t)(bkr + j * 8) * 256 + col0 + bnq];

    for (int k0 = 0; k0 < K; k0 += GBK) {
        #pragma unroll
        for (int j = 0; j < 4; j++) {
            int r = arr + j * 32;
            As[akq + 0][r] = f2tf32(ra[j].x); As[akq + 1][r] = f2tf32(ra[j].y);
            As[akq + 2][r] = f2tf32(ra[j].z); As[akq + 3][r] = f2tf32(ra[j].w);
        }
        #pragma unroll
        for (int j = 0; j < 4; j++) {
            int kr = bkr + j * 8;
            Bs[kr][bnq + 0] = f2tf32(rb[j].x); Bs[kr][bnq + 1] = f2tf32(rb[j].y);
            Bs[kr][bnq + 2] = f2tf32(rb[j].z); Bs[kr][bnq + 3] = f2tf32(rb[j].w);
        }
        __syncthreads();

        bool more = (k0 + GBK) < K;
        if (more) {
            #pragma unroll
            for (int j = 0; j < 4; j++)
                ra[j] = *(const float4*)&A[(size_t)(row0 + arr + j * 32) * K + k0 + GBK + akq];
            #pragma unroll
            for (int j = 0; j < 4; j++)
                rb[j] = *(const float4*)&B[(size_t)(k0 + GBK + bkr + j * 8) * 256 + col0 + bnq];
        }

        #pragma unroll
        for (int kk = 0; kk < GBK; kk += 8) {
            unsigned int af[4][4], bf[4][2];
            #pragma unroll
            for (int mi = 0; mi < 4; mi++) {
                int r = wr * 64 + mi * 16 + g;
                af[mi][0] = As[kk + tig][r];
                af[mi][1] = As[kk + tig][r + 8];
                af[mi][2] = As[kk + tig + 4][r];
                af[mi][3] = As[kk + tig + 4][r + 8];
            }
            #pragma unroll
            for (int ni = 0; ni < 4; ni++) {
                int c = wc * 32 + ni * 8 + g;
                bf[ni][0] = Bs[kk + tig][c];
                bf[ni][1] = Bs[kk + tig + 4][c];
            }
            #pragma unroll
            for (int mi = 0; mi < 4; mi++)
                #pragma unroll
                for (int ni = 0; ni < 4; ni++)
                    mma_tf32(acc[mi][ni], af[mi], bf[ni]);
        }
        __syncthreads();
    }

    #pragma unroll
    for (int mi = 0; mi < 4; mi++) {
        #pragma unroll
        for (int half = 0; half < 2; half++) {
            int r = row0 + wr * 64 + mi * 16 + g + half * 8;
            float sc = (mode == 1) ? g_dinv[r] : 1.0f;
            #pragma unroll
            for (int ni = 0; ni < 4; ni++) {
                int c = col0 + wc * 32 + ni * 8 + tig * 2;
                float v0 = acc[mi][ni][half * 2 + 0];
                float v1 = acc[mi][ni][half * 2 + 1];
                if (mode == 0) {
                    v0 = fmaxf(v0 + bias[c], 0.0f);
                    v1 = fmaxf(v1 + bias[c + 1], 0.0f);
                    *(float2*)&C[(size_t)r * 256 + c] = make_float2(v0, v1);
                } else {
                    __nv_bfloat162 bv = __floats2bfloat162_rn(v0 * sc, v1 * sc);
                    *(__nv_bfloat162*)&Cb[(size_t)r * 256 + c] = bv;
                }
            }
        }
    }
}

// ---------------- layer-2 aggregation (256-wide, bf16 input), unroll-4 ----------------
__global__ __launch_bounds__(256) void k_agg(float* __restrict__ out,
                                             const float* __restrict__ bias) {
    int gi = threadIdx.x >> 6;
    int lane = threadIdx.x & 63;
    int d = blockIdx.x * 4 + gi;
    const uint2* Xb = (const uint2*)g_Xb;

    uint2 u = Xb[(size_t)d * 64 + lane];
    float2 l0 = __bfloat1622float2(*(__nv_bfloat162*)&u.x);
    float2 h0 = __bfloat1622float2(*(__nv_bfloat162*)&u.y);
    float4 acc = make_float4(l0.x, l0.y, h0.x, h0.y);

    int j = g_rowptr[d], s1 = g_rowptr[d + 1];
    for (; j + 4 <= s1; j += 4) {
        int i0 = g_col[j], i1 = g_col[j + 1], i2 = g_col[j + 2], i3 = g_col[j + 3];
        uint2 u0 = Xb[(size_t)i0 * 64 + lane];
        uint2 u1 = Xb[(size_t)i1 * 64 + lane];
        uint2 u2 = Xb[(size_t)i2 * 64 + lane];
        uint2 u3 = Xb[(size_t)i3 * 64 + lane];
        float2 a0 = __bfloat1622float2(*(__nv_bfloat162*)&u0.x);
        float2 b0 = __bfloat1622float2(*(__nv_bfloat162*)&u0.y);
        float2 a1 = __bfloat1622float2(*(__nv_bfloat162*)&u1.x);
        float2 b1 = __bfloat1622float2(*(__nv_bfloat162*)&u1.y);
        float2 a2 = __bfloat1622float2(*(__nv_bfloat162*)&u2.x);
        float2 b2 = __bfloat1622float2(*(__nv_bfloat162*)&u2.y);
        float2 a3 = __bfloat1622float2(*(__nv_bfloat162*)&u3.x);
        float2 b3 = __bfloat1622float2(*(__nv_bfloat162*)&u3.y);
        acc.x += a0.x + a1.x + a2.x + a3.x;
        acc.y += a0.y + a1.y + a2.y + a3.y;
        acc.z += b0.x + b1.x + b2.x + b3.x;
        acc.w += b0.y + b1.y + b2.y + b3.y;
    }
    for (; j < s1; j++) {
        int s = g_col[j];
        uint2 us = Xb[(size_t)s * 64 + lane];
        float2 a = __bfloat1622float2(*(__nv_bfloat162*)&us.x);
        float2 b = __bfloat1622float2(*(__nv_bfloat162*)&us.y);
        acc.x += a.x; acc.y += a.y; acc.z += b.x; acc.w += b.y;
    }
    float sc = g_dinv[d];
    float4 bv = ((const float4*)bias)[lane];
    float4 o;
    o.x = acc.x * sc + bv.x; o.y = acc.y * sc + bv.y;
    o.z = acc.z * sc + bv.z; o.w = acc.w * sc + bv.w;
    ((float4*)out)[(size_t)d * 64 + lane] = o;
}

// ---------------- fc1 via tf32 MMA: a1 = tanh(h2 @ fc1wT + fc1b) ----------------
__global__ __launch_bounds__(256) void k_fc1_tc(const float* __restrict__ A,
                                                const float* __restrict__ fc1b) {
    __shared__ unsigned int As[GBK][136];
    __shared__ unsigned int Bs[GBK][72];
    int t = threadIdx.x;
    int row0 = blockIdx.x * 128;
    int wid = t >> 5, lane = t & 31;
    int wr = wid >> 1, wc = wid & 1;
    int g = lane >> 2, tig = lane & 3;
    float acc[2][4][4] = {};

    int arr = t >> 3, akq = (t & 7) * 4;
    int bkr = t >> 3, bcq = (t & 7) * 8;

    float4 ra[4];
    float4 rb0, rb1;
    #pragma unroll
    for (int j = 0; j < 4; j++)
        ra[j] = *(const float4*)&A[(size_t)(row0 + arr + j * 32) * 256 + akq];
    rb0 = *(const float4*)&g_fc1wT[(size_t)bkr * 64 + bcq];
    rb1 = *(const float4*)&g_fc1wT[(size_t)bkr * 64 + bcq + 4];

    for (int k0 = 0; k0 < 256; k0 += GBK) {
        #pragma unroll
        for (int j = 0; j < 4; j++) {
            int r = arr + j * 32;
            As[akq + 0][r] = f2tf32(ra[j].x); As[akq + 1][r] = f2tf32(ra[j].y);
            As[akq + 2][r] = f2tf32(ra[j].z); As[akq + 3][r] = f2tf32(ra[j].w);
        }
        Bs[bkr][bcq + 0] = f2tf32(rb0.x); Bs[bkr][bcq + 1] = f2tf32(rb0.y);
        Bs[bkr][bcq + 2] = f2tf32(rb0.z); Bs[bkr][bcq + 3] = f2tf32(rb0.w);
        Bs[bkr][bcq + 4] = f2tf32(rb1.x); Bs[bkr][bcq + 5] = f2tf32(rb1.y);
        Bs[bkr][bcq + 6] = f2tf32(rb1.z); Bs[bkr][bcq + 7] = f2tf32(rb1.w);
        __syncthreads();

        bool more = (k0 + GBK) < 256;
        if (more) {
            #pragma unroll
            for (int j = 0; j < 4; j++)
                ra[j] = *(const float4*)&A[(size_t)(row0 + arr + j * 32) * 256 + k0 + GBK + akq];
            rb0 = *(const float4*)&g_fc1wT[(size_t)(k0 + GBK + bkr) * 64 + bcq];
            rb1 = *(const float4*)&g_fc1wT[(size_t)(k0 + GBK + bkr) * 64 + bcq + 4];
        }

        #pragma unroll
        for (int kk = 0; kk < GBK; kk += 8) {
            unsigned int af[2][4], bf[4][2];
            #pragma unroll
            for (int mi = 0; mi < 2; mi++) {
                int r = wr * 32 + mi * 16 + g;
                af[mi][0] = As[kk + tig][r];
                af[mi][1] = As[kk + tig][r + 8];
                af[mi][2] = As[kk + tig + 4][r];
                af[mi][3] = As[kk + tig + 4][r + 8];
            }
            #pragma unroll
            for (int ni = 0; ni < 4; ni++) {
                int c = wc * 32 + ni * 8 + g;
                bf[ni][0] = Bs[kk + tig][c];
                bf[ni][1] = Bs[kk + tig + 4][c];
            }
            #pragma unroll
            for (int mi = 0; mi < 2; mi++)
                #pragma unroll
                for (int ni = 0; ni < 4; ni++)
                    mma_tf32(acc[mi][ni], af[mi], bf[ni]);
        }
        __syncthreads();
    }

    #pragma unroll
    for (int mi = 0; mi < 2; mi++) {
        #pragma unroll
        for (int half = 0; half < 2; half++) {
            int r = row0 + wr * 32 + mi * 16 + g + half * 8;
            #pragma unroll
            for (int ni = 0; ni < 4; ni++) {
                int c = wc * 32 + ni * 8 + tig * 2;
                float v0 = tanhf(acc[mi][ni][half * 2 + 0] + fc1b[c]);
                float v1 = tanhf(acc[mi][ni][half * 2 + 1] + fc1b[c + 1]);
                *(float2*)&g_a1[(size_t)r * 64 + c] = make_float2(v0, v1);
            }
        }
    }
}

// ---------------- fc2 + softmax + assign + gf partials ----------------
__global__ __launch_bounds__(256) void k_fc2(const float* __restrict__ h2,
                                             const float* __restrict__ fc2w,
                                             const float* __restrict__ fc2b) {
    __shared__ float a1s[64][65];
    __shared__ float ps[64][2];
    __shared__ float w2s[128];
    __shared__ float gfl[2][256];
    int t = threadIdx.x;
    int n0 = blockIdx.x * 64;
    gfl[0][t] = 0.0f; gfl[1][t] = 0.0f;
    if (t < 128) w2s[t] = fc2w[t];

    for (int i = t; i < 64 * 64; i += 256)
        a1s[i >> 6][i & 63] = g_a1[(size_t)n0 * 64 + i];
    __syncthreads();

    if (t < 128) {
        int n = t >> 1, c = t & 1;
        float l = fc2b[c];
        #pragma unroll
        for (int k = 0; k < 64; k++) l += w2s[c * 64 + k] * a1s[n][k];
        ps[n][c] = l;
    }
    __syncthreads();
    if (t < 64) {
        float l0 = ps[t][0], l1 = ps[t][1];
        float m = fmaxf(l0, l1);
        float e0 = expf(l0 - m), e1 = expf(l1 - m);
        float inv = 1.0f / (e0 + e1);
        float p0 = e0 * inv, p1 = e1 * inv;
        ps[t][0] = p0; ps[t][1] = p1;
        g_assign[2 * (n0 + t)] = p0;
        g_assign[2 * (n0 + t) + 1] = p1;
    }
    __syncthreads();

    for (int q = 0; q < 64; q += 4) {
        float h0 = h2[(size_t)(n0 + q + 0) * 256 + t];
        float h1v = h2[(size_t)(n0 + q + 1) * 256 + t];
        float h2v = h2[(size_t)(n0 + q + 2) * 256 + t];
        float h3 = h2[(size_t)(n0 + q + 3) * 256 + t];
        gfl[0][t] += ps[q][0] * h0 + ps[q + 1][0] * h1v + ps[q + 2][0] * h2v + ps[q + 3][0] * h3;
        gfl[1][t] += ps[q][1] * h0 + ps[q + 1][1] * h1v + ps[q + 2][1] * h2v + ps[q + 3][1] * h3;
    }
    atomicAdd(&g_gf[t], gfl[0][t]);
    atomicAdd(&g_gf[256 + t], gfl[1][t]);
}

// ---------------- new_adj ----------------
__global__ void k_newadj(const int* __restrict__ src, const int* __restrict__ dst) {
    float a0 = 0, a1 = 0, a2 = 0, a3 = 0;
    const float2* as2 = (const float2*)g_assign;
    for (int e = blockIdx.x * blockDim.x + threadIdx.x; e < EE; e += gridDim.x * blockDim.x) {
        int s = src[e], d = dst[e];
        float2 sv = as2[s];
        float2 dv = as2[d];
        a0 += sv.x * dv.x; a1 += sv.x * dv.y; a2 += sv.y * dv.x; a3 += sv.y * dv.y;
    }
    #pragma unroll
    for (int w = 16; w; w >>= 1) {
        a0 += __shfl_down_sync(0xffffffff, a0, w);
        a1 += __shfl_down_sync(0xffffffff, a1, w);
        a2 += __shfl_down_sync(0xffffffff, a2, w);
        a3 += __shfl_down_sync(0xffffffff, a3, w);
    }
    __shared__ float sa[8][4];
    int lane = threadIdx.x & 31, wid = threadIdx.x >> 5;
    if (lane == 0) { sa[wid][0] = a0; sa[wid][1] = a1; sa[wid][2] = a2; sa[wid][3] = a3; }
    __syncthreads();
    if (threadIdx.x < 4) {
        float sum = 0;
        #pragma unroll
        for (int w = 0; w < 8; w++) sum += sa[w][threadIdx.x];
        atomicAdd(&g_newadj[threadIdx.x], sum);
    }
}

// ---------------- finalize ----------------
__global__ void k_final(float* __restrict__ out) {
    int t = threadIdx.x;
    float g0 = g_gf[t], g1 = g_gf[256 + t];
    out[t]       = 0.5f * (g0 + g1);
    out[256 + t] = fminf(fmaxf(g0, -100.0f), 100.0f);
    out[512 + t] = fminf(fmaxf(g1, -100.0f), 100.0f);
    if (t == 0) {
        float a00 = g_newadj[0], a01 = g_newadj[1], a10 = g_newadj[2], a11 = g_newadj[3];
        float den0 = fmaxf(fabsf(a00) + fabsf(a01), 1e-12f);
        float den1 = fmaxf(fabsf(a10) + fabsf(a11), 1e-12f);
        float nd0 = a00 / den0, nd1 = a11 / den1;
        out[768] = 0.5f * ((nd0 - 1.0f) * (nd0 - 1.0f) + (nd1 - 1.0f) * (nd1 - 1.0f));
    }
}

extern "C" void kernel_launch(void* const* d_in, const int* in_sizes, int n_in,
                              void* d_out, int out_size) {
    const float* features = (const float*)d_in[0];
    const int*   edges    = (const int*)d_in[1];
    const float* W1    = (const float*)d_in[2];
    const float* b1    = (const float*)d_in[3];
    const float* W2    = (const float*)d_in[4];
    const float* b2    = (const float*)d_in[5];
    const float* fc1w  = (const float*)d_in[6];
    const float* fc1b  = (const float*)d_in[7];
    const float* fc2w  = (const float*)d_in[8];
    const float* fc2b  = (const float*)d_in[9];
    float* out = (float*)d_out;
    const int* src = edges;
    const int* dst = edges + EE;

    float *ph1, *ph2, *pZ;
    __nv_bfloat16* pXb;
    cudaGetSymbolAddress((void**)&pXb, g_Xb);
    cudaGetSymbolAddress((void**)&ph1, g_h1);
    cudaGetSymbolAddress((void**)&ph2, g_h2);
    cudaGetSymbolAddress((void**)&pZ,  g_Z);

    k_init<<<(D1 * H2) / 256, 256>>>(fc1w);   // covers NN(16384)=D1*H2 range
    k_deg<<<EE / 256, 256>>>(dst);
    k_scan<<<1, 1024>>>();
    k_scatter_pre<<<EE / 256, 256>>>(src, dst, features);

    // layer 1: aggregate bf16 features, tensor-core transform
    k_agg1<<<NN / 8, 256>>>();
    dim3 gg(2, NN / 128);
    k_gemm_tc<<<gg, 256>>>(pZ, W1, ph1, (__nv_bfloat16*)0, b1, F_IN, 0);

    // layer 2: transform (bf16 out), aggregate
    k_gemm_tc<<<gg, 256>>>(ph1, W2, (float*)0, pXb, (const float*)0, H1, 1);
    k_agg<<<NN / 4, 256>>>(ph2, b2);

    // MLP head: tensor-core fc1, then fc2/softmax/pool
    k_fc1_tc<<<NN / 128, 256>>>(ph2, fc1b);
    k_fc2<<<NN / 64, 256>>>(ph2, fc2w, fc2b);

    k_newadj<<<256, 256>>>(src, dst);
    k_final<<<1, 256>>>(out);
}

// round 10
// speedup vs baseline: 2.0806x; 1.0137x over previous
#include <cuda_runtime.h>
#include <cuda_bf16.h>
#include <cstdint>
#include <math.h>

#define NN     16384
#define EE     524288
#define F_IN   128
#define H1     256
#define H2     256
#define D1     64

// ---------------- scratch (device globals; no allocations) ----------------
__device__ __nv_bfloat16 g_Yb[NN * F_IN];  // raw features, bf16
__device__ __nv_bfloat16 g_Zb[NN * F_IN];  // aggregated features, bf16
__device__ __nv_bfloat16 g_h1b[NN * H1];   // relu(Z@W1+b1), bf16
__device__ __nv_bfloat16 g_Xb[NN * H1];    // dinv*(h1@W2), bf16
__device__ __nv_bfloat16 g_h2b[NN * H2];   // layer-2 output, bf16
__device__ float g_dinv[NN];
__device__ int   g_deg[NN];
__device__ int   g_rowptr[NN + 1];
__device__ int   g_slot[EE];
__device__ int   g_col[EE];
__device__ float g_fc1wT[H2 * D1];
__device__ float g_assign[NN * 2];
__device__ float g_gf[2 * H2];
__device__ float g_newadj[4];

// ---------------- init + fc1 weight transpose ----------------
__global__ void k_init(const float* __restrict__ w) {
    int i = blockIdx.x * blockDim.x + threadIdx.x;
    if (i < NN) g_deg[i] = 1;
    if (i < 2 * H2) g_gf[i] = 0.0f;
    if (i < 4) g_newadj[i] = 0.0f;
    if (i < D1 * H2) {
        int o = i >> 8, k = i & 255;
        g_fc1wT[k * D1 + o] = w[i];
    }
}

// ---------------- degree histogram (slot) + raw bf16 feature convert ----------------
__global__ void k_deg(const int* __restrict__ dst, const float* __restrict__ X) {
    int i = blockIdx.x * blockDim.x + threadIdx.x;
    g_slot[i] = atomicAdd(&g_deg[dst[i]], 1);     // slot >= 1 (deg starts at 1)
    float4 v = ((const float4*)X)[i];             // EE == NN*F_IN/4
    __nv_bfloat162 lo = __floats2bfloat162_rn(v.x, v.y);
    __nv_bfloat162 hi = __floats2bfloat162_rn(v.z, v.w);
    uint2 u; u.x = *(unsigned int*)&lo; u.y = *(unsigned int*)&hi;
    ((uint2*)g_Yb)[i] = u;
}

// ---------------- fused scan + dinv: 1 block, 1024 threads ----------------
__global__ __launch_bounds__(1024) void k_scan() {
    int t = threadIdx.x;
    int base = t * 16;
    int local[16];
    int s = 0;
    #pragma unroll
    for (int j = 0; j < 16; j++) {
        int dg = g_deg[base + j];
        g_dinv[base + j] = rsqrtf((float)dg);
        local[j] = s;
        s += dg - 1;
    }
    int lane = t & 31, wid = t >> 5;
    int v = s;
    #pragma unroll
    for (int d = 1; d < 32; d <<= 1) {
        int u = __shfl_up_sync(0xffffffffu, v, d);
        if (lane >= d) v += u;
    }
    __shared__ int wsum[32];
    if (lane == 31) wsum[wid] = v;
    __syncthreads();
    if (wid == 0) {
        int w = wsum[lane];
        #pragma unroll
        for (int d = 1; d < 32; d <<= 1) {
            int u = __shfl_up_sync(0xffffffffu, w, d);
            if (lane >= d) w += u;
        }
        wsum[lane] = w;
    }
    __syncthreads();
    int off = (v - s) + (wid ? wsum[wid - 1] : 0);
    #pragma unroll
    for (int j = 0; j < 16; j++) g_rowptr[base + j] = off + local[j];
    if (t == 1023) g_rowptr[NN] = off + s;
}

// ---------------- atomic-free scatter ----------------
__global__ void k_scatter(const int* __restrict__ src, const int* __restrict__ dst) {
    int e = blockIdx.x * blockDim.x + threadIdx.x;
    int d = dst[e];
    g_col[g_rowptr[d] + g_slot[e] - 1] = src[e];
}

// ---------------- layer-1 aggregation: Zb[d] = bf16( dinv[d]*(dinv[d]*Y[d] + sum dinv[s]*Y[s]) ) ----------------
__global__ __launch_bounds__(256) void k_agg1() {
    int gi = threadIdx.x >> 5;
    int lane = threadIdx.x & 31;
    int d = blockIdx.x * 8 + gi;
    const uint2* Y = (const uint2*)g_Yb;
    float scd = g_dinv[d];

    uint2 u = Y[(size_t)d * 32 + lane];
    float2 l0 = __bfloat1622float2(*(__nv_bfloat162*)&u.x);
    float2 h0 = __bfloat1622float2(*(__nv_bfloat162*)&u.y);
    float4 acc = make_float4(scd * l0.x, scd * l0.y, scd * h0.x, scd * h0.y);

    int j = g_rowptr[d], s1 = g_rowptr[d + 1];
    for (; j + 4 <= s1; j += 4) {
        int i0 = g_col[j], i1 = g_col[j + 1], i2 = g_col[j + 2], i3 = g_col[j + 3];
        float w0 = g_dinv[i0], w1 = g_dinv[i1], w2 = g_dinv[i2], w3 = g_dinv[i3];
        uint2 u0 = Y[(size_t)i0 * 32 + lane];
        uint2 u1 = Y[(size_t)i1 * 32 + lane];
        uint2 u2 = Y[(size_t)i2 * 32 + lane];
        uint2 u3 = Y[(size_t)i3 * 32 + lane];
        float2 a0 = __bfloat1622float2(*(__nv_bfloat162*)&u0.x);
        float2 b0 = __bfloat1622float2(*(__nv_bfloat162*)&u0.y);
        float2 a1 = __bfloat1622float2(*(__nv_bfloat162*)&u1.x);
        float2 b1 = __bfloat1622float2(*(__nv_bfloat162*)&u1.y);
        float2 a2 = __bfloat1622float2(*(__nv_bfloat162*)&u2.x);
        float2 b2 = __bfloat1622float2(*(__nv_bfloat162*)&u2.y);
        float2 a3 = __bfloat1622float2(*(__nv_bfloat162*)&u3.x);
        float2 b3 = __bfloat1622float2(*(__nv_bfloat162*)&u3.y);
        acc.x += w0 * a0.x + w1 * a1.x + w2 * a2.x + w3 * a3.x;
        acc.y += w0 * a0.y + w1 * a1.y + w2 * a2.y + w3 * a3.y;
        acc.z += w0 * b0.x + w1 * b1.x + w2 * b2.x + w3 * b3.x;
        acc.w += w0 * b0.y + w1 * b1.y + w2 * b2.y + w3 * b3.y;
    }
    for (; j < s1; j++) {
        int s = g_col[j];
        float w = g_dinv[s];
        uint2 us = Y[(size_t)s * 32 + lane];
        float2 a = __bfloat1622float2(*(__nv_bfloat162*)&us.x);
        float2 b = __bfloat1622float2(*(__nv_bfloat162*)&us.y);
        acc.x += w * a.x; acc.y += w * a.y; acc.z += w * b.x; acc.w += w * b.y;
    }
    __nv_bfloat162 lo = __floats2bfloat162_rn(acc.x * scd, acc.y * scd);
    __nv_bfloat162 hi = __floats2bfloat162_rn(acc.z * scd, acc.w * scd);
    uint2 o; o.x = *(unsigned int*)&lo; o.y = *(unsigned int*)&hi;
    ((uint2*)g_Zb)[(size_t)d * 32 + lane] = o;
}

// ---------------- tf32 helpers ----------------
__device__ __forceinline__ unsigned int f2tf32(float x) {
    unsigned int r;
    asm("cvt.rna.tf32.f32 %0, %1;" : "=r"(r) : "f"(x));
    return r;
}
__device__ __forceinline__ void mma_tf32(float* d, const unsigned int* a, const unsigned int* b) {
    asm volatile(
        "mma.sync.aligned.m16n8k8.row.col.f32.tf32.tf32.f32 "
        "{%0,%1,%2,%3},{%4,%5,%6,%7},{%8,%9},{%0,%1,%2,%3};\n"
        : "+f"(d[0]), "+f"(d[1]), "+f"(d[2]), "+f"(d[3])
        : "r"(a[0]), "r"(a[1]), "r"(a[2]), "r"(a[3]), "r"(b[0]), "r"(b[1]));
}

// ---------------- tf32 GEMM, bf16 A, fp32 B; bf16 out ----------------
// mode 0: Cb = bf16(relu(AB + bias))   mode 1: Cb = bf16(dinv[row] * AB)
#define GBK 32
__global__ __launch_bounds__(256) void k_gemm_tc(const __nv_bfloat16* __restrict__ A,
                                                 const float* __restrict__ B,
                                                 __nv_bfloat16* __restrict__ Cb,
                                                 const float* __restrict__ bias,
                                                 int K, int mode) {
    __shared__ unsigned int As[GBK][136];
    __shared__ unsigned int Bs[GBK][136];
    int t = threadIdx.x;
    int row0 = blockIdx.y * 128, col0 = blockIdx.x * 128;
    int wid = t >> 5, lane = t & 31;
    int wr = wid >> 2, wc = wid & 3;
    int g = lane >> 2, tig = lane & 3;
    float acc[4][4][4] = {};

    int arr = t >> 3, akq = (t & 7) * 4;
    int bkr = t >> 5, bnq = (t & 31) * 4;

    uint2 ra[4];
    float4 rb[4];
    #pragma unroll
    for (int j = 0; j < 4; j++)
        ra[j] = *(const uint2*)&A[(size_t)(row0 + arr + j * 32) * K + akq];
    #pragma unroll
    for (int j = 0; j < 4; j++)
        rb[j] = *(const float4*)&B[(size_t)(bkr + j * 8) * 256 + col0 + bnq];

    for (int k0 = 0; k0 < K; k0 += GBK) {
        #pragma unroll
        for (int j = 0; j < 4; j++) {
            int r = arr + j * 32;
            float2 lo = __bfloat1622float2(*(__nv_bfloat162*)&ra[j].x);
            float2 hi = __bfloat1622float2(*(__nv_bfloat162*)&ra[j].y);
            As[akq + 0][r] = f2tf32(lo.x); As[akq + 1][r] = f2tf32(lo.y);
            As[akq + 2][r] = f2tf32(hi.x); As[akq + 3][r] = f2tf32(hi.y);
        }
        #pragma unroll
        for (int j = 0; j < 4; j++) {
            int kr = bkr + j * 8;
            Bs[kr][bnq + 0] = f2tf32(rb[j].x); Bs[kr][bnq + 1] = f2tf32(rb[j].y);
            Bs[kr][bnq + 2] = f2tf32(rb[j].z); Bs[kr][bnq + 3] = f2tf32(rb[j].w);
        }
        __syncthreads();

        bool more = (k0 + GBK) < K;
        if (more) {
            #pragma unroll
            for (int j = 0; j < 4; j++)
                ra[j] = *(const uint2*)&A[(size_t)(row0 + arr + j * 32) * K + k0 + GBK + akq];
            #pragma unroll
            for (int j = 0; j < 4; j++)
                rb[j] = *(const float4*)&B[(size_t)(k0 + GBK + bkr + j * 8) * 256 + col0 + bnq];
        }

        #pragma unroll
        for (int kk = 0; kk < GBK; kk += 8) {
            unsigned int af[4][4], bf[4][2];
            #pragma unroll
            for (int mi = 0; mi < 4; mi++) {
                int r = wr * 64 + mi * 16 + g;
                af[mi][0] = As[kk + tig][r];
                af[mi][1] = As[kk + tig][r + 8];
                af[mi][2] = As[kk + tig + 4][r];
                af[mi][3] = As[kk + tig + 4][r + 8];
            }
            #pragma unroll
            for (int ni = 0; ni < 4; ni++) {
                int c = wc * 32 + ni * 8 + g;
                bf[ni][0] = Bs[kk + tig][c];
                bf[ni][1] = Bs[kk + tig + 4][c];
            }
            #pragma unroll
            for (int mi = 0; mi < 4; mi++)
                #pragma unroll
                for (int ni = 0; ni < 4; ni++)
                    mma_tf32(acc[mi][ni], af[mi], bf[ni]);
        }
        __syncthreads();
    }

    #pragma unroll
    for (int mi = 0; mi < 4; mi++) {
        #pragma unroll
        for (int half = 0; half < 2; half++) {
            int r = row0 + wr * 64 + mi * 16 + g + half * 8;
            float sc = (mode == 1) ? g_dinv[r] : 1.0f;
            #pragma unroll
            for (int ni = 0; ni < 4; ni++) {
                int c = col0 + wc * 32 + ni * 8 + tig * 2;
                float v0 = acc[mi][ni][half * 2 + 0];
                float v1 = acc[mi][ni][half * 2 + 1];
                if (mode == 0) {
                    v0 = fmaxf(v0 + bias[c], 0.0f);
                    v1 = fmaxf(v1 + bias[c + 1], 0.0f);
                } else {
                    v0 *= sc; v1 *= sc;
                }
                __nv_bfloat162 bv = __floats2bfloat162_rn(v0, v1);
                *(__nv_bfloat162*)&Cb[(size_t)r * 256 + c] = bv;
            }
        }
    }
}

// ---------------- layer-2 aggregation (bf16 in/out) ----------------
__global__ __launch_bounds__(256) void k_agg2(const float* __restrict__ bias) {
    int gi = threadIdx.x >> 6;
    int lane = threadIdx.x & 63;
    int d = blockIdx.x * 4 + gi;
    const uint2* Xb = (const uint2*)g_Xb;

    uint2 u = Xb[(size_t)d * 64 + lane];
    float2 l0 = __bfloat1622float2(*(__nv_bfloat162*)&u.x);
    float2 h0 = __bfloat1622float2(*(__nv_bfloat162*)&u.y);
    float4 acc = make_float4(l0.x, l0.y, h0.x, h0.y);

    int j = g_rowptr[d], s1 = g_rowptr[d + 1];
    for (; j + 4 <= s1; j += 4) {
        int i0 = g_col[j], i1 = g_col[j + 1], i2 = g_col[j + 2], i3 = g_col[j + 3];
        uint2 u0 = Xb[(size_t)i0 * 64 + lane];
        uint2 u1 = Xb[(size_t)i1 * 64 + lane];
        uint2 u2 = Xb[(size_t)i2 * 64 + lane];
        uint2 u3 = Xb[(size_t)i3 * 64 + lane];
        float2 a0 = __bfloat1622float2(*(__nv_bfloat162*)&u0.x);
        float2 b0 = __bfloat1622float2(*(__nv_bfloat162*)&u0.y);
        float2 a1 = __bfloat1622float2(*(__nv_bfloat162*)&u1.x);
        float2 b1 = __bfloat1622float2(*(__nv_bfloat162*)&u1.y);
        float2 a2 = __bfloat1622float2(*(__nv_bfloat162*)&u2.x);
        float2 b2 = __bfloat1622float2(*(__nv_bfloat162*)&u2.y);
        float2 a3 = __bfloat1622float2(*(__nv_bfloat162*)&u3.x);
        float2 b3 = __bfloat1622float2(*(__nv_bfloat162*)&u3.y);
        acc.x += a0.x + a1.x + a2.x + a3.x;
        acc.y += a0.y + a1.y + a2.y + a3.y;
        acc.z += b0.x + b1.x + b2.x + b3.x;
        acc.w += b0.y + b1.y + b2.y + b3.y;
    }
    for (; j < s1; j++) {
        int s = g_col[j];
        uint2 us = Xb[(size_t)s * 64 + lane];
        float2 a = __bfloat1622float2(*(__nv_bfloat162*)&us.x);
        float2 b = __bfloat1622float2(*(__nv_bfloat162*)&us.y);
        acc.x += a.x; acc.y += a.y; acc.z += b.x; acc.w += b.y;
    }
    float sc = g_dinv[d];
    float4 bv = ((const float4*)bias)[lane];
    __nv_bfloat162 lo = __floats2bfloat162_rn(acc.x * sc + bv.x, acc.y * sc + bv.y);
    __nv_bfloat162 hi = __floats2bfloat162_rn(acc.z * sc + bv.z, acc.w * sc + bv.w);
    uint2 o; o.x = *(unsigned int*)&lo; o.y = *(unsigned int*)&hi;
    ((uint2*)g_h2b)[(size_t)d * 64 + lane] = o;
}

// ---------------- fused fc1 (tf32 MMA) + fc2 + softmax + assign + gf partials ----------------
// 128 nodes per block, 8 warps. Smem unioned: MMA buffers, then epilogue buffers.
__global__ __launch_bounds__(256) void k_fc1fc2(const float* __restrict__ fc1b,
                                                const float* __restrict__ fc2w,
                                                const float* __restrict__ fc2b) {
    __shared__ char buf[36864];
    unsigned int (*As)[136] = (unsigned int(*)[136])buf;            // 17408 B
    unsigned int (*Bs)[72]  = (unsigned int(*)[72])(buf + 17408);   // 9216 B
    float (*a1s)[65]  = (float(*)[65])buf;                          // 33280 B (aliases As/Bs)
    float (*ps)[2]    = (float(*)[2])(buf + 33280);                 // 1024 B
    float *w2s        = (float*)(buf + 34304);                      // 512 B
    float (*gfl)[256] = (float(*)[256])(buf + 34816);               // 2048 B

    int t = threadIdx.x;
    int row0 = blockIdx.x * 128;
    int wid = t >> 5, lane = t & 31;
    int wr = wid >> 1, wc = wid & 1;
    int g = lane >> 2, tig = lane & 3;
    float acc[2][4][4] = {};

    int arr = t >> 3, akq = (t & 7) * 4;
    int bkr = t >> 3, bcq = (t & 7) * 8;

    const __nv_bfloat16* A = g_h2b;
    uint2 ra[4];
    float4 rb0, rb1;
    #pragma unroll
    for (int j = 0; j < 4; j++)
        ra[j] = *(const uint2*)&A[(size_t)(row0 + arr + j * 32) * 256 + akq];
    rb0 = *(const float4*)&g_fc1wT[(size_t)bkr * 64 + bcq];
    rb1 = *(const float4*)&g_fc1wT[(size_t)bkr * 64 + bcq + 4];

    for (int k0 = 0; k0 < 256; k0 += GBK) {
        #pragma unroll
        for (int j = 0; j < 4; j++) {
            int r = arr + j * 32;
            float2 lo = __bfloat1622float2(*(__nv_bfloat162*)&ra[j].x);
            float2 hi = __bfloat1622float2(*(__nv_bfloat162*)&ra[j].y);
            As[akq + 0][r] = f2tf32(lo.x); As[akq + 1][r] = f2tf32(lo.y);
            As[akq + 2][r] = f2tf32(hi.x); As[akq + 3][r] = f2tf32(hi.y);
        }
        Bs[bkr][bcq + 0] = f2tf32(rb0.x); Bs[bkr][bcq + 1] = f2tf32(rb0.y);
        Bs[bkr][bcq + 2] = f2tf32(rb0.z); Bs[bkr][bcq + 3] = f2tf32(rb0.w);
        Bs[bkr][bcq + 4] = f2tf32(rb1.x); Bs[bkr][bcq + 5] = f2tf32(rb1.y);
        Bs[bkr][bcq + 6] = f2tf32(rb1.z); Bs[bkr][bcq + 7] = f2tf32(rb1.w);
        __syncthreads();

        bool more = (k0 + GBK) < 256;
        if (more) {
            #pragma unroll
            for (int j = 0; j < 4; j++)
                ra[j] = *(const uint2*)&A[(size_t)(row0 + arr + j * 32) * 256 + k0 + GBK + akq];
            rb0 = *(const float4*)&g_fc1wT[(size_t)(k0 + GBK + bkr) * 64 + bcq];
            rb1 = *(const float4*)&g_fc1wT[(size_t)(k0 + GBK + bkr) * 64 + bcq + 4];
        }

        #pragma unroll
        for (int kk = 0; kk < GBK; kk += 8) {
            unsigned int af[2][4], bf[4][2];
            #pragma unroll
            for (int mi = 0; mi < 2; mi++) {
                int r = wr * 32 + mi * 16 + g;
                af[mi][0] = As[kk + tig][r];
                af[mi][1] = As[kk + tig][r + 8];
                af[mi][2] = As[kk + tig + 4][r];
                af[mi][3] = As[kk + tig + 4][r + 8];
            }
            #pragma unroll
            for (int ni = 0; ni < 4; ni++) {
                int c = wc * 32 + ni * 8 + g;
                bf[ni][0] = Bs[kk + tig][c];
                bf[ni][1] = Bs[kk + tig + 4][c];
            }
            #pragma unroll
            for (int mi = 0; mi < 2; mi++)
                #pragma unroll
                for (int ni = 0; ni < 4; ni++)
                    mma_tf32(acc[mi][ni], af[mi], bf[ni]);
        }
        __syncthreads();
    }
    // ---- epilogue: a1 into smem (aliases MMA buffers; all reads complete) ----
    #pragma unroll
    for (int mi = 0; mi < 2; mi++) {
        #pragma unroll
        for (int half = 0; half < 2; half++) {
            int rr = wr * 32 + mi * 16 + g + half * 8;   // 0..127
            #pragma unroll
            for (int ni = 0; ni < 4; ni++) {
                int c = wc * 32 + ni * 8 + tig * 2;
                a1s[rr][c]     = tanhf(acc[mi][ni][half * 2 + 0] + fc1b[c]);
                a1s[rr][c + 1] = tanhf(acc[mi][ni][half * 2 + 1] + fc1b[c + 1]);
            }
        }
    }
    if (t < 128) w2s[t] = fc2w[t];
    gfl[0][t] = 0.0f; gfl[1][t] = 0.0f;
    __syncthreads();

    // fc2 logits: 256 threads = 128 nodes x 2 classes
    {
        int n = t >> 1, c = t & 1;
        float l = fc2b[c];
        #pragma unroll
        for (int k = 0; k < 64; k++) l += w2s[c * 64 + k] * a1s[n][k];
        ps[n][c] = l;
    }
    __syncthreads();
    if (t < 128) {
        float l0 = ps[t][0], l1 = ps[t][1];
        float m = fmaxf(l0, l1);
        float e0 = expf(l0 - m), e1 = expf(l1 - m);
        float inv = 1.0f / (e0 + e1);
        float p0 = e0 * inv, p1 = e1 * inv;
        ps[t][0] = p0; ps[t][1] = p1;
        g_assign[2 * (row0 + t)] = p0;
        g_assign[2 * (row0 + t) + 1] = p1;
    }
    __syncthreads();

    // gf partials: thread t = feature t, loop nodes
    float s0 = 0.0f, s1v = 0.0f;
    #pragma unroll 4
    for (int n = 0; n < 128; n++) {
        float h = __bfloat162float(g_h2b[(size_t)(row0 + n) * 256 + t]);
        s0 += ps[n][0] * h;
        s1v += ps[n][1] * h;
    }
    atomicAdd(&g_gf[t], s0);
    atomicAdd(&g_gf[256 + t], s1v);
}

// ---------------- new_adj ----------------
__global__ void k_newadj(const int* __restrict__ src, const int* __restrict__ dst) {
    float a0 = 0, a1 = 0, a2 = 0, a3 = 0;
    const float2* as2 = (const float2*)g_assign;
    for (int e = blockIdx.x * blockDim.x + threadIdx.x; e < EE; e += gridDim.x * blockDim.x) {
        int s = src[e], d = dst[e];
        float2 sv = as2[s];
        float2 dv = as2[d];
        a0 += sv.x * dv.x; a1 += sv.x * dv.y; a2 += sv.y * dv.x; a3 += sv.y * dv.y;
    }
    #pragma unroll
    for (int w = 16; w; w >>= 1) {
        a0 += __shfl_down_sync(0xffffffff, a0, w);
        a1 += __shfl_down_sync(0xffffffff, a1, w);
        a2 += __shfl_down_sync(0xffffffff, a2, w);
        a3 += __shfl_down_sync(0xffffffff, a3, w);
    }
    __shared__ float sa[8][4];
    int lane = threadIdx.x & 31, wid = threadIdx.x >> 5;
    if (lane == 0) { sa[wid][0] = a0; sa[wid][1] = a1; sa[wid][2] = a2; sa[wid][3] = a3; }
    __syncthreads();
    if (threadIdx.x < 4) {
        float sum = 0;
        #pragma unroll
        for (int w = 0; w < 8; w++) sum += sa[w][threadIdx.x];
        atomicAdd(&g_newadj[threadIdx.x], sum);
    }
}

// ---------------- finalize ----------------
__global__ void k_final(float* __restrict__ out) {
    int t = threadIdx.x;
    float g0 = g_gf[t], g1 = g_gf[256 + t];
    out[t]       = 0.5f * (g0 + g1);
    out[256 + t] = fminf(fmaxf(g0, -100.0f), 100.0f);
    out[512 + t] = fminf(fmaxf(g1, -100.0f), 100.0f);
    if (t == 0) {
        float a00 = g_newadj[0], a01 = g_newadj[1], a10 = g_newadj[2], a11 = g_newadj[3];
        float den0 = fmaxf(fabsf(a00) + fabsf(a01), 1e-12f);
        float den1 = fmaxf(fabsf(a10) + fabsf(a11), 1e-12f);
        float nd0 = a00 / den0, nd1 = a11 / den1;
        out[768] = 0.5f * ((nd0 - 1.0f) * (nd0 - 1.0f) + (nd1 - 1.0f) * (nd1 - 1.0f));
    }
}

extern "C" void kernel_launch(void* const* d_in, const int* in_sizes, int n_in,
                              void* d_out, int out_size) {
    const float* features = (const float*)d_in[0];
    const int*   edges    = (const int*)d_in[1];
    const float* W1    = (const float*)d_in[2];
    const float* b1    = (const float*)d_in[3];
    const float* W2    = (const float*)d_in[4];
    const float* b2    = (const float*)d_in[5];
    const float* fc1w  = (const float*)d_in[6];
    const float* fc1b  = (const float*)d_in[7];
    const float* fc2w  = (const float*)d_in[8];
    const float* fc2b  = (const float*)d_in[9];
    float* out = (float*)d_out;
    const int* src = edges;
    const int* dst = edges + EE;

    __nv_bfloat16 *pZb, *ph1b, *pXb;
    cudaGetSymbolAddress((void**)&pZb,  g_Zb);
    cudaGetSymbolAddress((void**)&ph1b, g_h1b);
    cudaGetSymbolAddress((void**)&pXb,  g_Xb);

    k_init<<<(D1 * H2) / 256, 256>>>(fc1w);
    k_deg<<<EE / 256, 256>>>(dst, features);
    k_scan<<<1, 1024>>>();
    k_scatter<<<EE / 256, 256>>>(src, dst);

    // layer 1: aggregate bf16 features (dinv inline), tensor-core transform
    k_agg1<<<NN / 8, 256>>>();
    dim3 gg(2, NN / 128);
    k_gemm_tc<<<gg, 256>>>(pZb, W1, ph1b, b1, F_IN, 0);    // h1b = bf16(relu(Z@W1+b1))

    // layer 2: transform (bf16 out), aggregate (bf16 out)
    k_gemm_tc<<<gg, 256>>>(ph1b, W2, pXb, (const float*)0, H1, 1);  // Xb = bf16(dinv*(h1@W2))
    k_agg2<<<NN / 4, 256>>>(b2);

    // fused MLP head
    k_fc1fc2<<<NN / 128, 256>>>(fc1b, fc2w, fc2b);

    k_newadj<<<256, 256>>>(src, dst);
    k_final<<<1, 256>>>(out);
}

// round 11
// speedup vs baseline: 2.1319x; 1.0247x over previous
#include <cuda_runtime.h>
#include <cuda_bf16.h>
#include <cstdint>
#include <math.h>

#define NN     16384
#define EE     524288
#define F_IN   128
#define H1     256
#define H2     256
#define D1     64

// ---------------- scratch (device globals; no allocations) ----------------
// NOTE: graph is self-restoring: g_deg / g_gf / g_newadj are returned to zero
// by the tail kernels each call, so every replay sees identical initial state.
__device__ __nv_bfloat16 g_Yb[NN * F_IN];  // raw features, bf16
__device__ __nv_bfloat16 g_Zb[NN * F_IN];  // aggregated features, bf16
__device__ __nv_bfloat16 g_h1b[NN * H1];   // relu(Z@W1+b1), bf16
__device__ __nv_bfloat16 g_Xb[NN * H1];    // dinv*(h1@W2), bf16
__device__ __nv_bfloat16 g_h2b[NN * H2];   // layer-2 output, bf16
__device__ float g_dinv[NN];
__device__ int   g_deg[NN];                // in-degree (0-based), zeroed at tail
__device__ int   g_rowptr[NN + 1];
__device__ int   g_slot[EE];
__device__ int   g_col[EE];
__device__ float g_fc1wT[H2 * D1];
__device__ float g_assign[NN * 2];
__device__ float g_gf[2 * H2];             // zeroed at tail
__device__ float g_newadj[4];              // zeroed at tail

// ---------------- degree histogram (0-based slot) + bf16 feature convert + fc1 transpose ----------------
__global__ void k_deg(const int* __restrict__ dst, const float* __restrict__ X,
                      const float* __restrict__ w) {
    int i = blockIdx.x * blockDim.x + threadIdx.x;
    g_slot[i] = atomicAdd(&g_deg[dst[i]], 1);
    float4 v = ((const float4*)X)[i];             // EE == NN*F_IN/4
    __nv_bfloat162 lo = __floats2bfloat162_rn(v.x, v.y);
    __nv_bfloat162 hi = __floats2bfloat162_rn(v.z, v.w);
    uint2 u; u.x = *(unsigned int*)&lo; u.y = *(unsigned int*)&hi;
    ((uint2*)g_Yb)[i] = u;
    if (i < D1 * H2) {                            // transpose fc1_w [64,256] -> [256,64]
        int o = i >> 8, k = i & 255;
        g_fc1wT[k * D1 + o] = w[i];
    }
}

// ---------------- fused scan + dinv: 1 block, 1024 threads ----------------
__global__ __launch_bounds__(1024) void k_scan() {
    int t = threadIdx.x;
    int base = t * 16;
    int local[16];
    int s = 0;
    #pragma unroll
    for (int j = 0; j < 16; j++) {
        int dg = g_deg[base + j];                 // in-degree (no self loop)
        g_dinv[base + j] = rsqrtf((float)(dg + 1));
        local[j] = s;
        s += dg;
    }
    int lane = t & 31, wid = t >> 5;
    int v = s;
    #pragma unroll
    for (int d = 1; d < 32; d <<= 1) {
        int u = __shfl_up_sync(0xffffffffu, v, d);
        if (lane >= d) v += u;
    }
    __shared__ int wsum[32];
    if (lane == 31) wsum[wid] = v;
    __syncthreads();
    if (wid == 0) {
        int w = wsum[lane];
        #pragma unroll
        for (int d = 1; d < 32; d <<= 1) {
            int u = __shfl_up_sync(0xffffffffu, w, d);
            if (lane >= d) w += u;
        }
        wsum[lane] = w;
    }
    __syncthreads();
    int off = (v - s) + (wid ? wsum[wid - 1] : 0);
    #pragma unroll
    for (int j = 0; j < 16; j++) g_rowptr[base + j] = off + local[j];
    if (t == 1023) g_rowptr[NN] = off + s;
}

// ---------------- atomic-free scatter ----------------
__global__ void k_scatter(const int* __restrict__ src, const int* __restrict__ dst) {
    int e = blockIdx.x * blockDim.x + threadIdx.x;
    int d = dst[e];
    g_col[g_rowptr[d] + g_slot[e]] = src[e];
}

// ---------------- layer-1 aggregation, unroll-8 gathers ----------------
// Zb[d] = bf16( dinv[d]*(dinv[d]*Y[d] + sum dinv[s]*Y[s]) )
__global__ __launch_bounds__(256) void k_agg1() {
    int gi = threadIdx.x >> 5;
    int lane = threadIdx.x & 31;
    int d = blockIdx.x * 8 + gi;
    const uint2* Y = (const uint2*)g_Yb;
    float scd = g_dinv[d];

    uint2 u = Y[(size_t)d * 32 + lane];
    float2 l0 = __bfloat1622float2(*(__nv_bfloat162*)&u.x);
    float2 h0 = __bfloat1622float2(*(__nv_bfloat162*)&u.y);
    float4 acc = make_float4(scd * l0.x, scd * l0.y, scd * h0.x, scd * h0.y);

    int j = g_rowptr[d], s1 = g_rowptr[d + 1];
    for (; j + 8 <= s1; j += 8) {
        int idx[8];
        float w[8];
        uint2 uu[8];
        #pragma unroll
        for (int q = 0; q < 8; q++) idx[q] = g_col[j + q];
        #pragma unroll
        for (int q = 0; q < 8; q++) uu[q] = Y[(size_t)idx[q] * 32 + lane];
        #pragma unroll
        for (int q = 0; q < 8; q++) w[q] = g_dinv[idx[q]];
        #pragma unroll
        for (int q = 0; q < 8; q++) {
            float2 a = __bfloat1622float2(*(__nv_bfloat162*)&uu[q].x);
            float2 b = __bfloat1622float2(*(__nv_bfloat162*)&uu[q].y);
            acc.x += w[q] * a.x; acc.y += w[q] * a.y;
            acc.z += w[q] * b.x; acc.w += w[q] * b.y;
        }
    }
    for (; j < s1; j++) {
        int s = g_col[j];
        float w = g_dinv[s];
        uint2 us = Y[(size_t)s * 32 + lane];
        float2 a = __bfloat1622float2(*(__nv_bfloat162*)&us.x);
        float2 b = __bfloat1622float2(*(__nv_bfloat162*)&us.y);
        acc.x += w * a.x; acc.y += w * a.y; acc.z += w * b.x; acc.w += w * b.y;
    }
    __nv_bfloat162 lo = __floats2bfloat162_rn(acc.x * scd, acc.y * scd);
    __nv_bfloat162 hi = __floats2bfloat162_rn(acc.z * scd, acc.w * scd);
    uint2 o; o.x = *(unsigned int*)&lo; o.y = *(unsigned int*)&hi;
    ((uint2*)g_Zb)[(size_t)d * 32 + lane] = o;
}

// ---------------- tf32 helpers ----------------
__device__ __forceinline__ unsigned int f2tf32(float x) {
    unsigned int r;
    asm("cvt.rna.tf32.f32 %0, %1;" : "=r"(r) : "f"(x));
    return r;
}
__device__ __forceinline__ void mma_tf32(float* d, const unsigned int* a, const unsigned int* b) {
    asm volatile(
        "mma.sync.aligned.m16n8k8.row.col.f32.tf32.tf32.f32 "
        "{%0,%1,%2,%3},{%4,%5,%6,%7},{%8,%9},{%0,%1,%2,%3};\n"
        : "+f"(d[0]), "+f"(d[1]), "+f"(d[2]), "+f"(d[3])
        : "r"(a[0]), "r"(a[1]), "r"(a[2]), "r"(a[3]), "r"(b[0]), "r"(b[1]));
}

// ---------------- tf32 GEMM, bf16 A, fp32 B; bf16 out ----------------
// mode 0: Cb = bf16(relu(AB + bias))   mode 1: Cb = bf16(dinv[row] * AB)
#define GBK 32
__global__ __launch_bounds__(256) void k_gemm_tc(const __nv_bfloat16* __restrict__ A,
                                                 const float* __restrict__ B,
                                                 __nv_bfloat16* __restrict__ Cb,
                                                 const float* __restrict__ bias,
                                                 int K, int mode) {
    __shared__ unsigned int As[GBK][136];
    __shared__ unsigned int Bs[GBK][136];
    int t = threadIdx.x;
    int row0 = blockIdx.y * 128, col0 = blockIdx.x * 128;
    int wid = t >> 5, lane = t & 31;
    int wr = wid >> 2, wc = wid & 3;
    int g = lane >> 2, tig = lane & 3;
    float acc[4][4][4] = {};

    int arr = t >> 3, akq = (t & 7) * 4;
    int bkr = t >> 5, bnq = (t & 31) * 4;

    uint2 ra[4];
    float4 rb[4];
    #pragma unroll
    for (int j = 0; j < 4; j++)
        ra[j] = *(const uint2*)&A[(size_t)(row0 + arr + j * 32) * K + akq];
    #pragma unroll
    for (int j = 0; j < 4; j++)
        rb[j] = *(const float4*)&B[(size_t)(bkr + j * 8) * 256 + col0 + bnq];

    for (int k0 = 0; k0 < K; k0 += GBK) {
        #pragma unroll
        for (int j = 0; j < 4; j++) {
            int r = arr + j * 32;
            float2 lo = __bfloat1622float2(*(__nv_bfloat162*)&ra[j].x);
            float2 hi = __bfloat1622float2(*(__nv_bfloat162*)&ra[j].y);
            As[akq + 0][r] = f2tf32(lo.x); As[akq + 1][r] = f2tf32(lo.y);
            As[akq + 2][r] = f2tf32(hi.x); As[akq + 3][r] = f2tf32(hi.y);
        }
        #pragma unroll
        for (int j = 0; j < 4; j++) {
            int kr = bkr + j * 8;
            Bs[kr][bnq + 0] = f2tf32(rb[j].x); Bs[kr][bnq + 1] = f2tf32(rb[j].y);
            Bs[kr][bnq + 2] = f2tf32(rb[j].z); Bs[kr][bnq + 3] = f2tf32(rb[j].w);
        }
        __syncthreads();

        bool more = (k0 + GBK) < K;
        if (more) {
            #pragma unroll
            for (int j = 0; j < 4; j++)
                ra[j] = *(const uint2*)&A[(size_t)(row0 + arr + j * 32) * K + k0 + GBK + akq];
            #pragma unroll
            for (int j = 0; j < 4; j++)
                rb[j] = *(const float4*)&B[(size_t)(k0 + GBK + bkr + j * 8) * 256 + col0 + bnq];
        }

        #pragma unroll
        for (int kk = 0; kk < GBK; kk += 8) {
            unsigned int af[4][4], bf[4][2];
            #pragma unroll
            for (int mi = 0; mi < 4; mi++) {
                int r = wr * 64 + mi * 16 + g;
                af[mi][0] = As[kk + tig][r];
                af[mi][1] = As[kk + tig][r + 8];
                af[mi][2] = As[kk + tig + 4][r];
                af[mi][3] = As[kk + tig + 4][r + 8];
            }
            #pragma unroll
            for (int ni = 0; ni < 4; ni++) {
                int c = wc * 32 + ni * 8 + g;
                bf[ni][0] = Bs[kk + tig][c];
                bf[ni][1] = Bs[kk + tig + 4][c];
            }
            #pragma unroll
            for (int mi = 0; mi < 4; mi++)
                #pragma unroll
                for (int ni = 0; ni < 4; ni++)
                    mma_tf32(acc[mi][ni], af[mi], bf[ni]);
        }
        __syncthreads();
    }

    #pragma unroll
    for (int mi = 0; mi < 4; mi++) {
        #pragma unroll
        for (int half = 0; half < 2; half++) {
            int r = row0 + wr * 64 + mi * 16 + g + half * 8;
            float sc = (mode == 1) ? g_dinv[r] : 1.0f;
            #pragma unroll
            for (int ni = 0; ni < 4; ni++) {
                int c = col0 + wc * 32 + ni * 8 + tig * 2;
                float v0 = acc[mi][ni][half * 2 + 0];
                float v1 = acc[mi][ni][half * 2 + 1];
                if (mode == 0) {
                    v0 = fmaxf(v0 + bias[c], 0.0f);
                    v1 = fmaxf(v1 + bias[c + 1], 0.0f);
                } else {
                    v0 *= sc; v1 *= sc;
                }
                __nv_bfloat162 bv = __floats2bfloat162_rn(v0, v1);
                *(__nv_bfloat162*)&Cb[(size_t)r * 256 + c] = bv;
            }
        }
    }
}

// ---------------- layer-2 aggregation (bf16 in/out), unroll-8 ----------------
__global__ __launch_bounds__(256) void k_agg2(const float* __restrict__ bias) {
    int gi = threadIdx.x >> 6;
    int lane = threadIdx.x & 63;
    int d = blockIdx.x * 4 + gi;
    const uint2* Xb = (const uint2*)g_Xb;

    uint2 u = Xb[(size_t)d * 64 + lane];
    float2 l0 = __bfloat1622float2(*(__nv_bfloat162*)&u.x);
    float2 h0 = __bfloat1622float2(*(__nv_bfloat162*)&u.y);
    float4 acc = make_float4(l0.x, l0.y, h0.x, h0.y);

    int j = g_rowptr[d], s1 = g_rowptr[d + 1];
    for (; j + 8 <= s1; j += 8) {
        int idx[8];
        uint2 uu[8];
        #pragma unroll
        for (int q = 0; q < 8; q++) idx[q] = g_col[j + q];
        #pragma unroll
        for (int q = 0; q < 8; q++) uu[q] = Xb[(size_t)idx[q] * 64 + lane];
        #pragma unroll
        for (int q = 0; q < 8; q++) {
            float2 a = __bfloat1622float2(*(__nv_bfloat162*)&uu[q].x);
            float2 b = __bfloat1622float2(*(__nv_bfloat162*)&uu[q].y);
            acc.x += a.x; acc.y += a.y; acc.z += b.x; acc.w += b.y;
        }
    }
    for (; j < s1; j++) {
        int s = g_col[j];
        uint2 us = Xb[(size_t)s * 64 + lane];
        float2 a = __bfloat1622float2(*(__nv_bfloat162*)&us.x);
        float2 b = __bfloat1622float2(*(__nv_bfloat162*)&us.y);
        acc.x += a.x; acc.y += a.y; acc.z += b.x; acc.w += b.y;
    }
    float sc = g_dinv[d];
    float4 bv = ((const float4*)bias)[lane];
    __nv_bfloat162 lo = __floats2bfloat162_rn(acc.x * sc + bv.x, acc.y * sc + bv.y);
    __nv_bfloat162 hi = __floats2bfloat162_rn(acc.z * sc + bv.z, acc.w * sc + bv.w);
    uint2 o; o.x = *(unsigned int*)&lo; o.y = *(unsigned int*)&hi;
    ((uint2*)g_h2b)[(size_t)d * 64 + lane] = o;
}

// ---------------- fused fc1 (tf32 MMA) + fc2 + softmax + assign + gf partials ----------------
__global__ __launch_bounds__(256) void k_fc1fc2(const float* __restrict__ fc1b,
                                                const float* __restrict__ fc2w,
                                                const float* __restrict__ fc2b) {
    __shared__ char buf[36864];
    unsigned int (*As)[136] = (unsigned int(*)[136])buf;            // 17408 B
    unsigned int (*Bs)[72]  = (unsigned int(*)[72])(buf + 17408);   // 9216 B
    float (*a1s)[65]  = (float(*)[65])buf;                          // 33280 B (aliases As/Bs)
    float (*ps)[2]    = (float(*)[2])(buf + 33280);                 // 1024 B
    float *w2s        = (float*)(buf + 34304);                      // 512 B

    int t = threadIdx.x;
    int row0 = blockIdx.x * 128;
    int wid = t >> 5, lane = t & 31;
    int wr = wid >> 1, wc = wid & 1;
    int g = lane >> 2, tig = lane & 3;
    float acc[2][4][4] = {};

    int arr = t >> 3, akq = (t & 7) * 4;
    int bkr = t >> 3, bcq = (t & 7) * 8;

    const __nv_bfloat16* A = g_h2b;
    uint2 ra[4];
    float4 rb0, rb1;
    #pragma unroll
    for (int j = 0; j < 4; j++)
        ra[j] = *(const uint2*)&A[(size_t)(row0 + arr + j * 32) * 256 + akq];
    rb0 = *(const float4*)&g_fc1wT[(size_t)bkr * 64 + bcq];
    rb1 = *(const float4*)&g_fc1wT[(size_t)bkr * 64 + bcq + 4];

    for (int k0 = 0; k0 < 256; k0 += GBK) {
        #pragma unroll
        for (int j = 0; j < 4; j++) {
            int r = arr + j * 32;
            float2 lo = __bfloat1622float2(*(__nv_bfloat162*)&ra[j].x);
            float2 hi = __bfloat1622float2(*(__nv_bfloat162*)&ra[j].y);
            As[akq + 0][r] = f2tf32(lo.x); As[akq + 1][r] = f2tf32(lo.y);
            As[akq + 2][r] = f2tf32(hi.x); As[akq + 3][r] = f2tf32(hi.y);
        }
        Bs[bkr][bcq + 0] = f2tf32(rb0.x); Bs[bkr][bcq + 1] = f2tf32(rb0.y);
        Bs[bkr][bcq + 2] = f2tf32(rb0.z); Bs[bkr][bcq + 3] = f2tf32(rb0.w);
        Bs[bkr][bcq + 4] = f2tf32(rb1.x); Bs[bkr][bcq + 5] = f2tf32(rb1.y);
        Bs[bkr][bcq + 6] = f2tf32(rb1.z); Bs[bkr][bcq + 7] = f2tf32(rb1.w);
        __syncthreads();

        bool more = (k0 + GBK) < 256;
        if (more) {
            #pragma unroll
            for (int j = 0; j < 4; j++)
                ra[j] = *(const uint2*)&A[(size_t)(row0 + arr + j * 32) * 256 + k0 + GBK + akq];
            rb0 = *(const float4*)&g_fc1wT[(size_t)(k0 + GBK + bkr) * 64 + bcq];
            rb1 = *(const float4*)&g_fc1wT[(size_t)(k0 + GBK + bkr) * 64 + bcq + 4];
        }

        #pragma unroll
        for (int kk = 0; kk < GBK; kk += 8) {
            unsigned int af[2][4], bf[4][2];
            #pragma unroll
            for (int mi = 0; mi < 2; mi++) {
                int r = wr * 32 + mi * 16 + g;
                af[mi][0] = As[kk + tig][r];
                af[mi][1] = As[kk + tig][r + 8];
                af[mi][2] = As[kk + tig + 4][r];
                af[mi][3] = As[kk + tig + 4][r + 8];
            }
            #pragma unroll
            for (int ni = 0; ni < 4; ni++) {
                int c = wc * 32 + ni * 8 + g;
                bf[ni][0] = Bs[kk + tig][c];
                bf[ni][1] = Bs[kk + tig + 4][c];
            }
            #pragma unroll
            for (int mi = 0; mi < 2; mi++)
                #pragma unroll
                for (int ni = 0; ni < 4; ni++)
                    mma_tf32(acc[mi][ni], af[mi], bf[ni]);
        }
        __syncthreads();
    }
    // ---- epilogue: a1 into smem (aliases MMA buffers; all reads complete) ----
    #pragma unroll
    for (int mi = 0; mi < 2; mi++) {
        #pragma unroll
        for (int half = 0; half < 2; half++) {
            int rr = wr * 32 + mi * 16 + g + half * 8;   // 0..127
            #pragma unroll
            for (int ni = 0; ni < 4; ni++) {
                int c = wc * 32 + ni * 8 + tig * 2;
                a1s[rr][c]     = tanhf(acc[mi][ni][half * 2 + 0] + fc1b[c]);
                a1s[rr][c + 1] = tanhf(acc[mi][ni][half * 2 + 1] + fc1b[c + 1]);
            }
        }
    }
    if (t < 128) w2s[t] = fc2w[t];
    __syncthreads();

    // fc2 logits: 256 threads = 128 nodes x 2 classes
    {
        int n = t >> 1, c = t & 1;
        float l = fc2b[c];
        #pragma unroll
        for (int k = 0; k < 64; k++) l += w2s[c * 64 + k] * a1s[n][k];
        ps[n][c] = l;
    }
    __syncthreads();
    if (t < 128) {
        float l0 = ps[t][0], l1 = ps[t][1];
        float m = fmaxf(l0, l1);
        float e0 = expf(l0 - m), e1 = expf(l1 - m);
        float inv = 1.0f / (e0 + e1);
        float p0 = e0 * inv, p1 = e1 * inv;
        ps[t][0] = p0; ps[t][1] = p1;
        g_assign[2 * (row0 + t)] = p0;
        g_assign[2 * (row0 + t) + 1] = p1;
    }
    __syncthreads();

    // gf partials: thread t = feature t, loop nodes
    float s0 = 0.0f, s1v = 0.0f;
    #pragma unroll 4
    for (int n = 0; n < 128; n++) {
        float h = __bfloat162float(g_h2b[(size_t)(row0 + n) * 256 + t]);
        s0 += ps[n][0] * h;
        s1v += ps[n][1] * h;
    }
    atomicAdd(&g_gf[t], s0);
    atomicAdd(&g_gf[256 + t], s1v);
}

// ---------------- new_adj (+ restore g_deg to 0 for next replay) ----------------
__global__ void k_newadj(const int* __restrict__ src, const int* __restrict__ dst) {
    int gtid = blockIdx.x * blockDim.x + threadIdx.x;
    if (gtid < NN) g_deg[gtid] = 0;           // self-restore for graph replay
    float a0 = 0, a1 = 0, a2 = 0, a3 = 0;
    const float2* as2 = (const float2*)g_assign;
    for (int e = gtid; e < EE; e += gridDim.x * blockDim.x) {
        int s = src[e], d = dst[e];
        float2 sv = as2[s];
        float2 dv = as2[d];
        a0 += sv.x * dv.x; a1 += sv.x * dv.y; a2 += sv.y * dv.x; a3 += sv.y * dv.y;
    }
    #pragma unroll
    for (int w = 16; w; w >>= 1) {
        a0 += __shfl_down_sync(0xffffffff, a0, w);
        a1 += __shfl_down_sync(0xffffffff, a1, w);
        a2 += __shfl_down_sync(0xffffffff, a2, w);
        a3 += __shfl_down_sync(0xffffffff, a3, w);
    }
    __shared__ float sa[8][4];
    int lane = threadIdx.x & 31, wid = threadIdx.x >> 5;
    if (lane == 0) { sa[wid][0] = a0; sa[wid][1] = a1; sa[wid][2] = a2; sa[wid][3] = a3; }
    __syncthreads();
    if (threadIdx.x < 4) {
        float sum = 0;
        #pragma unroll
        for (int w = 0; w < 8; w++) sum += sa[w][threadIdx.x];
        atomicAdd(&g_newadj[threadIdx.x], sum);
    }
}

// ---------------- finalize (+ restore g_gf / g_newadj to 0) ----------------
__global__ void k_final(float* __restrict__ out) {
    int t = threadIdx.x;
    float g0 = g_gf[t], g1 = g_gf[256 + t];
    g_gf[t] = 0.0f; g_gf[256 + t] = 0.0f;     // self-restore
    out[t]       = 0.5f * (g0 + g1);
    out[256 + t] = fminf(fmaxf(g0, -100.0f), 100.0f);
    out[512 + t] = fminf(fmaxf(g1, -100.0f), 100.0f);
    if (t == 0) {
        float a00 = g_newadj[0], a01 = g_newadj[1], a10 = g_newadj[2], a11 = g_newadj[3];
        g_newadj[0] = 0.0f; g_newadj[1] = 0.0f; g_newadj[2] = 0.0f; g_newadj[3] = 0.0f;
        float den0 = fmaxf(fabsf(a00) + fabsf(a01), 1e-12f);
        float den1 = fmaxf(fabsf(a10) + fabsf(a11), 1e-12f);
        float nd0 = a00 / den0, nd1 = a11 / den1;
        out[768] = 0.5f * ((nd0 - 1.0f) * (nd0 - 1.0f) + (nd1 - 1.0f) * (nd1 - 1.0f));
    }
}

extern "C" void kernel_launch(void* const* d_in, const int* in_sizes, int n_in,
                              void* d_out, int out_size) {
    const float* features = (const float*)d_in[0];
    const int*   edges    = (const int*)d_in[1];
    const float* W1    = (const float*)d_in[2];
    const float* b1    = (const float*)d_in[3];
    const float* W2    = (const float*)d_in[4];
    const float* b2    = (const float*)d_in[5];
    const float* fc1w  = (const float*)d_in[6];
    const float* fc1b  = (const float*)d_in[7];
    const float* fc2w  = (const float*)d_in[8];
    const float* fc2b  = (const float*)d_in[9];
    float* out = (float*)d_out;
    const int* src = edges;
    const int* dst = edges + EE;

    __nv_bfloat16 *pZb, *ph1b, *pXb;
    cudaGetSymbolAddress((void**)&pZb,  g_Zb);
    cudaGetSymbolAddress((void**)&ph1b, g_h1b);
    cudaGetSymbolAddress((void**)&pXb,  g_Xb);

    k_deg<<<EE / 256, 256>>>(dst, features, fc1w);
    k_scan<<<1, 1024>>>();
    k_scatter<<<EE / 256, 256>>>(src, dst);

    // layer 1: aggregate bf16 features (dinv inline), tensor-core transform
    k_agg1<<<NN / 8, 256>>>();
    dim3 gg(2, NN / 128);
    k_gemm_tc<<<gg, 256>>>(pZb, W1, ph1b, b1, F_IN, 0);    // h1b = bf16(relu(Z@W1+b1))

    // layer 2: transform (bf16 out), aggregate (bf16 out)
    k_gemm_tc<<<gg, 256>>>(ph1b, W2, pXb, (const float*)0, H1, 1);
    k_agg2<<<NN / 4, 256>>>(b2);

    // fused MLP head
    k_fc1fc2<<<NN / 128, 256>>>(fc1b, fc2w, fc2b);

    k_newadj<<<256, 256>>>(src, dst);
    k_final<<<1, 256>>>(out);
}

// round 12
// speedup vs baseline: 2.1685x; 1.0172x over previous
#include <cuda_runtime.h>
#include <cuda_bf16.h>
#include <cstdint>
#include <math.h>

#define NN     16384
#define EE     524288
#define F_IN   128
#define H1     256
#define H2     256
#define D1     64

// ---------------- scratch (device globals; no allocations) ----------------
// Self-restoring graph state: g_deg / g_gf / g_newadj return to zero each call.
__device__ __nv_bfloat16 g_Yb[NN * F_IN];  // dinv[r]*features, bf16
__device__ __nv_bfloat16 g_Zb[NN * F_IN];  // aggregated features, bf16
__device__ __nv_bfloat16 g_h1b[NN * H1];   // relu(Z@W1+b1), bf16
__device__ __nv_bfloat16 g_Xb[NN * H1];    // dinv*(h1@W2), bf16
__device__ __nv_bfloat16 g_h2b[NN * H2];   // layer-2 output, bf16
__device__ float g_dinv[NN];
__device__ int   g_deg[NN];                // in-degree (0-based), zeroed at tail
__device__ int   g_rowptr[NN + 1];
__device__ int   g_slot[EE];
__device__ int   g_col[EE];
__device__ float g_fc1wT[H2 * D1];
__device__ float g_assign[NN * 2];
__device__ float g_gf[2 * H2];             // zeroed at tail
__device__ float g_newadj[4];              // zeroed at tail

// ---------------- degree histogram (0-based slot) + fc1 transpose ----------------
__global__ void k_deg(const int* __restrict__ dst, const float* __restrict__ w) {
    int i = blockIdx.x * blockDim.x + threadIdx.x;
    g_slot[i] = atomicAdd(&g_deg[dst[i]], 1);
    if (i < D1 * H2) {                            // transpose fc1_w [64,256] -> [256,64]
        int o = i >> 8, k = i & 255;
        g_fc1wT[k * D1 + o] = w[i];
    }
}

// ---------------- fused scan + dinv: 1 block, 1024 threads ----------------
__global__ __launch_bounds__(1024) void k_scan() {
    int t = threadIdx.x;
    int base = t * 16;
    int local[16];
    int s = 0;
    #pragma unroll
    for (int j = 0; j < 16; j++) {
        int dg = g_deg[base + j];                 // in-degree (no self loop)
        g_dinv[base + j] = rsqrtf((float)(dg + 1));
        local[j] = s;
        s += dg;
    }
    int lane = t & 31, wid = t >> 5;
    int v = s;
    #pragma unroll
    for (int d = 1; d < 32; d <<= 1) {
        int u = __shfl_up_sync(0xffffffffu, v, d);
        if (lane >= d) v += u;
    }
    __shared__ int wsum[32];
    if (lane == 31) wsum[wid] = v;
    __syncthreads();
    if (wid == 0) {
        int w = wsum[lane];
        #pragma unroll
        for (int d = 1; d < 32; d <<= 1) {
            int u = __shfl_up_sync(0xffffffffu, w, d);
            if (lane >= d) w += u;
        }
        wsum[lane] = w;
    }
    __syncthreads();
    int off = (v - s) + (wid ? wsum[wid - 1] : 0);
    #pragma unroll
    for (int j = 0; j < 16; j++) g_rowptr[base + j] = off + local[j];
    if (t == 1023) g_rowptr[NN] = off + s;
}

// ---------------- atomic-free scatter + bf16(dinv*X) convert (post-scan) ----------------
__global__ void k_scatter(const int* __restrict__ src, const int* __restrict__ dst,
                          const float* __restrict__ X) {
    int i = blockIdx.x * blockDim.x + threadIdx.x;
    {
        int d = dst[i];
        g_col[g_rowptr[d] + g_slot[i]] = src[i];
    }
    {   // EE threads == NN*F_IN/4 float4 elements
        int node = i >> 5;
        float sc = g_dinv[node];
        float4 v = ((const float4*)X)[i];
        __nv_bfloat162 lo = __floats2bfloat162_rn(v.x * sc, v.y * sc);
        __nv_bfloat162 hi = __floats2bfloat162_rn(v.z * sc, v.w * sc);
        uint2 u; u.x = *(unsigned int*)&lo; u.y = *(unsigned int*)&hi;
        ((uint2*)g_Yb)[i] = u;
    }
}

// ---------------- layer-1 aggregation: 2 warps per node, unroll-8 ----------------
// Zb[d] = bf16( dinv[d] * (Yb[d] + sum Yb[s]) ),   Yb pre-scaled by dinv[src]
__global__ __launch_bounds__(256) void k_agg1() {
    __shared__ float4 part[4][32];
    int t = threadIdx.x;
    int w = t >> 5, lane = t & 31;
    int n = w >> 1, half = w & 1;
    int d = blockIdx.x * 4 + n;
    const uint2* Y = (const uint2*)g_Yb;

    float4 acc = make_float4(0.f, 0.f, 0.f, 0.f);
    if (half == 0) {
        uint2 u = Y[d * 32 + lane];
        float2 a = __bfloat1622float2(*(__nv_bfloat162*)&u.x);
        float2 b = __bfloat1622float2(*(__nv_bfloat162*)&u.y);
        acc = make_float4(a.x, a.y, b.x, b.y);
    }
    int s0 = g_rowptr[d], s1 = g_rowptr[d + 1];
    int len = s1 - s0;
    int j    = s0 + ((len * half) >> 1);
    int jend = s0 + ((len * (half + 1)) >> 1);
    for (; j + 8 <= jend; j += 8) {
        int idx[8];
        uint2 uu[8];
        #pragma unroll
        for (int q = 0; q < 8; q++) idx[q] = g_col[j + q];
        #pragma unroll
        for (int q = 0; q < 8; q++) uu[q] = Y[idx[q] * 32 + lane];
        #pragma unroll
        for (int q = 0; q < 8; q++) {
            float2 a = __bfloat1622float2(*(__nv_bfloat162*)&uu[q].x);
            float2 b = __bfloat1622float2(*(__nv_bfloat162*)&uu[q].y);
            acc.x += a.x; acc.y += a.y; acc.z += b.x; acc.w += b.y;
        }
    }
    for (; j < jend; j++) {
        uint2 us = Y[g_col[j] * 32 + lane];
        float2 a = __bfloat1622float2(*(__nv_bfloat162*)&us.x);
        float2 b = __bfloat1622float2(*(__nv_bfloat162*)&us.y);
        acc.x += a.x; acc.y += a.y; acc.z += b.x; acc.w += b.y;
    }
    if (half == 1) part[n][lane] = acc;
    __syncthreads();
    if (half == 0) {
        float4 p = part[n][lane];
        float scd = g_dinv[d];
        __nv_bfloat162 lo = __floats2bfloat162_rn((acc.x + p.x) * scd, (acc.y + p.y) * scd);
        __nv_bfloat162 hi = __floats2bfloat162_rn((acc.z + p.z) * scd, (acc.w + p.w) * scd);
        uint2 o; o.x = *(unsigned int*)&lo; o.y = *(unsigned int*)&hi;
        ((uint2*)g_Zb)[d * 32 + lane] = o;
    }
}

// ---------------- tf32 helpers ----------------
__device__ __forceinline__ unsigned int f2tf32(float x) {
    unsigned int r;
    asm("cvt.rna.tf32.f32 %0, %1;" : "=r"(r) : "f"(x));
    return r;
}
__device__ __forceinline__ void mma_tf32(float* d, const unsigned int* a, const unsigned int* b) {
    asm volatile(
        "mma.sync.aligned.m16n8k8.row.col.f32.tf32.tf32.f32 "
        "{%0,%1,%2,%3},{%4,%5,%6,%7},{%8,%9},{%0,%1,%2,%3};\n"
        : "+f"(d[0]), "+f"(d[1]), "+f"(d[2]), "+f"(d[3])
        : "r"(a[0]), "r"(a[1]), "r"(a[2]), "r"(a[3]), "r"(b[0]), "r"(b[1]));
}

// ---------------- tf32 GEMM, bf16 A, fp32 B; bf16 out ----------------
// mode 0: Cb = bf16(relu(AB + bias))   mode 1: Cb = bf16(dinv[row] * AB)
#define GBK 32
__global__ __launch_bounds__(256) void k_gemm_tc(const __nv_bfloat16* __restrict__ A,
                                                 const float* __restrict__ B,
                                                 __nv_bfloat16* __restrict__ Cb,
                                                 const float* __restrict__ bias,
                                                 int K, int mode) {
    __shared__ unsigned int As[GBK][136];
    __shared__ unsigned int Bs[GBK][136];
    int t = threadIdx.x;
    int row0 = blockIdx.y * 128, col0 = blockIdx.x * 128;
    int wid = t >> 5, lane = t & 31;
    int wr = wid >> 2, wc = wid & 3;
    int g = lane >> 2, tig = lane & 3;
    float acc[4][4][4] = {};

    int arr = t >> 3, akq = (t & 7) * 4;
    int bkr = t >> 5, bnq = (t & 31) * 4;

    uint2 ra[4];
    float4 rb[4];
    #pragma unroll
    for (int j = 0; j < 4; j++)
        ra[j] = *(const uint2*)&A[(size_t)(row0 + arr + j * 32) * K + akq];
    #pragma unroll
    for (int j = 0; j < 4; j++)
        rb[j] = *(const float4*)&B[(size_t)(bkr + j * 8) * 256 + col0 + bnq];

    for (int k0 = 0; k0 < K; k0 += GBK) {
        #pragma unroll
        for (int j = 0; j < 4; j++) {
            int r = arr + j * 32;
            float2 lo = __bfloat1622float2(*(__nv_bfloat162*)&ra[j].x);
            float2 hi = __bfloat1622float2(*(__nv_bfloat162*)&ra[j].y);
            As[akq + 0][r] = f2tf32(lo.x); As[akq + 1][r] = f2tf32(lo.y);
            As[akq + 2][r] = f2tf32(hi.x); As[akq + 3][r] = f2tf32(hi.y);
        }
        #pragma unroll
        for (int j = 0; j < 4; j++) {
            int kr = bkr + j * 8;
            Bs[kr][bnq + 0] = f2tf32(rb[j].x); Bs[kr][bnq + 1] = f2tf32(rb[j].y);
            Bs[kr][bnq + 2] = f2tf32(rb[j].z); Bs[kr][bnq + 3] = f2tf32(rb[j].w);
        }
        __syncthreads();

        bool more = (k0 + GBK) < K;
        if (more) {
            #pragma unroll
            for (int j = 0; j < 4; j++)
                ra[j] = *(const uint2*)&A[(size_t)(row0 + arr + j * 32) * K + k0 + GBK + akq];
            #pragma unroll
            for (int j = 0; j < 4; j++)
                rb[j] = *(const float4*)&B[(size_t)(k0 + GBK + bkr + j * 8) * 256 + col0 + bnq];
        }

        #pragma unroll
        for (int kk = 0; kk < GBK; kk += 8) {
            unsigned int af[4][4], bf[4][2];
            #pragma unroll
            for (int mi = 0; mi < 4; mi++) {
                int r = wr * 64 + mi * 16 + g;
                af[mi][0] = As[kk + tig][r];
                af[mi][1] = As[kk + tig][r + 8];
                af[mi][2] = As[kk + tig + 4][r];
                af[mi][3] = As[kk + tig + 4][r + 8];
            }
            #pragma unroll
            for (int ni = 0; ni < 4; ni++) {
                int c = wc * 32 + ni * 8 + g;
                bf[ni][0] = Bs[kk + tig][c];
                bf[ni][1] = Bs[kk + tig + 4][c];
            }
            #pragma unroll
            for (int mi = 0; mi < 4; mi++)
                #pragma unroll
                for (int ni = 0; ni < 4; ni++)
                    mma_tf32(acc[mi][ni], af[mi], bf[ni]);
        }
        __syncthreads();
    }

    #pragma unroll
    for (int mi = 0; mi < 4; mi++) {
        #pragma unroll
        for (int half = 0; half < 2; half++) {
            int r = row0 + wr * 64 + mi * 16 + g + half * 8;
            float sc = (mode == 1) ? g_dinv[r] : 1.0f;
            #pragma unroll
            for (int ni = 0; ni < 4; ni++) {
                int c = col0 + wc * 32 + ni * 8 + tig * 2;
                float v0 = acc[mi][ni][half * 2 + 0];
                float v1 = acc[mi][ni][half * 2 + 1];
                if (mode == 0) {
                    v0 = fmaxf(v0 + bias[c], 0.0f);
                    v1 = fmaxf(v1 + bias[c + 1], 0.0f);
                } else {
                    v0 *= sc; v1 *= sc;
                }
                __nv_bfloat162 bv = __floats2bfloat162_rn(v0, v1);
                *(__nv_bfloat162*)&Cb[(size_t)r * 256 + c] = bv;
            }
        }
    }
}

// ---------------- layer-2 aggregation: 2 groups (64 lanes) per node, unroll-8 ----------------
__global__ __launch_bounds__(256) void k_agg2(const float* __restrict__ bias) {
    __shared__ float4 part[2][64];
    int t = threadIdx.x;
    int grp = t >> 6;            // 0..3
    int lane = t & 63;
    int n = grp >> 1, half = grp & 1;
    int d = blockIdx.x * 2 + n;
    const uint2* Xb = (const uint2*)g_Xb;

    float4 acc = make_float4(0.f, 0.f, 0.f, 0.f);
    if (half == 0) {
        uint2 u = Xb[d * 64 + lane];
        float2 a = __bfloat1622float2(*(__nv_bfloat162*)&u.x);
        float2 b = __bfloat1622float2(*(__nv_bfloat162*)&u.y);
        acc = make_float4(a.x, a.y, b.x, b.y);
    }
    int s0 = g_rowptr[d], s1 = g_rowptr[d + 1];
    int len = s1 - s0;
    int j    = s0 + ((len * half) >> 1);
    int jend = s0 + ((len * (half + 1)) >> 1);
    for (; j + 8 <= jend; j += 8) {
        int idx[8];
        uint2 uu[8];
        #pragma unroll
        for (int q = 0; q < 8; q++) idx[q] = g_col[j + q];
        #pragma unroll
        for (int q = 0; q < 8; q++) uu[q] = Xb[idx[q] * 64 + lane];
        #pragma unroll
        for (int q = 0; q < 8; q++) {
            float2 a = __bfloat1622float2(*(__nv_bfloat162*)&uu[q].x);
            float2 b = __bfloat1622float2(*(__nv_bfloat162*)&uu[q].y);
            acc.x += a.x; acc.y += a.y; acc.z += b.x; acc.w += b.y;
        }
    }
    for (; j < jend; j++) {
        uint2 us = Xb[g_col[j] * 64 + lane];
        float2 a = __bfloat1622float2(*(__nv_bfloat162*)&us.x);
        float2 b = __bfloat1622float2(*(__nv_bfloat162*)&us.y);
        acc.x += a.x; acc.y += a.y; acc.z += b.x; acc.w += b.y;
    }
    if (half == 1) part[n][lane] = acc;
    __syncthreads();
    if (half == 0) {
        float4 p = part[n][lane];
        float sc = g_dinv[d];
        float4 bv = ((const float4*)bias)[lane];
        __nv_bfloat162 lo = __floats2bfloat162_rn((acc.x + p.x) * sc + bv.x,
                                                  (acc.y + p.y) * sc + bv.y);
        __nv_bfloat162 hi = __floats2bfloat162_rn((acc.z + p.z) * sc + bv.z,
                                                  (acc.w + p.w) * sc + bv.w);
        uint2 o; o.x = *(unsigned int*)&lo; o.y = *(unsigned int*)&hi;
        ((uint2*)g_h2b)[d * 64 + lane] = o;
    }
}

// ---------------- fused fc1 (tf32 MMA) + fc2 + softmax + assign + gf partials ----------------
__global__ __launch_bounds__(256) void k_fc1fc2(const float* __restrict__ fc1b,
                                                const float* __restrict__ fc2w,
                                                const float* __restrict__ fc2b) {
    __shared__ char buf[36864];
    unsigned int (*As)[136] = (unsigned int(*)[136])buf;            // 17408 B
    unsigned int (*Bs)[72]  = (unsigned int(*)[72])(buf + 17408);   // 9216 B
    float (*a1s)[65]  = (float(*)[65])buf;                          // 33280 B (aliases As/Bs)
    float (*ps)[2]    = (float(*)[2])(buf + 33280);                 // 1024 B
    float *w2s        = (float*)(buf + 34304);                      // 512 B

    int t = threadIdx.x;
    int row0 = blockIdx.x * 128;
    int wid = t >> 5, lane = t & 31;
    int wr = wid >> 1, wc = wid & 1;
    int g = lane >> 2, tig = lane & 3;
    float acc[2][4][4] = {};

    int arr = t >> 3, akq = (t & 7) * 4;
    int bkr = t >> 3, bcq = (t & 7) * 8;

    const __nv_bfloat16* A = g_h2b;
    uint2 ra[4];
    float4 rb0, rb1;
    #pragma unroll
    for (int j = 0; j < 4; j++)
        ra[j] = *(const uint2*)&A[(size_t)(row0 + arr + j * 32) * 256 + akq];
    rb0 = *(const float4*)&g_fc1wT[(size_t)bkr * 64 + bcq];
    rb1 = *(const float4*)&g_fc1wT[(size_t)bkr * 64 + bcq + 4];

    for (int k0 = 0; k0 < 256; k0 += GBK) {
        #pragma unroll
        for (int j = 0; j < 4; j++) {
            int r = arr + j * 32;
            float2 lo = __bfloat1622float2(*(__nv_bfloat162*)&ra[j].x);
            float2 hi = __bfloat1622float2(*(__nv_bfloat162*)&ra[j].y);
            As[akq + 0][r] = f2tf32(lo.x); As[akq + 1][r] = f2tf32(lo.y);
            As[akq + 2][r] = f2tf32(hi.x); As[akq + 3][r] = f2tf32(hi.y);
        }
        Bs[bkr][bcq + 0] = f2tf32(rb0.x); Bs[bkr][bcq + 1] = f2tf32(rb0.y);
        Bs[bkr][bcq + 2] = f2tf32(rb0.z); Bs[bkr][bcq + 3] = f2tf32(rb0.w);
        Bs[bkr][bcq + 4] = f2tf32(rb1.x); Bs[bkr][bcq + 5] = f2tf32(rb1.y);
        Bs[bkr][bcq + 6] = f2tf32(rb1.z); Bs[bkr][bcq + 7] = f2tf32(rb1.w);
        __syncthreads();

        bool more = (k0 + GBK) < 256;
        if (more) {
            #pragma unroll
            for (int j = 0; j < 4; j++)
                ra[j] = *(const uint2*)&A[(size_t)(row0 + arr + j * 32) * 256 + k0 + GBK + akq];
            rb0 = *(const float4*)&g_fc1wT[(size_t)(k0 + GBK + bkr) * 64 + bcq];
            rb1 = *(const float4*)&g_fc1wT[(size_t)(k0 + GBK + bkr) * 64 + bcq + 4];
        }

        #pragma unroll
        for (int kk = 0; kk < GBK; kk += 8) {
            unsigned int af[2][4], bf[4][2];
            #pragma unroll
            for (int mi = 0; mi < 2; mi++) {
                int r = wr * 32 + mi * 16 + g;
                af[mi][0] = As[kk + tig][r];
                af[mi][1] = As[kk + tig][r + 8];
                af[mi][2] = As[kk + tig + 4][r];
                af[mi][3] = As[kk + tig + 4][r + 8];
            }
            #pragma unroll
            for (int ni = 0; ni < 4; ni++) {
                int c = wc * 32 + ni * 8 + g;
                bf[ni][0] = Bs[kk + tig][c];
                bf[ni][1] = Bs[kk + tig + 4][c];
            }
            #pragma unroll
            for (int mi = 0; mi < 2; mi++)
                #pragma unroll
                for (int ni = 0; ni < 4; ni++)
                    mma_tf32(acc[mi][ni], af[mi], bf[ni]);
        }
        __syncthreads();
    }
    // ---- epilogue: a1 into smem (aliases MMA buffers; all reads complete) ----
    #pragma unroll
    for (int mi = 0; mi < 2; mi++) {
        #pragma unroll
        for (int half = 0; half < 2; half++) {
            int rr = wr * 32 + mi * 16 + g + half * 8;   // 0..127
            #pragma unroll
            for (int ni = 0; ni < 4; ni++) {
                int c = wc * 32 + ni * 8 + tig * 2;
                a1s[rr][c]     = tanhf(acc[mi][ni][half * 2 + 0] + fc1b[c]);
                a1s[rr][c + 1] = tanhf(acc[mi][ni][half * 2 + 1] + fc1b[c + 1]);
            }
        }
    }
    if (t < 128) w2s[t] = fc2w[t];
    __syncthreads();

    // fc2 logits: 256 threads = 128 nodes x 2 classes
    {
        int n = t >> 1, c = t & 1;
        float l = fc2b[c];
        #pragma unroll
        for (int k = 0; k < 64; k++) l += w2s[c * 64 + k] * a1s[n][k];
        ps[n][c] = l;
    }
    __syncthreads();
    if (t < 128) {
        float l0 = ps[t][0], l1 = ps[t][1];
        float m = fmaxf(l0, l1);
        float e0 = expf(l0 - m), e1 = expf(l1 - m);
        float inv = 1.0f / (e0 + e1);
        float p0 = e0 * inv, p1 = e1 * inv;
        ps[t][0] = p0; ps[t][1] = p1;
        g_assign[2 * (row0 + t)] = p0;
        g_assign[2 * (row0 + t) + 1] = p1;
    }
    __syncthreads();

    // gf partials: thread t = feature t, loop nodes
    float s0 = 0.0f, s1v = 0.0f;
    #pragma unroll 4
    for (int n = 0; n < 128; n++) {
        float h = __bfloat162float(g_h2b[(size_t)(row0 + n) * 256 + t]);
        s0 += ps[n][0] * h;
        s1v += ps[n][1] * h;
    }
    atomicAdd(&g_gf[t], s0);
    atomicAdd(&g_gf[256 + t], s1v);
}

// ---------------- new_adj (+ restore g_deg to 0 for next replay) ----------------
__global__ void k_newadj(const int* __restrict__ src, const int* __restrict__ dst) {
    int gtid = blockIdx.x * blockDim.x + threadIdx.x;
    if (gtid < NN) g_deg[gtid] = 0;           // self-restore for graph replay
    float a0 = 0, a1 = 0, a2 = 0, a3 = 0;
    const float2* as2 = (const float2*)g_assign;
    for (int e = gtid; e < EE; e += gridDim.x * blockDim.x) {
        int s = src[e], d = dst[e];
        float2 sv = as2[s];
        float2 dv = as2[d];
        a0 += sv.x * dv.x; a1 += sv.x * dv.y; a2 += sv.y * dv.x; a3 += sv.y * dv.y;
    }
    #pragma unroll
    for (int w = 16; w; w >>= 1) {
        a0 += __shfl_down_sync(0xffffffff, a0, w);
        a1 += __shfl_down_sync(0xffffffff, a1, w);
        a2 += __shfl_down_sync(0xffffffff, a2, w);
        a3 += __shfl_down_sync(0xffffffff, a3, w);
    }
    __shared__ float sa[8][4];
    int lane = threadIdx.x & 31, wid = threadIdx.x >> 5;
    if (lane == 0) { sa[wid][0] = a0; sa[wid][1] = a1; sa[wid][2] = a2; sa[wid][3] = a3; }
    __syncthreads();
    if (threadIdx.x < 4) {
        float sum = 0;
        #pragma unroll
        for (int w = 0; w < 8; w++) sum += sa[w][threadIdx.x];
        atomicAdd(&g_newadj[threadIdx.x], sum);
    }
}

// ---------------- finalize (+ restore g_gf / g_newadj to 0) ----------------
__global__ void k_final(float* __restrict__ out) {
    int t = threadIdx.x;
    float g0 = g_gf[t], g1 = g_gf[256 + t];
    g_gf[t] = 0.0f; g_gf[256 + t] = 0.0f;     // self-restore
    out[t]       = 0.5f * (g0 + g1);
    out[256 + t] = fminf(fmaxf(g0, -100.0f), 100.0f);
    out[512 + t] = fminf(fmaxf(g1, -100.0f), 100.0f);
    if (t == 0) {
        float a00 = g_newadj[0], a01 = g_newadj[1], a10 = g_newadj[2], a11 = g_newadj[3];
        g_newadj[0] = 0.0f; g_newadj[1] = 0.0f; g_newadj[2] = 0.0f; g_newadj[3] = 0.0f;
        float den0 = fmaxf(fabsf(a00) + fabsf(a01), 1e-12f);
        float den1 = fmaxf(fabsf(a10) + fabsf(a11), 1e-12f);
        float nd0 = a00 / den0, nd1 = a11 / den1;
        out[768] = 0.5f * ((nd0 - 1.0f) * (nd0 - 1.0f) + (nd1 - 1.0f) * (nd1 - 1.0f));
    }
}

extern "C" void kernel_launch(void* const* d_in, const int* in_sizes, int n_in,
                              void* d_out, int out_size) {
    const float* features = (const float*)d_in[0];
    const int*   edges    = (const int*)d_in[1];
    const float* W1    = (const float*)d_in[2];
    const float* b1    = (const float*)d_in[3];
    const float* W2    = (const float*)d_in[4];
    const float* b2    = (const float*)d_in[5];
    const float* fc1w  = (const float*)d_in[6];
    const float* fc1b  = (const float*)d_in[7];
    const float* fc2w  = (const float*)d_in[8];
    const float* fc2b  = (const float*)d_in[9];
    float* out = (float*)d_out;
    const int* src = edges;
    const int* dst = edges + EE;

    __nv_bfloat16 *pZb, *ph1b, *pXb;
    cudaGetSymbolAddress((void**)&pZb,  g_Zb);
    cudaGetSymbolAddress((void**)&ph1b, g_h1b);
    cudaGetSymbolAddress((void**)&pXb,  g_Xb);

    k_deg<<<EE / 256, 256>>>(dst, fc1w);
    k_scan<<<1, 1024>>>();
    k_scatter<<<EE / 256, 256>>>(src, dst, features);

    // layer 1: aggregate bf16 features (dinv premultiplied), tensor-core transform
    k_agg1<<<NN / 4, 256>>>();
    dim3 gg(2, NN / 128);
    k_gemm_tc<<<gg, 256>>>(pZb, W1, ph1b, b1, F_IN, 0);    // h1b = bf16(relu(Z@W1+b1))

    // layer 2: transform (bf16 out), aggregate (bf16 out)
    k_gemm_tc<<<gg, 256>>>(ph1b, W2, pXb, (const float*)0, H1, 1);
    k_agg2<<<NN / 2, 256>>>(b2);

    // fused MLP head
    k_fc1fc2<<<NN / 128, 256>>>(fc1b, fc2w, fc2b);

    k_newadj<<<256, 256>>>(src, dst);
    k_final<<<1, 256>>>(out);
}

// round 13
// speedup vs baseline: 2.2497x; 1.0374x over previous
#include <cuda_runtime.h>
#include <cuda_bf16.h>
#include <cstdint>
#include <math.h>

#define NN     16384
#define EE     524288
#define F_IN   128
#define H1     256
#define H2     256
#define D1     64

// ---------------- scratch (device globals; no allocations) ----------------
// Self-restoring graph state: g_deg / g_gf / g_newadj / g_done return to zero each call.
__device__ __nv_bfloat16 g_Yb[NN * F_IN];  // dinv[r]*features, bf16
__device__ __nv_bfloat16 g_Zb[NN * F_IN];  // aggregated features, bf16
__device__ __nv_bfloat16 g_h1b[NN * H1];   // relu(Z@W1+b1), bf16
__device__ __nv_bfloat16 g_Xb[NN * H1];    // dinv*(h1@W2), bf16
__device__ __nv_bfloat16 g_h2b[NN * H2];   // layer-2 output, bf16
__device__ float g_dinv[NN];
__device__ int   g_deg[NN];
__device__ int   g_rowptr[NN + 1];
__device__ int   g_slot[EE];
__device__ int   g_col[EE];
__device__ float g_fc1wT[H2 * D1];
__device__ float g_assign[NN * 2];
__device__ float g_gf[2 * H2];
__device__ float g_newadj[4];
__device__ unsigned int g_done;

// ---------------- degree histogram (0-based slot) + fc1 transpose ----------------
__global__ void k_deg(const int* __restrict__ dst, const float* __restrict__ w) {
    int i = blockIdx.x * blockDim.x + threadIdx.x;
    g_slot[i] = atomicAdd(&g_deg[dst[i]], 1);
    if (i < D1 * H2) {
        int o = i >> 8, k = i & 255;
        g_fc1wT[k * D1 + o] = w[i];
    }
}

// ---------------- fused scan + dinv: 1 block, 1024 threads ----------------
__global__ __launch_bounds__(1024) void k_scan() {
    int t = threadIdx.x;
    int base = t * 16;
    int local[16];
    int s = 0;
    #pragma unroll
    for (int j = 0; j < 16; j++) {
        int dg = g_deg[base + j];
        g_dinv[base + j] = rsqrtf((float)(dg + 1));
        local[j] = s;
        s += dg;
    }
    int lane = t & 31, wid = t >> 5;
    int v = s;
    #pragma unroll
    for (int d = 1; d < 32; d <<= 1) {
        int u = __shfl_up_sync(0xffffffffu, v, d);
        if (lane >= d) v += u;
    }
    __shared__ int wsum[32];
    if (lane == 31) wsum[wid] = v;
    __syncthreads();
    if (wid == 0) {
        int w = wsum[lane];
        #pragma unroll
        for (int d = 1; d < 32; d <<= 1) {
            int u = __shfl_up_sync(0xffffffffu, w, d);
            if (lane >= d) w += u;
        }
        wsum[lane] = w;
    }
    __syncthreads();
    int off = (v - s) + (wid ? wsum[wid - 1] : 0);
    #pragma unroll
    for (int j = 0; j < 16; j++) g_rowptr[base + j] = off + local[j];
    if (t == 1023) g_rowptr[NN] = off + s;
}

// ---------------- atomic-free scatter + bf16(dinv*X) convert ----------------
__global__ void k_scatter(const int* __restrict__ src, const int* __restrict__ dst,
                          const float* __restrict__ X) {
    int i = blockIdx.x * blockDim.x + threadIdx.x;
    {
        int d = dst[i];
        g_col[g_rowptr[d] + g_slot[i]] = src[i];
    }
    {
        int node = i >> 5;
        float sc = g_dinv[node];
        float4 v = ((const float4*)X)[i];
        __nv_bfloat162 lo = __floats2bfloat162_rn(v.x * sc, v.y * sc);
        __nv_bfloat162 hi = __floats2bfloat162_rn(v.z * sc, v.w * sc);
        uint2 u; u.x = *(unsigned int*)&lo; u.y = *(unsigned int*)&hi;
        ((uint2*)g_Yb)[i] = u;
    }
}

// ---------------- bf16x2 SIMD add ----------------
__device__ __forceinline__ unsigned int h2add(unsigned int a, unsigned int b) {
    unsigned int r;
    asm("add.rn.bf16x2 %0, %1, %2;" : "=r"(r) : "r"(a), "r"(b));
    return r;
}

// ---------------- layer-1 aggregation: 2 warps/node, bf16-tree unroll-8 ----------------
// Zb[d] = bf16( dinv[d] * (Yb[d] + sum Yb[s]) ),  Yb pre-scaled by dinv[src]
__global__ __launch_bounds__(256) void k_agg1() {
    __shared__ float4 part[4][32];
    int t = threadIdx.x;
    int w = t >> 5, lane = t & 31;
    int n = w >> 1, half = w & 1;
    int d = blockIdx.x * 4 + n;
    const uint2* Y = (const uint2*)g_Yb;

    float4 acc = make_float4(0.f, 0.f, 0.f, 0.f);
    if (half == 0) {
        uint2 u = Y[d * 32 + lane];
        float2 a = __bfloat1622float2(*(__nv_bfloat162*)&u.x);
        float2 b = __bfloat1622float2(*(__nv_bfloat162*)&u.y);
        acc = make_float4(a.x, a.y, b.x, b.y);
    }
    int s0 = g_rowptr[d], s1 = g_rowptr[d + 1];
    int len = s1 - s0;
    int j    = s0 + ((len * half) >> 1);
    int jend = s0 + ((len * (half + 1)) >> 1);
    for (; j + 8 <= jend; j += 8) {
        int idx[8];
        uint2 uu[8];
        #pragma unroll
        for (int q = 0; q < 8; q++) idx[q] = g_col[j + q];
        #pragma unroll
        for (int q = 0; q < 8; q++) uu[q] = Y[idx[q] * 32 + lane];
        // bf16 pairwise tree: sums of 8 (3 roundings), then fp32 accumulate
        unsigned int s0x = h2add(uu[0].x, uu[1].x), s0y = h2add(uu[0].y, uu[1].y);
        unsigned int s1x = h2add(uu[2].x, uu[3].x), s1y = h2add(uu[2].y, uu[3].y);
        unsigned int s2x = h2add(uu[4].x, uu[5].x), s2y = h2add(uu[4].y, uu[5].y);
        unsigned int s3x = h2add(uu[6].x, uu[7].x), s3y = h2add(uu[6].y, uu[7].y);
        unsigned int t0x = h2add(s0x, s1x), t0y = h2add(s0y, s1y);
        unsigned int t1x = h2add(s2x, s3x), t1y = h2add(s2y, s3y);
        unsigned int rx = h2add(t0x, t1x), ry = h2add(t0y, t1y);
        float2 a = __bfloat1622float2(*(__nv_bfloat162*)&rx);
        float2 b = __bfloat1622float2(*(__nv_bfloat162*)&ry);
        acc.x += a.x; acc.y += a.y; acc.z += b.x; acc.w += b.y;
    }
    for (; j < jend; j++) {
        uint2 us = Y[g_col[j] * 32 + lane];
        float2 a = __bfloat1622float2(*(__nv_bfloat162*)&us.x);
        float2 b = __bfloat1622float2(*(__nv_bfloat162*)&us.y);
        acc.x += a.x; acc.y += a.y; acc.z += b.x; acc.w += b.y;
    }
    if (half == 1) part[n][lane] = acc;
    __syncthreads();
    if (half == 0) {
        float4 p = part[n][lane];
        float scd = g_dinv[d];
        __nv_bfloat162 lo = __floats2bfloat162_rn((acc.x + p.x) * scd, (acc.y + p.y) * scd);
        __nv_bfloat162 hi = __floats2bfloat162_rn((acc.z + p.z) * scd, (acc.w + p.w) * scd);
        uint2 o; o.x = *(unsigned int*)&lo; o.y = *(unsigned int*)&hi;
        ((uint2*)g_Zb)[d * 32 + lane] = o;
    }
}

// ---------------- tf32 helpers ----------------
__device__ __forceinline__ unsigned int f2tf32(float x) {
    unsigned int r;
    asm("cvt.rna.tf32.f32 %0, %1;" : "=r"(r) : "f"(x));
    return r;
}
__device__ __forceinline__ void mma_tf32(float* d, const unsigned int* a, const unsigned int* b) {
    asm volatile(
        "mma.sync.aligned.m16n8k8.row.col.f32.tf32.tf32.f32 "
        "{%0,%1,%2,%3},{%4,%5,%6,%7},{%8,%9},{%0,%1,%2,%3};\n"
        : "+f"(d[0]), "+f"(d[1]), "+f"(d[2]), "+f"(d[3])
        : "r"(a[0]), "r"(a[1]), "r"(a[2]), "r"(a[3]), "r"(b[0]), "r"(b[1]));
}

// ---------------- tf32 GEMM, bf16 A, fp32 B; bf16 out ----------------
// mode 0: Cb = bf16(relu(AB + bias))   mode 1: Cb = bf16(dinv[row] * AB)
#define GBK 32
__global__ __launch_bounds__(256) void k_gemm_tc(const __nv_bfloat16* __restrict__ A,
                                                 const float* __restrict__ B,
                                                 __nv_bfloat16* __restrict__ Cb,
                                                 const float* __restrict__ bias,
                                                 int K, int mode) {
    __shared__ unsigned int As[GBK][136];
    __shared__ unsigned int Bs[GBK][136];
    int t = threadIdx.x;
    int row0 = blockIdx.y * 128, col0 = blockIdx.x * 128;
    int wid = t >> 5, lane = t & 31;
    int wr = wid >> 2, wc = wid & 3;
    int g = lane >> 2, tig = lane & 3;
    float acc[4][4][4] = {};

    int arr = t >> 3, akq = (t & 7) * 4;
    int bkr = t >> 5, bnq = (t & 31) * 4;

    uint2 ra[4];
    float4 rb[4];
    #pragma unroll
    for (int j = 0; j < 4; j++)
        ra[j] = *(const uint2*)&A[(size_t)(row0 + arr + j * 32) * K + akq];
    #pragma unroll
    for (int j = 0; j < 4; j++)
        rb[j] = *(const float4*)&B[(size_t)(bkr + j * 8) * 256 + col0 + bnq];

    for (int k0 = 0; k0 < K; k0 += GBK) {
        #pragma unroll
        for (int j = 0; j < 4; j++) {
            int r = arr + j * 32;
            float2 lo = __bfloat1622float2(*(__nv_bfloat162*)&ra[j].x);
            float2 hi = __bfloat1622float2(*(__nv_bfloat162*)&ra[j].y);
            As[akq + 0][r] = f2tf32(lo.x); As[akq + 1][r] = f2tf32(lo.y);
            As[akq + 2][r] = f2tf32(hi.x); As[akq + 3][r] = f2tf32(hi.y);
        }
        #pragma unroll
        for (int j = 0; j < 4; j++) {
            int kr = bkr + j * 8;
            Bs[kr][bnq + 0] = f2tf32(rb[j].x); Bs[kr][bnq + 1] = f2tf32(rb[j].y);
            Bs[kr][bnq + 2] = f2tf32(rb[j].z); Bs[kr][bnq + 3] = f2tf32(rb[j].w);
        }
        __syncthreads();

        bool more = (k0 + GBK) < K;
        if (more) {
            #pragma unroll
            for (int j = 0; j < 4; j++)
                ra[j] = *(const uint2*)&A[(size_t)(row0 + arr + j * 32) * K + k0 + GBK + akq];
            #pragma unroll
            for (int j = 0; j < 4; j++)
                rb[j] = *(const float4*)&B[(size_t)(k0 + GBK + bkr + j * 8) * 256 + col0 + bnq];
        }

        #pragma unroll
        for (int kk = 0; kk < GBK; kk += 8) {
            unsigned int af[4][4], bf[4][2];
            #pragma unroll
            for (int mi = 0; mi < 4; mi++) {
                int r = wr * 64 + mi * 16 + g;
                af[mi][0] = As[kk + tig][r];
                af[mi][1] = As[kk + tig][r + 8];
                af[mi][2] = As[kk + tig + 4][r];
                af[mi][3] = As[kk + tig + 4][r + 8];
            }
            #pragma unroll
            for (int ni = 0; ni < 4; ni++) {
                int c = wc * 32 + ni * 8 + g;
                bf[ni][0] = Bs[kk + tig][c];
                bf[ni][1] = Bs[kk + tig + 4][c];
            }
            #pragma unroll
            for (int mi = 0; mi < 4; mi++)
                #pragma unroll
                for (int ni = 0; ni < 4; ni++)
                    mma_tf32(acc[mi][ni], af[mi], bf[ni]);
        }
        __syncthreads();
    }

    #pragma unroll
    for (int mi = 0; mi < 4; mi++) {
        #pragma unroll
        for (int half = 0; half < 2; half++) {
            int r = row0 + wr * 64 + mi * 16 + g + half * 8;
            float sc = (mode == 1) ? g_dinv[r] : 1.0f;
            #pragma unroll
            for (int ni = 0; ni < 4; ni++) {
                int c = col0 + wc * 32 + ni * 8 + tig * 2;
                float v0 = acc[mi][ni][half * 2 + 0];
                float v1 = acc[mi][ni][half * 2 + 1];
                if (mode == 0) {
                    v0 = fmaxf(v0 + bias[c], 0.0f);
                    v1 = fmaxf(v1 + bias[c + 1], 0.0f);
                } else {
                    v0 *= sc; v1 *= sc;
                }
                __nv_bfloat162 bv = __floats2bfloat162_rn(v0, v1);
                *(__nv_bfloat162*)&Cb[(size_t)r * 256 + c] = bv;
            }
        }
    }
}

// ---------------- layer-2 aggregation: 2 groups (64 lanes)/node, bf16-tree unroll-8 ----------------
__global__ __launch_bounds__(256) void k_agg2(const float* __restrict__ bias) {
    __shared__ float4 part[2][64];
    int t = threadIdx.x;
    int grp = t >> 6;
    int lane = t & 63;
    int n = grp >> 1, half = grp & 1;
    int d = blockIdx.x * 2 + n;
    const uint2* Xb = (const uint2*)g_Xb;

    float4 acc = make_float4(0.f, 0.f, 0.f, 0.f);
    if (half == 0) {
        uint2 u = Xb[d * 64 + lane];
        float2 a = __bfloat1622float2(*(__nv_bfloat162*)&u.x);
        float2 b = __bfloat1622float2(*(__nv_bfloat162*)&u.y);
        acc = make_float4(a.x, a.y, b.x, b.y);
    }
    int s0 = g_rowptr[d], s1 = g_rowptr[d + 1];
    int len = s1 - s0;
    int j    = s0 + ((len * half) >> 1);
    int jend = s0 + ((len * (half + 1)) >> 1);
    for (; j + 8 <= jend; j += 8) {
        int idx[8];
        uint2 uu[8];
        #pragma unroll
        for (int q = 0; q < 8; q++) idx[q] = g_col[j + q];
        #pragma unroll
        for (int q = 0; q < 8; q++) uu[q] = Xb[idx[q] * 64 + lane];
        unsigned int s0x = h2add(uu[0].x, uu[1].x), s0y = h2add(uu[0].y, uu[1].y);
        unsigned int s1x = h2add(uu[2].x, uu[3].x), s1y = h2add(uu[2].y, uu[3].y);
        unsigned int s2x = h2add(uu[4].x, uu[5].x), s2y = h2add(uu[4].y, uu[5].y);
        unsigned int s3x = h2add(uu[6].x, uu[7].x), s3y = h2add(uu[6].y, uu[7].y);
        unsigned int t0x = h2add(s0x, s1x), t0y = h2add(s0y, s1y);
        unsigned int t1x = h2add(s2x, s3x), t1y = h2add(s2y, s3y);
        unsigned int rx = h2add(t0x, t1x), ry = h2add(t0y, t1y);
        float2 a = __bfloat1622float2(*(__nv_bfloat162*)&rx);
        float2 b = __bfloat1622float2(*(__nv_bfloat162*)&ry);
        acc.x += a.x; acc.y += a.y; acc.z += b.x; acc.w += b.y;
    }
    for (; j < jend; j++) {
        uint2 us = Xb[g_col[j] * 64 + lane];
        float2 a = __bfloat1622float2(*(__nv_bfloat162*)&us.x);
        float2 b = __bfloat1622float2(*(__nv_bfloat162*)&us.y);
        acc.x += a.x; acc.y += a.y; acc.z += b.x; acc.w += b.y;
    }
    if (half == 1) part[n][lane] = acc;
    __syncthreads();
    if (half == 0) {
        float4 p = part[n][lane];
        float sc = g_dinv[d];
        float4 bv = ((const float4*)bias)[lane];
        __nv_bfloat162 lo = __floats2bfloat162_rn((acc.x + p.x) * sc + bv.x,
                                                  (acc.y + p.y) * sc + bv.y);
        __nv_bfloat162 hi = __floats2bfloat162_rn((acc.z + p.z) * sc + bv.z,
                                                  (acc.w + p.w) * sc + bv.w);
        uint2 o; o.x = *(unsigned int*)&lo; o.y = *(unsigned int*)&hi;
        ((uint2*)g_h2b)[d * 64 + lane] = o;
    }
}

// ---------------- fused fc1 (tf32 MMA) + fc2 + softmax + assign + gf partials ----------------
__global__ __launch_bounds__(256) void k_fc1fc2(const float* __restrict__ fc1b,
                                                const float* __restrict__ fc2w,
                                                const float* __restrict__ fc2b) {
    __shared__ char buf[36864];
    unsigned int (*As)[136] = (unsigned int(*)[136])buf;
    unsigned int (*Bs)[72]  = (unsigned int(*)[72])(buf + 17408);
    float (*a1s)[65]  = (float(*)[65])buf;
    float (*ps)[2]    = (float(*)[2])(buf + 33280);
    float *w2s        = (float*)(buf + 34304);

    int t = threadIdx.x;
    int row0 = blockIdx.x * 128;
    int wid = t >> 5, lane = t & 31;
    int wr = wid >> 1, wc = wid & 1;
    int g = lane >> 2, tig = lane & 3;
    float acc[2][4][4] = {};

    int arr = t >> 3, akq = (t & 7) * 4;
    int bkr = t >> 3, bcq = (t & 7) * 8;

    const __nv_bfloat16* A = g_h2b;
    uint2 ra[4];
    float4 rb0, rb1;
    #pragma unroll
    for (int j = 0; j < 4; j++)
        ra[j] = *(const uint2*)&A[(size_t)(row0 + arr + j * 32) * 256 + akq];
    rb0 = *(const float4*)&g_fc1wT[(size_t)bkr * 64 + bcq];
    rb1 = *(const float4*)&g_fc1wT[(size_t)bkr * 64 + bcq + 4];

    for (int k0 = 0; k0 < 256; k0 += GBK) {
        #pragma unroll
        for (int j = 0; j < 4; j++) {
            int r = arr + j * 32;
            float2 lo = __bfloat1622float2(*(__nv_bfloat162*)&ra[j].x);
            float2 hi = __bfloat1622float2(*(__nv_bfloat162*)&ra[j].y);
            As[akq + 0][r] = f2tf32(lo.x); As[akq + 1][r] = f2tf32(lo.y);
            As[akq + 2][r] = f2tf32(hi.x); As[akq + 3][r] = f2tf32(hi.y);
        }
        Bs[bkr][bcq + 0] = f2tf32(rb0.x); Bs[bkr][bcq + 1] = f2tf32(rb0.y);
        Bs[bkr][bcq + 2] = f2tf32(rb0.z); Bs[bkr][bcq + 3] = f2tf32(rb0.w);
        Bs[bkr][bcq + 4] = f2tf32(rb1.x); Bs[bkr][bcq + 5] = f2tf32(rb1.y);
        Bs[bkr][bcq + 6] = f2tf32(rb1.z); Bs[bkr][bcq + 7] = f2tf32(rb1.w);
        __syncthreads();

        bool more = (k0 + GBK) < 256;
        if (more) {
            #pragma unroll
            for (int j = 0; j < 4; j++)
                ra[j] = *(const uint2*)&A[(size_t)(row0 + arr + j * 32) * 256 + k0 + GBK + akq];
            rb0 = *(const float4*)&g_fc1wT[(size_t)(k0 + GBK + bkr) * 64 + bcq];
            rb1 = *(const float4*)&g_fc1wT[(size_t)(k0 + GBK + bkr) * 64 + bcq + 4];
        }

        #pragma unroll
        for (int kk = 0; kk < GBK; kk += 8) {
            unsigned int af[2][4], bf[4][2];
            #pragma unroll
            for (int mi = 0; mi < 2; mi++) {
                int r = wr * 32 + mi * 16 + g;
                af[mi][0] = As[kk + tig][r];
                af[mi][1] = As[kk + tig][r + 8];
                af[mi][2] = As[kk + tig + 4][r];
                af[mi][3] = As[kk + tig + 4][r + 8];
            }
            #pragma unroll
            for (int ni = 0; ni < 4; ni++) {
                int c = wc * 32 + ni * 8 + g;
                bf[ni][0] = Bs[kk + tig][c];
                bf[ni][1] = Bs[kk + tig + 4][c];
            }
            #pragma unroll
            for (int mi = 0; mi < 2; mi++)
                #pragma unroll
                for (int ni = 0; ni < 4; ni++)
                    mma_tf32(acc[mi][ni], af[mi], bf[ni]);
        }
        __syncthreads();
    }
    #pragma unroll
    for (int mi = 0; mi < 2; mi++) {
        #pragma unroll
        for (int half = 0; half < 2; half++) {
            int rr = wr * 32 + mi * 16 + g + half * 8;
            #pragma unroll
            for (int ni = 0; ni < 4; ni++) {
                int c = wc * 32 + ni * 8 + tig * 2;
                a1s[rr][c]     = tanhf(acc[mi][ni][half * 2 + 0] + fc1b[c]);
                a1s[rr][c + 1] = tanhf(acc[mi][ni][half * 2 + 1] + fc1b[c + 1]);
            }
        }
    }
    if (t < 128) w2s[t] = fc2w[t];
    __syncthreads();

    {
        int n = t >> 1, c = t & 1;
        float l = fc2b[c];
        #pragma unroll
        for (int k = 0; k < 64; k++) l += w2s[c * 64 + k] * a1s[n][k];
        ps[n][c] = l;
    }
    __syncthreads();
    if (t < 128) {
        float l0 = ps[t][0], l1 = ps[t][1];
        float m = fmaxf(l0, l1);
        float e0 = expf(l0 - m), e1 = expf(l1 - m);
        float inv = 1.0f / (e0 + e1);
        float p0 = e0 * inv, p1 = e1 * inv;
        ps[t][0] = p0; ps[t][1] = p1;
        g_assign[2 * (row0 + t)] = p0;
        g_assign[2 * (row0 + t) + 1] = p1;
    }
    __syncthreads();

    float s0 = 0.0f, s1v = 0.0f;
    #pragma unroll 4
    for (int n = 0; n < 128; n++) {
        float h = __bfloat162float(g_h2b[(size_t)(row0 + n) * 256 + t]);
        s0 += ps[n][0] * h;
        s1v += ps[n][1] * h;
    }
    atomicAdd(&g_gf[t], s0);
    atomicAdd(&g_gf[256 + t], s1v);
}

// ---------------- new_adj + finalize (last-block) + state restore ----------------
__global__ void k_newadj(const int* __restrict__ src, const int* __restrict__ dst,
                         float* __restrict__ out) {
    int gtid = blockIdx.x * blockDim.x + threadIdx.x;
    if (gtid < NN) g_deg[gtid] = 0;           // self-restore for graph replay
    float a0 = 0, a1 = 0, a2 = 0, a3 = 0;
    const float2* as2 = (const float2*)g_assign;
    for (int e = gtid; e < EE; e += gridDim.x * blockDim.x) {
        int s = src[e], d = dst[e];
        float2 sv = as2[s];
        float2 dv = as2[d];
        a0 += sv.x * dv.x; a1 += sv.x * dv.y; a2 += sv.y * dv.x; a3 += sv.y * dv.y;
    }
    #pragma unroll
    for (int w = 16; w; w >>= 1) {
        a0 += __shfl_down_sync(0xffffffff, a0, w);
        a1 += __shfl_down_sync(0xffffffff, a1, w);
        a2 += __shfl_down_sync(0xffffffff, a2, w);
        a3 += __shfl_down_sync(0xffffffff, a3, w);
    }
    __shared__ float sa[8][4];
    int lane = threadIdx.x & 31, wid = threadIdx.x >> 5;
    if (lane == 0) { sa[wid][0] = a0; sa[wid][1] = a1; sa[wid][2] = a2; sa[wid][3] = a3; }
    __syncthreads();
    if (threadIdx.x < 4) {
        float sum = 0;
        #pragma unroll
        for (int w = 0; w < 8; w++) sum += sa[w][threadIdx.x];
        atomicAdd(&g_newadj[threadIdx.x], sum);
        __threadfence();
    }
    __syncthreads();

    // last-block finalize
    __shared__ int is_last;
    if (threadIdx.x == 0) {
        unsigned int ticket = atomicAdd(&g_done, 1);
        is_last = (ticket == gridDim.x - 1);
    }
    __syncthreads();
    if (is_last) {
        int t = threadIdx.x;
        float g0 = g_gf[t], g1 = g_gf[256 + t];
        g_gf[t] = 0.0f; g_gf[256 + t] = 0.0f;     // self-restore
        out[t]       = 0.5f * (g0 + g1);
        out[256 + t] = fminf(fmaxf(g0, -100.0f), 100.0f);
        out[512 + t] = fminf(fmaxf(g1, -100.0f), 100.0f);
        if (t == 0) {
            float b00 = g_newadj[0], b01 = g_newadj[1], b10 = g_newadj[2], b11 = g_newadj[3];
            g_newadj[0] = 0.0f; g_newadj[1] = 0.0f; g_newadj[2] = 0.0f; g_newadj[3] = 0.0f;
            g_done = 0;                            // self-restore
            float den0 = fmaxf(fabsf(b00) + fabsf(b01), 1e-12f);
            float den1 = fmaxf(fabsf(b10) + fabsf(b11), 1e-12f);
            float nd0 = b00 / den0, nd1 = b11 / den1;
            out[768] = 0.5f * ((nd0 - 1.0f) * (nd0 - 1.0f) + (nd1 - 1.0f) * (nd1 - 1.0f));
        }
    }
}

extern "C" void kernel_launch(void* const* d_in, const int* in_sizes, int n_in,
                              void* d_out, int out_size) {
    const float* features = (const float*)d_in[0];
    const int*   edges    = (const int*)d_in[1];
    const float* W1    = (const float*)d_in[2];
    const float* b1    = (const float*)d_in[3];
    const float* W2    = (const float*)d_in[4];
    const float* b2    = (const float*)d_in[5];
    const float* fc1w  = (const float*)d_in[6];
    const float* fc1b  = (const float*)d_in[7];
    const float* fc2w  = (const float*)d_in[8];
    const float* fc2b  = (const float*)d_in[9];
    float* out = (float*)d_out;
    const int* src = edges;
    const int* dst = edges + EE;

    __nv_bfloat16 *pZb, *ph1b, *pXb;
    cudaGetSymbolAddress((void**)&pZb,  g_Zb);
    cudaGetSymbolAddress((void**)&ph1b, g_h1b);
    cudaGetSymbolAddress((void**)&pXb,  g_Xb);

    k_deg<<<EE / 256, 256>>>(dst, fc1w);
    k_scan<<<1, 1024>>>();
    k_scatter<<<EE / 256, 256>>>(src, dst, features);

    // layer 1: aggregate bf16 features (dinv premultiplied), tensor-core transform
    k_agg1<<<NN / 4, 256>>>();
    dim3 gg(2, NN / 128);
    k_gemm_tc<<<gg, 256>>>(pZb, W1, ph1b, b1, F_IN, 0);

    // layer 2: transform (bf16 out), aggregate (bf16 out)
    k_gemm_tc<<<gg, 256>>>(ph1b, W2, pXb, (const float*)0, H1, 1);
    k_agg2<<<NN / 2, 256>>>(b2);

    // fused MLP head
    k_fc1fc2<<<NN / 128, 256>>>(fc1b, fc2w, fc2b);

    // new_adj + finalize (fused, last-block)
    k_newadj<<<256, 256>>>(src, dst, out);
}